// round 9
// baseline (speedup 1.0000x reference)
#include <cuda_runtime.h>
#include <cuda_bf16.h>
#include <cuda_fp16.h>
#include <math.h>

#define NN 10000
#define NE 256000
#define HH 128
#define H2 256
#define H3 384
#define NR 20

typedef unsigned int u32;

// ---------------- scratch (static device globals; no allocation) ----------------
__device__ __half g_x16[NN * H3];                  // node MLP out, fp16
__device__ __half g_mu16[NN * 3 * HH];             // mu converted to fp16 (for gathers)
__device__ __half g_filters[(size_t)NE * H3];      // fp16 filters (196 MB)
__device__ u32   g_bhp[(HH / 2) * H3];
__device__ u32   g_blp[(HH / 2) * H3];
__device__ u32   g_i1h[(HH / 2) * H3];
__device__ u32   g_i1l[(HH / 2) * H3];
__device__ u32   g_i2h[(H3 / 2) * H3];
__device__ u32   g_i2l[(H3 / 2) * H3];
__device__ u32   g_vch[(HH / 2) * H2];
__device__ u32   g_vcl[(HH / 2) * H2];
__device__ u32   g_m1h[(H2 / 2) * H3];
__device__ u32   g_m1l[(H2 / 2) * H3];
__device__ u32   g_m2h[(H3 / 2) * H3];
__device__ u32   g_m2l[(H3 / 2) * H3];
__device__ float g_qmid[NN * HH];
__device__ float g_mumid[NN * 3 * HH];
__device__ float g_vnorm[NN * HH];
__device__ float g_inner[NN * HH];
__device__ float g_muw[NN * 3 * HH];
__device__ int   g_count[NN];
__device__ int   g_off[NN + 1];
__device__ int   g_cursor[NN];
__device__ int   g_elist[NE];

__device__ __forceinline__ float silu_f(float x) {
    return x / (1.0f + __expf(-x));
}

__device__ __forceinline__ u32 pack_bf16x2(float lo, float hi) {
    u32 r;
    asm("cvt.rn.bf16x2.f32 %0, %1, %2;" : "=r"(r) : "f"(hi), "f"(lo));
    return r;
}

__device__ __forceinline__ void mma_bf16(float& c0, float& c1, float& c2, float& c3,
                                         u32 a0, u32 a1, u32 a2, u32 a3,
                                         u32 b0, u32 b1) {
    asm("mma.sync.aligned.m16n8k16.row.col.f32.bf16.bf16.f32 "
        "{%0,%1,%2,%3}, {%4,%5,%6,%7}, {%8,%9}, {%0,%1,%2,%3};"
        : "+f"(c0), "+f"(c1), "+f"(c2), "+f"(c3)
        : "r"(a0), "r"(a1), "r"(a2), "r"(a3), "r"(b0), "r"(b1));
}

__device__ __forceinline__ void split_a(float2 f, u32& hi, u32& lo) {
    hi = pack_bf16x2(f.x, f.y);
    lo = pack_bf16x2(f.x - __uint_as_float(hi << 16),
                     f.y - __uint_as_float(hi & 0xFFFF0000u));
}

// ---------------- weight split (one-shot, tiny). W is [2*kpairs, width] ----------------
__global__ void k_splitw(const float* __restrict__ W, u32* __restrict__ hi,
                         u32* __restrict__ lo, int kpairs, int width) {
    int i = blockIdx.x * blockDim.x + threadIdx.x;
    if (i < kpairs * width) {
        int p = i / width, col = i % width;
        float w0 = W[(2 * p) * width + col];
        float w1 = W[(2 * p + 1) * width + col];
        u32 h01 = pack_bf16x2(w0, w1);
        float h0 = __uint_as_float(h01 << 16);
        float h1 = __uint_as_float(h01 & 0xFFFF0000u);
        hi[i] = h01;
        lo[i] = pack_bf16x2(w0 - h0, w1 - h1);
    }
}

// ---------------- mu -> fp16 (one-shot) ----------------
__global__ void k_mu2h(const float* __restrict__ mu) {
    int i = blockIdx.x * blockDim.x + threadIdx.x;
    if (i < NN * 3 * HH) g_mu16[i] = __float2half(mu[i]);
}

// ---------------- CSR build ----------------
__global__ void k_zero() {
    int i = blockIdx.x * blockDim.x + threadIdx.x;
    if (i < NN) g_count[i] = 0;
}

__global__ void k_count(const int* __restrict__ ei) {
    for (int e = blockIdx.x * blockDim.x + threadIdx.x; e < NE;
         e += gridDim.x * blockDim.x)
        atomicAdd(&g_count[ei[e]], 1);
}

__global__ __launch_bounds__(1024) void k_scan() {
    __shared__ int ps[1024];
    int tid = threadIdx.x;
    const int CH = (NN + 1023) / 1024;
    int base = tid * CH;
    int s = 0;
    for (int j = 0; j < CH; ++j) {
        int idx = base + j;
        if (idx < NN) s += g_count[idx];
    }
    ps[tid] = s;
    __syncthreads();
    for (int off = 1; off < 1024; off <<= 1) {
        int v = 0;
        if (tid >= off) v = ps[tid - off];
        __syncthreads();
        ps[tid] += v;
        __syncthreads();
    }
    int run = ps[tid] - s;
    for (int j = 0; j < CH; ++j) {
        int idx = base + j;
        if (idx < NN) {
            g_off[idx] = run;
            g_cursor[idx] = run;
            run += g_count[idx];
        }
    }
    if (tid == 1023) g_off[NN] = ps[1023];
}

__global__ void k_fill(const int* __restrict__ ei) {
    for (int e = blockIdx.x * blockDim.x + threadIdx.x; e < NE;
         e += gridDim.x * blockDim.x) {
        int t = ei[e];
        int pos = atomicAdd(&g_cursor[t], 1);
        g_elist[pos] = e;
    }
}

// ---------------- node inter MLP via bf16 split mma ----------------
#define SQP 132
#define SH2P 388
#define NODE_SMEM ((32 * SQP + 32 * SH2P) * 4)
__global__ __launch_bounds__(256) void k_node_mlp(
    const float* __restrict__ q,
    const float* __restrict__ b1, const float* __restrict__ b2)
{
    extern __shared__ float smn[];
    float* sq = smn;
    float* sh = smn + 32 * SQP;
    int tid = threadIdx.x;
    int n0 = blockIdx.x * 32;

    for (int i = tid; i < 32 * HH; i += 256) {
        int r = i >> 7, c = i & 127;
        int n = n0 + r;
        sq[r * SQP + c] = (n < NN) ? q[n * HH + c] : 0.f;
    }
    __syncthreads();

    int wid  = tid >> 5;
    int lane = tid & 31;
    int gid  = lane >> 2;
    int tig  = lane & 3;
    int nbase = wid * 48;

    {
        float acc[2][6][4];
        #pragma unroll
        for (int r = 0; r < 2; ++r)
            #pragma unroll
            for (int t = 0; t < 6; ++t)
                #pragma unroll
                for (int c = 0; c < 4; ++c) acc[r][t][c] = 0.f;

        #pragma unroll 1
        for (int k0 = 0; k0 < HH; k0 += 16) {
            int kp = k0 >> 1;
            u32 bh[6][2], bl[6][2];
            #pragma unroll
            for (int t = 0; t < 6; ++t) {
                int col = nbase + t * 8 + gid;
                int i0 = (kp + tig) * H3 + col;
                int i1 = (kp + 4 + tig) * H3 + col;
                bh[t][0] = __ldg(&g_i1h[i0]);
                bh[t][1] = __ldg(&g_i1h[i1]);
                bl[t][0] = __ldg(&g_i1l[i0]);
                bl[t][1] = __ldg(&g_i1l[i1]);
            }
            #pragma unroll
            for (int r = 0; r < 2; ++r) {
                int rb = r * 16;
                float2 f0 = *(const float2*)&sq[(rb + gid)     * SQP + k0 + 2 * tig];
                float2 f1 = *(const float2*)&sq[(rb + gid + 8) * SQP + k0 + 2 * tig];
                float2 f2 = *(const float2*)&sq[(rb + gid)     * SQP + k0 + 8 + 2 * tig];
                float2 f3 = *(const float2*)&sq[(rb + gid + 8) * SQP + k0 + 8 + 2 * tig];
                u32 ah0, al0, ah1, al1, ah2, al2, ah3, al3;
                split_a(f0, ah0, al0); split_a(f1, ah1, al1);
                split_a(f2, ah2, al2); split_a(f3, ah3, al3);
                #pragma unroll
                for (int t = 0; t < 6; ++t) {
                    mma_bf16(acc[r][t][0], acc[r][t][1], acc[r][t][2], acc[r][t][3],
                             ah0, ah1, ah2, ah3, bh[t][0], bh[t][1]);
                    mma_bf16(acc[r][t][0], acc[r][t][1], acc[r][t][2], acc[r][t][3],
                             al0, al1, al2, al3, bh[t][0], bh[t][1]);
                    mma_bf16(acc[r][t][0], acc[r][t][1], acc[r][t][2], acc[r][t][3],
                             ah0, ah1, ah2, ah3, bl[t][0], bl[t][1]);
                }
            }
        }
        #pragma unroll
        for (int r = 0; r < 2; ++r) {
            int row0 = r * 16 + gid;
            int row1 = row0 + 8;
            #pragma unroll
            for (int t = 0; t < 6; ++t) {
                int col = nbase + t * 8 + 2 * tig;
                float b0v = __ldg(&b1[col]);
                float b1v = __ldg(&b1[col + 1]);
                sh[row0 * SH2P + col]     = silu_f(acc[r][t][0] + b0v);
                sh[row0 * SH2P + col + 1] = silu_f(acc[r][t][1] + b1v);
                sh[row1 * SH2P + col]     = silu_f(acc[r][t][2] + b0v);
                sh[row1 * SH2P + col + 1] = silu_f(acc[r][t][3] + b1v);
            }
        }
    }
    __syncthreads();

    {
        float acc[2][6][4];
        #pragma unroll
        for (int r = 0; r < 2; ++r)
            #pragma unroll
            for (int t = 0; t < 6; ++t)
                #pragma unroll
                for (int c = 0; c < 4; ++c) acc[r][t][c] = 0.f;

        #pragma unroll 1
        for (int k0 = 0; k0 < H3; k0 += 16) {
            int kp = k0 >> 1;
            u32 bh[6][2], bl[6][2];
            #pragma unroll
            for (int t = 0; t < 6; ++t) {
                int col = nbase + t * 8 + gid;
                int i0 = (kp + tig) * H3 + col;
                int i1 = (kp + 4 + tig) * H3 + col;
                bh[t][0] = __ldg(&g_i2h[i0]);
                bh[t][1] = __ldg(&g_i2h[i1]);
                bl[t][0] = __ldg(&g_i2l[i0]);
                bl[t][1] = __ldg(&g_i2l[i1]);
            }
            #pragma unroll
            for (int r = 0; r < 2; ++r) {
                int rb = r * 16;
                float2 f0 = *(const float2*)&sh[(rb + gid)     * SH2P + k0 + 2 * tig];
                float2 f1 = *(const float2*)&sh[(rb + gid + 8) * SH2P + k0 + 2 * tig];
                float2 f2 = *(const float2*)&sh[(rb + gid)     * SH2P + k0 + 8 + 2 * tig];
                float2 f3 = *(const float2*)&sh[(rb + gid + 8) * SH2P + k0 + 8 + 2 * tig];
                u32 ah0, al0, ah1, al1, ah2, al2, ah3, al3;
                split_a(f0, ah0, al0); split_a(f1, ah1, al1);
                split_a(f2, ah2, al2); split_a(f3, ah3, al3);
                #pragma unroll
                for (int t = 0; t < 6; ++t) {
                    mma_bf16(acc[r][t][0], acc[r][t][1], acc[r][t][2], acc[r][t][3],
                             ah0, ah1, ah2, ah3, bh[t][0], bh[t][1]);
                    mma_bf16(acc[r][t][0], acc[r][t][1], acc[r][t][2], acc[r][t][3],
                             al0, al1, al2, al3, bh[t][0], bh[t][1]);
                    mma_bf16(acc[r][t][0], acc[r][t][1], acc[r][t][2], acc[r][t][3],
                             ah0, ah1, ah2, ah3, bl[t][0], bl[t][1]);
                }
            }
        }
        #pragma unroll
        for (int r = 0; r < 2; ++r) {
            int row0 = r * 16 + gid;
            int row1 = row0 + 8;
            #pragma unroll
            for (int t = 0; t < 6; ++t) {
                int col = nbase + t * 8 + 2 * tig;
                float b0v = __ldg(&b2[col]);
                float b1v = __ldg(&b2[col + 1]);
                if (n0 + row0 < NN)
                    *(__half2*)&g_x16[(size_t)(n0 + row0) * H3 + col] =
                        __floats2half2_rn(acc[r][t][0] + b0v, acc[r][t][1] + b1v);
                if (n0 + row1 < NN)
                    *(__half2*)&g_x16[(size_t)(n0 + row1) * H3 + col] =
                        __floats2half2_rn(acc[r][t][2] + b0v, acc[r][t][3] + b1v);
            }
        }
    }
}

// ---------------- edge filter MLP (Round-7 proven: split-in-loop phase 2) ----------------
#define SHP 132
__global__ __launch_bounds__(256) void k_edge_filter(
    const float* __restrict__ rbf, const float* __restrict__ cut,
    const float* __restrict__ Wf1, const float* __restrict__ bf1,
    const float* __restrict__ bf2)
{
    __shared__ float srb[64][NR];
    __shared__ float scut[64];
    __shared__ __align__(16) float sh[64 * SHP];
    int tid = threadIdx.x;
    int e0 = blockIdx.x * 64;

    for (int i = tid; i < 64 * NR; i += 256)
        srb[i / NR][i % NR] = rbf[(e0 + i / NR) * NR + (i % NR)];
    if (tid < 64) scut[tid] = cut[e0 + tid];
    __syncthreads();

    {
        int rg = tid >> 4;
        int cg = tid & 15;
        int r0 = rg * 4;
        for (int pass = 0; pass < 2; ++pass) {
            int c0 = cg * 4 + pass * 64;
            float acc[4][4] = {};
            for (int k = 0; k < NR; ++k) {
                float4 w = *reinterpret_cast<const float4*>(&Wf1[k * HH + c0]);
                #pragma unroll
                for (int i = 0; i < 4; ++i) {
                    float s = srb[r0 + i][k];
                    acc[i][0] = fmaf(s, w.x, acc[i][0]);
                    acc[i][1] = fmaf(s, w.y, acc[i][1]);
                    acc[i][2] = fmaf(s, w.z, acc[i][2]);
                    acc[i][3] = fmaf(s, w.w, acc[i][3]);
                }
            }
            #pragma unroll
            for (int i = 0; i < 4; ++i)
                #pragma unroll
                for (int j = 0; j < 4; ++j)
                    sh[(r0 + i) * SHP + c0 + j] = silu_f(acc[i][j] + bf1[c0 + j]);
        }
    }
    __syncthreads();

    int wid  = tid >> 5;
    int lane = tid & 31;
    int gid  = lane >> 2;
    int tig  = lane & 3;
    int nbase = wid * 48;

    float acc[4][6][4];
    #pragma unroll
    for (int r = 0; r < 4; ++r)
        #pragma unroll
        for (int t = 0; t < 6; ++t)
            #pragma unroll
            for (int c = 0; c < 4; ++c) acc[r][t][c] = 0.f;

    #pragma unroll 1
    for (int k0 = 0; k0 < HH; k0 += 16) {
        int kp = k0 >> 1;
        u32 bh[6][2], bl[6][2];
        #pragma unroll
        for (int t = 0; t < 6; ++t) {
            int col = nbase + t * 8 + gid;
            int i0 = (kp + tig) * H3 + col;
            int i1 = (kp + 4 + tig) * H3 + col;
            bh[t][0] = __ldg(&g_bhp[i0]);
            bh[t][1] = __ldg(&g_bhp[i1]);
            bl[t][0] = __ldg(&g_blp[i0]);
            bl[t][1] = __ldg(&g_blp[i1]);
        }
        #pragma unroll
        for (int r = 0; r < 4; ++r) {
            int rb = r * 16;
            float2 f0 = *(const float2*)&sh[(rb + gid)     * SHP + k0 + 2 * tig];
            float2 f1 = *(const float2*)&sh[(rb + gid + 8) * SHP + k0 + 2 * tig];
            float2 f2 = *(const float2*)&sh[(rb + gid)     * SHP + k0 + 8 + 2 * tig];
            float2 f3 = *(const float2*)&sh[(rb + gid + 8) * SHP + k0 + 8 + 2 * tig];
            u32 ah0, al0, ah1, al1, ah2, al2, ah3, al3;
            split_a(f0, ah0, al0); split_a(f1, ah1, al1);
            split_a(f2, ah2, al2); split_a(f3, ah3, al3);
            #pragma unroll
            for (int t = 0; t < 6; ++t) {
                mma_bf16(acc[r][t][0], acc[r][t][1], acc[r][t][2], acc[r][t][3],
                         ah0, ah1, ah2, ah3, bh[t][0], bh[t][1]);
                mma_bf16(acc[r][t][0], acc[r][t][1], acc[r][t][2], acc[r][t][3],
                         al0, al1, al2, al3, bh[t][0], bh[t][1]);
                mma_bf16(acc[r][t][0], acc[r][t][1], acc[r][t][2], acc[r][t][3],
                         ah0, ah1, ah2, ah3, bl[t][0], bl[t][1]);
            }
        }
    }

    #pragma unroll
    for (int r = 0; r < 4; ++r) {
        int row0 = r * 16 + gid;
        int row1 = row0 + 8;
        float c0v = scut[row0];
        float c1v = scut[row1];
        #pragma unroll
        for (int t = 0; t < 6; ++t) {
            int col = nbase + t * 8 + 2 * tig;
            float b0v = bf2[col];
            float b1v = bf2[col + 1];
            __half2 v0 = __floats2half2_rn((acc[r][t][0] + b0v) * c0v,
                                           (acc[r][t][1] + b1v) * c0v);
            __half2 v1 = __floats2half2_rn((acc[r][t][2] + b0v) * c1v,
                                           (acc[r][t][3] + b1v) * c1v);
            *(__half2*)&g_filters[(size_t)(e0 + row0) * H3 + col] = v0;
            *(__half2*)&g_filters[(size_t)(e0 + row1) * H3 + col] = v1;
        }
    }
}

// ---------------- pull aggregation (CSR) -> qmid, mumid (fp16 gathers) ----------------
__global__ __launch_bounds__(128) void k_aggregate(
    const float* __restrict__ q, const float* __restrict__ mu,
    const int* __restrict__ ei, const float* __restrict__ uv)
{
    int n = blockIdx.x;
    int h = threadIdx.x;
    int beg = g_off[n], end = g_off[n + 1];
    float qa = 0.f, m0 = 0.f, m1 = 0.f, m2 = 0.f;
    for (int i = beg; i < end; ++i) {
        int e = g_elist[i];
        int s = ei[NE + e];
        const __half* f = &g_filters[(size_t)e * H3];
        float fq = __half2float(f[h]);
        float fr = __half2float(f[HH + h]);
        float fm = __half2float(f[2 * HH + h]);
        const __half* xs = &g_x16[s * H3];
        float xq = __half2float(xs[h]) * fq;
        float xr = __half2float(xs[HH + h]) * fr;
        float xm = __half2float(xs[2 * HH + h]) * fm;
        float u0 = uv[e * 3 + 0], u1 = uv[e * 3 + 1], u2 = uv[e * 3 + 2];
        const __half* ms = &g_mu16[s * 3 * HH];
        qa += xq;
        m0 = fmaf(u0, xr, fmaf(__half2float(ms[h]),          xm, m0));
        m1 = fmaf(u1, xr, fmaf(__half2float(ms[HH + h]),     xm, m1));
        m2 = fmaf(u2, xr, fmaf(__half2float(ms[2 * HH + h]), xm, m2));
    }
    g_qmid[n * HH + h] = q[n * HH + h] + qa;
    g_mumid[n * 3 * HH + h]          = mu[n * 3 * HH + h] + m0;
    g_mumid[n * 3 * HH + HH + h]     = mu[n * 3 * HH + HH + h] + m1;
    g_mumid[n * 3 * HH + 2 * HH + h] = mu[n * 3 * HH + 2 * HH + h] + m2;
}

// ---------------- equivariant linear via bf16 split mma ----------------
#define EMP 132
#define EOP 260
#define EQ_SMEM ((48 * EMP + 48 * EOP) * 4)
__global__ __launch_bounds__(256) void k_equiv()
{
    extern __shared__ float sme[];
    float* smu  = sme;
    float* sout = sme + 48 * EMP;
    int tid = threadIdx.x;
    int n0 = blockIdx.x * 16;
    int row_base = n0 * 3;

    for (int i = tid; i < 48 * HH; i += 256) {
        int r = i >> 7, c = i & 127;
        int grow = row_base + r;
        smu[r * EMP + c] = (grow < NN * 3) ? g_mumid[grow * HH + c] : 0.f;
    }
    __syncthreads();

    int wid  = tid >> 5;
    int lane = tid & 31;
    int gid  = lane >> 2;
    int tig  = lane & 3;
    int nbase = wid * 32;

    float acc[3][4][4];
    #pragma unroll
    for (int r = 0; r < 3; ++r)
        #pragma unroll
        for (int t = 0; t < 4; ++t)
            #pragma unroll
            for (int c = 0; c < 4; ++c) acc[r][t][c] = 0.f;

    #pragma unroll 1
    for (int k0 = 0; k0 < HH; k0 += 16) {
        int kp = k0 >> 1;
        u32 bh[4][2], bl[4][2];
        #pragma unroll
        for (int t = 0; t < 4; ++t) {
            int col = nbase + t * 8 + gid;
            int i0 = (kp + tig) * H2 + col;
            int i1 = (kp + 4 + tig) * H2 + col;
            bh[t][0] = __ldg(&g_vch[i0]);
            bh[t][1] = __ldg(&g_vch[i1]);
            bl[t][0] = __ldg(&g_vcl[i0]);
            bl[t][1] = __ldg(&g_vcl[i1]);
        }
        #pragma unroll
        for (int r = 0; r < 3; ++r) {
            int rb = r * 16;
            float2 f0 = *(const float2*)&smu[(rb + gid)     * EMP + k0 + 2 * tig];
            float2 f1 = *(const float2*)&smu[(rb + gid + 8) * EMP + k0 + 2 * tig];
            float2 f2 = *(const float2*)&smu[(rb + gid)     * EMP + k0 + 8 + 2 * tig];
            float2 f3 = *(const float2*)&smu[(rb + gid + 8) * EMP + k0 + 8 + 2 * tig];
            u32 ah0, al0, ah1, al1, ah2, al2, ah3, al3;
            split_a(f0, ah0, al0); split_a(f1, ah1, al1);
            split_a(f2, ah2, al2); split_a(f3, ah3, al3);
            #pragma unroll
            for (int t = 0; t < 4; ++t) {
                mma_bf16(acc[r][t][0], acc[r][t][1], acc[r][t][2], acc[r][t][3],
                         ah0, ah1, ah2, ah3, bh[t][0], bh[t][1]);
                mma_bf16(acc[r][t][0], acc[r][t][1], acc[r][t][2], acc[r][t][3],
                         al0, al1, al2, al3, bh[t][0], bh[t][1]);
                mma_bf16(acc[r][t][0], acc[r][t][1], acc[r][t][2], acc[r][t][3],
                         ah0, ah1, ah2, ah3, bl[t][0], bl[t][1]);
            }
        }
    }

    #pragma unroll
    for (int r = 0; r < 3; ++r) {
        int row0 = r * 16 + gid;
        int row1 = row0 + 8;
        #pragma unroll
        for (int t = 0; t < 4; ++t) {
            int col = nbase + t * 8 + 2 * tig;
            sout[row0 * EOP + col]     = acc[r][t][0];
            sout[row0 * EOP + col + 1] = acc[r][t][1];
            sout[row1 * EOP + col]     = acc[r][t][2];
            sout[row1 * EOP + col + 1] = acc[r][t][3];
        }
    }
    __syncthreads();

    for (int slot = tid; slot < 16 * HH; slot += 256) {
        int r = slot >> 7;
        int o = slot & 127;
        int n = n0 + r;
        if (n >= NN) break;
        float v0 = sout[(r * 3 + 0) * EOP + o];
        float v1 = sout[(r * 3 + 1) * EOP + o];
        float v2 = sout[(r * 3 + 2) * EOP + o];
        float w0 = sout[(r * 3 + 0) * EOP + HH + o];
        float w1 = sout[(r * 3 + 1) * EOP + HH + o];
        float w2 = sout[(r * 3 + 2) * EOP + HH + o];
        g_vnorm[n * HH + o] = sqrtf(v0 * v0 + v1 * v1 + v2 * v2 + 1e-8f);
        g_inner[n * HH + o] = v0 * w0 + v1 * w1 + v2 * w2;
        g_muw[n * 3 * HH + o]          = w0;
        g_muw[n * 3 * HH + HH + o]     = w1;
        g_muw[n * 3 * HH + 2 * HH + o] = w2;
    }
}

// ---------------- scalar mix MLP via bf16 split mma + final update ----------------
#define MXP 388
#define MIX_SMEM ((32 * MXP * 2) * 4)
__global__ __launch_bounds__(256) void k_mix(
    const float* __restrict__ bm1, const float* __restrict__ bm2,
    float* __restrict__ qout, float* __restrict__ muout)
{
    extern __shared__ float smx[];
    float* sA = smx;
    float* sB = smx + 32 * MXP;
    int tid = threadIdx.x;
    int n0 = blockIdx.x * 32;

    for (int i = tid; i < 32 * H2; i += 256) {
        int r = i >> 8, c = i & 255;
        int n = n0 + r;
        float v = 0.f;
        if (n < NN) v = (c < HH) ? g_qmid[n * HH + c] : g_vnorm[n * HH + (c - HH)];
        sA[r * MXP + c] = v;
    }
    __syncthreads();

    int wid  = tid >> 5;
    int lane = tid & 31;
    int gid  = lane >> 2;
    int tig  = lane & 3;
    int nbase = wid * 48;

    {
        float acc[2][6][4];
        #pragma unroll
        for (int r = 0; r < 2; ++r)
            #pragma unroll
            for (int t = 0; t < 6; ++t)
                #pragma unroll
                for (int c = 0; c < 4; ++c) acc[r][t][c] = 0.f;

        #pragma unroll 1
        for (int k0 = 0; k0 < H2; k0 += 16) {
            int kp = k0 >> 1;
            u32 bh[6][2], bl[6][2];
            #pragma unroll
            for (int t = 0; t < 6; ++t) {
                int col = nbase + t * 8 + gid;
                int i0 = (kp + tig) * H3 + col;
                int i1 = (kp + 4 + tig) * H3 + col;
                bh[t][0] = __ldg(&g_m1h[i0]);
                bh[t][1] = __ldg(&g_m1h[i1]);
                bl[t][0] = __ldg(&g_m1l[i0]);
                bl[t][1] = __ldg(&g_m1l[i1]);
            }
            #pragma unroll
            for (int r = 0; r < 2; ++r) {
                int rb = r * 16;
                float2 f0 = *(const float2*)&sA[(rb + gid)     * MXP + k0 + 2 * tig];
                float2 f1 = *(const float2*)&sA[(rb + gid + 8) * MXP + k0 + 2 * tig];
                float2 f2 = *(const float2*)&sA[(rb + gid)     * MXP + k0 + 8 + 2 * tig];
                float2 f3 = *(const float2*)&sA[(rb + gid + 8) * MXP + k0 + 8 + 2 * tig];
                u32 ah0, al0, ah1, al1, ah2, al2, ah3, al3;
                split_a(f0, ah0, al0); split_a(f1, ah1, al1);
                split_a(f2, ah2, al2); split_a(f3, ah3, al3);
                #pragma unroll
                for (int t = 0; t < 6; ++t) {
                    mma_bf16(acc[r][t][0], acc[r][t][1], acc[r][t][2], acc[r][t][3],
                             ah0, ah1, ah2, ah3, bh[t][0], bh[t][1]);
                    mma_bf16(acc[r][t][0], acc[r][t][1], acc[r][t][2], acc[r][t][3],
                             al0, al1, al2, al3, bh[t][0], bh[t][1]);
                    mma_bf16(acc[r][t][0], acc[r][t][1], acc[r][t][2], acc[r][t][3],
                             ah0, ah1, ah2, ah3, bl[t][0], bl[t][1]);
                }
            }
        }
        #pragma unroll
        for (int r = 0; r < 2; ++r) {
            int row0 = r * 16 + gid;
            int row1 = row0 + 8;
            #pragma unroll
            for (int t = 0; t < 6; ++t) {
                int col = nbase + t * 8 + 2 * tig;
                float b0v = __ldg(&bm1[col]);
                float b1v = __ldg(&bm1[col + 1]);
                sB[row0 * MXP + col]     = silu_f(acc[r][t][0] + b0v);
                sB[row0 * MXP + col + 1] = silu_f(acc[r][t][1] + b1v);
                sB[row1 * MXP + col]     = silu_f(acc[r][t][2] + b0v);
                sB[row1 * MXP + col + 1] = silu_f(acc[r][t][3] + b1v);
            }
        }
    }
    __syncthreads();

    {
        float acc[2][6][4];
        #pragma unroll
        for (int r = 0; r < 2; ++r)
            #pragma unroll
            for (int t = 0; t < 6; ++t)
                #pragma unroll
                for (int c = 0; c < 4; ++c) acc[r][t][c] = 0.f;

        #pragma unroll 1
        for (int k0 = 0; k0 < H3; k0 += 16) {
            int kp = k0 >> 1;
            u32 bh[6][2], bl[6][2];
            #pragma unroll
            for (int t = 0; t < 6; ++t) {
                int col = nbase + t * 8 + gid;
                int i0 = (kp + tig) * H3 + col;
                int i1 = (kp + 4 + tig) * H3 + col;
                bh[t][0] = __ldg(&g_m2h[i0]);
                bh[t][1] = __ldg(&g_m2h[i1]);
                bl[t][0] = __ldg(&g_m2l[i0]);
                bl[t][1] = __ldg(&g_m2l[i1]);
            }
            #pragma unroll
            for (int r = 0; r < 2; ++r) {
                int rb = r * 16;
                float2 f0 = *(const float2*)&sB[(rb + gid)     * MXP + k0 + 2 * tig];
                float2 f1 = *(const float2*)&sB[(rb + gid + 8) * MXP + k0 + 2 * tig];
                float2 f2 = *(const float2*)&sB[(rb + gid)     * MXP + k0 + 8 + 2 * tig];
                float2 f3 = *(const float2*)&sB[(rb + gid + 8) * MXP + k0 + 8 + 2 * tig];
                u32 ah0, al0, ah1, al1, ah2, al2, ah3, al3;
                split_a(f0, ah0, al0); split_a(f1, ah1, al1);
                split_a(f2, ah2, al2); split_a(f3, ah3, al3);
                #pragma unroll
                for (int t = 0; t < 6; ++t) {
                    mma_bf16(acc[r][t][0], acc[r][t][1], acc[r][t][2], acc[r][t][3],
                             ah0, ah1, ah2, ah3, bh[t][0], bh[t][1]);
                    mma_bf16(acc[r][t][0], acc[r][t][1], acc[r][t][2], acc[r][t][3],
                             al0, al1, al2, al3, bh[t][0], bh[t][1]);
                    mma_bf16(acc[r][t][0], acc[r][t][1], acc[r][t][2], acc[r][t][3],
                             ah0, ah1, ah2, ah3, bl[t][0], bl[t][1]);
                }
            }
        }
        __syncthreads();
        #pragma unroll
        for (int r = 0; r < 2; ++r) {
            int row0 = r * 16 + gid;
            int row1 = row0 + 8;
            #pragma unroll
            for (int t = 0; t < 6; ++t) {
                int col = nbase + t * 8 + 2 * tig;
                float b0v = __ldg(&bm2[col]);
                float b1v = __ldg(&bm2[col + 1]);
                sA[row0 * MXP + col]     = acc[r][t][0] + b0v;
                sA[row0 * MXP + col + 1] = acc[r][t][1] + b1v;
                sA[row1 * MXP + col]     = acc[r][t][2] + b0v;
                sA[row1 * MXP + col + 1] = acc[r][t][3] + b1v;
            }
        }
    }
    __syncthreads();

    for (int slot = tid; slot < 32 * HH; slot += 256) {
        int r = slot >> 7;
        int o = slot & 127;
        int n = n0 + r;
        if (n >= NN) break;
        float dq  = sA[r * MXP + o];
        float dms = sA[r * MXP + HH + o];
        float dqm = sA[r * MXP + 2 * HH + o];
        qout[n * HH + o] = g_qmid[n * HH + o] + dq + dqm * g_inner[n * HH + o];
        #pragma unroll
        for (int d = 0; d < 3; ++d) {
            int idx = n * 3 * HH + d * HH + o;
            muout[idx] = g_mumid[idx] + g_muw[idx] * dms;
        }
    }
}

// ---------------- launch ----------------
extern "C" void kernel_launch(void* const* d_in, const int* in_sizes, int n_in,
                              void* d_out, int out_size)
{
    const float* q   = (const float*)d_in[0];
    const float* mu  = (const float*)d_in[1];
    const int*   ei  = (const int*)d_in[2];
    const float* rbf = (const float*)d_in[3];
    const float* uv  = (const float*)d_in[4];
    const float* cut = (const float*)d_in[5];
    const float* Wi1 = (const float*)d_in[6];
    const float* bi1 = (const float*)d_in[7];
    const float* Wi2 = (const float*)d_in[8];
    const float* bi2 = (const float*)d_in[9];
    const float* Wf1 = (const float*)d_in[10];
    const float* bf1 = (const float*)d_in[11];
    const float* Wf2 = (const float*)d_in[12];
    const float* bf2 = (const float*)d_in[13];
    const float* Wv  = (const float*)d_in[14];
    const float* Wm1 = (const float*)d_in[15];
    const float* bm1 = (const float*)d_in[16];
    const float* Wm2 = (const float*)d_in[17];
    const float* bm2 = (const float*)d_in[18];

    float* qout  = (float*)d_out;
    float* muout = qout + (size_t)NN * HH;

    cudaFuncSetAttribute(k_node_mlp, cudaFuncAttributeMaxDynamicSharedMemorySize, NODE_SMEM);
    cudaFuncSetAttribute(k_equiv,    cudaFuncAttributeMaxDynamicSharedMemorySize, EQ_SMEM);
    cudaFuncSetAttribute(k_mix,      cudaFuncAttributeMaxDynamicSharedMemorySize, MIX_SMEM);

    // CSR build + weight splits + mu conversion
    k_zero<<<(NN + 255) / 256, 256>>>();
    k_count<<<512, 256>>>(ei);
    k_mu2h<<<(NN * 3 * HH + 255) / 256, 256>>>(mu);
    {
        u32 *p0, *p1;
        cudaGetSymbolAddress((void**)&p0, g_bhp); cudaGetSymbolAddress((void**)&p1, g_blp);
        k_splitw<<<((HH / 2) * H3 + 255) / 256, 256>>>(Wf2, p0, p1, HH / 2, H3);
        cudaGetSymbolAddress((void**)&p0, g_i1h); cudaGetSymbolAddress((void**)&p1, g_i1l);
        k_splitw<<<((HH / 2) * H3 + 255) / 256, 256>>>(Wi1, p0, p1, HH / 2, H3);
        cudaGetSymbolAddress((void**)&p0, g_i2h); cudaGetSymbolAddress((void**)&p1, g_i2l);
        k_splitw<<<((H3 / 2) * H3 + 255) / 256, 256>>>(Wi2, p0, p1, H3 / 2, H3);
        cudaGetSymbolAddress((void**)&p0, g_vch); cudaGetSymbolAddress((void**)&p1, g_vcl);
        k_splitw<<<((HH / 2) * H2 + 255) / 256, 256>>>(Wv, p0, p1, HH / 2, H2);
        cudaGetSymbolAddress((void**)&p0, g_m1h); cudaGetSymbolAddress((void**)&p1, g_m1l);
        k_splitw<<<((H2 / 2) * H3 + 255) / 256, 256>>>(Wm1, p0, p1, H2 / 2, H3);
        cudaGetSymbolAddress((void**)&p0, g_m2h); cudaGetSymbolAddress((void**)&p1, g_m2l);
        k_splitw<<<((H3 / 2) * H3 + 255) / 256, 256>>>(Wm2, p0, p1, H3 / 2, H3);
    }
    k_scan<<<1, 1024>>>();
    k_fill<<<512, 256>>>(ei);

    // dense stages
    k_node_mlp<<<(NN + 31) / 32, 256, NODE_SMEM>>>(q, bi1, bi2);
    k_edge_filter<<<NE / 64, 256>>>(rbf, cut, Wf1, bf1, bf2);

    // message aggregation
    k_aggregate<<<NN, 128>>>(q, mu, ei, uv);

    // mixing
    k_equiv<<<(NN + 15) / 16, 256, EQ_SMEM>>>();
    k_mix<<<(NN + 31) / 32, 256, MIX_SMEM>>>(bm1, bm2, qout, muout);
}

// round 10
// speedup vs baseline: 1.0326x; 1.0326x over previous
#include <cuda_runtime.h>
#include <cuda_bf16.h>
#include <cuda_fp16.h>
#include <math.h>

#define NN 10000
#define NE 256000
#define HH 128
#define H2 256
#define H3 384
#define NR 20

typedef unsigned int u32;

// ---------------- scratch (static device globals; no allocation) ----------------
__device__ float  g_x[NN * H3];                    // node MLP out (fp32, L2-resident)
__device__ __half g_filters[(size_t)NE * H3];      // fp16 filters in CSR order (196 MB)
__device__ float4 g_uv4[NE];                       // unit vectors in CSR order
__device__ int    g_src[NE];                       // source node in CSR order
__device__ int    g_epos[NE];                      // edge -> CSR position
__device__ u32   g_bhp[(HH / 2) * H3];
__device__ u32   g_blp[(HH / 2) * H3];
__device__ u32   g_i1h[(HH / 2) * H3];
__device__ u32   g_i1l[(HH / 2) * H3];
__device__ u32   g_i2h[(H3 / 2) * H3];
__device__ u32   g_i2l[(H3 / 2) * H3];
__device__ u32   g_vch[(HH / 2) * H2];
__device__ u32   g_vcl[(HH / 2) * H2];
__device__ u32   g_m1h[(H2 / 2) * H3];
__device__ u32   g_m1l[(H2 / 2) * H3];
__device__ u32   g_m2h[(H3 / 2) * H3];
__device__ u32   g_m2l[(H3 / 2) * H3];
__device__ float g_qmid[NN * HH];
__device__ float g_mumid[NN * 3 * HH];
__device__ float g_vnorm[NN * HH];
__device__ float g_inner[NN * HH];
__device__ float g_muw[NN * 3 * HH];
__device__ int   g_count[NN];
__device__ int   g_off[NN + 1];
__device__ int   g_cursor[NN];

__device__ __forceinline__ float silu_f(float x) {
    return x / (1.0f + __expf(-x));
}

__device__ __forceinline__ u32 pack_bf16x2(float lo, float hi) {
    u32 r;
    asm("cvt.rn.bf16x2.f32 %0, %1, %2;" : "=r"(r) : "f"(hi), "f"(lo));
    return r;
}

__device__ __forceinline__ void mma_bf16(float& c0, float& c1, float& c2, float& c3,
                                         u32 a0, u32 a1, u32 a2, u32 a3,
                                         u32 b0, u32 b1) {
    asm("mma.sync.aligned.m16n8k16.row.col.f32.bf16.bf16.f32 "
        "{%0,%1,%2,%3}, {%4,%5,%6,%7}, {%8,%9}, {%0,%1,%2,%3};"
        : "+f"(c0), "+f"(c1), "+f"(c2), "+f"(c3)
        : "r"(a0), "r"(a1), "r"(a2), "r"(a3), "r"(b0), "r"(b1));
}

__device__ __forceinline__ void split_a(float2 f, u32& hi, u32& lo) {
    hi = pack_bf16x2(f.x, f.y);
    lo = pack_bf16x2(f.x - __uint_as_float(hi << 16),
                     f.y - __uint_as_float(hi & 0xFFFF0000u));
}

// ---------------- weight split (one-shot, tiny). W is [2*kpairs, width] ----------------
__global__ void k_splitw(const float* __restrict__ W, u32* __restrict__ hi,
                         u32* __restrict__ lo, int kpairs, int width) {
    int i = blockIdx.x * blockDim.x + threadIdx.x;
    if (i < kpairs * width) {
        int p = i / width, col = i % width;
        float w0 = W[(2 * p) * width + col];
        float w1 = W[(2 * p + 1) * width + col];
        u32 h01 = pack_bf16x2(w0, w1);
        float h0 = __uint_as_float(h01 << 16);
        float h1 = __uint_as_float(h01 & 0xFFFF0000u);
        hi[i] = h01;
        lo[i] = pack_bf16x2(w0 - h0, w1 - h1);
    }
}

// ---------------- CSR build ----------------
__global__ void k_zero() {
    int i = blockIdx.x * blockDim.x + threadIdx.x;
    if (i < NN) g_count[i] = 0;
}

__global__ void k_count(const int* __restrict__ ei) {
    for (int e = blockIdx.x * blockDim.x + threadIdx.x; e < NE;
         e += gridDim.x * blockDim.x)
        atomicAdd(&g_count[ei[e]], 1);
}

__global__ __launch_bounds__(1024) void k_scan() {
    __shared__ int ps[1024];
    int tid = threadIdx.x;
    const int CH = (NN + 1023) / 1024;
    int base = tid * CH;
    int s = 0;
    for (int j = 0; j < CH; ++j) {
        int idx = base + j;
        if (idx < NN) s += g_count[idx];
    }
    ps[tid] = s;
    __syncthreads();
    for (int off = 1; off < 1024; off <<= 1) {
        int v = 0;
        if (tid >= off) v = ps[tid - off];
        __syncthreads();
        ps[tid] += v;
        __syncthreads();
    }
    int run = ps[tid] - s;
    for (int j = 0; j < CH; ++j) {
        int idx = base + j;
        if (idx < NN) {
            g_off[idx] = run;
            g_cursor[idx] = run;
            run += g_count[idx];
        }
    }
    if (tid == 1023) g_off[NN] = ps[1023];
}

// fill: scatter edge data into CSR order
__global__ void k_fill(const int* __restrict__ ei, const float* __restrict__ uv) {
    for (int e = blockIdx.x * blockDim.x + threadIdx.x; e < NE;
         e += gridDim.x * blockDim.x) {
        int t = ei[e];
        int pos = atomicAdd(&g_cursor[t], 1);
        g_epos[e] = pos;
        g_src[pos] = ei[NE + e];
        g_uv4[pos] = make_float4(uv[3 * e], uv[3 * e + 1], uv[3 * e + 2], 0.f);
    }
}

// ---------------- node inter MLP via bf16 split mma (R7 proven) ----------------
#define SQP 132
#define SH2P 388
#define NODE_SMEM ((32 * SQP + 32 * SH2P) * 4)
__global__ __launch_bounds__(256) void k_node_mlp(
    const float* __restrict__ q,
    const float* __restrict__ b1, const float* __restrict__ b2)
{
    extern __shared__ float smn[];
    float* sq = smn;
    float* sh = smn + 32 * SQP;
    int tid = threadIdx.x;
    int n0 = blockIdx.x * 32;

    for (int i = tid; i < 32 * HH; i += 256) {
        int r = i >> 7, c = i & 127;
        int n = n0 + r;
        sq[r * SQP + c] = (n < NN) ? q[n * HH + c] : 0.f;
    }
    __syncthreads();

    int wid  = tid >> 5;
    int lane = tid & 31;
    int gid  = lane >> 2;
    int tig  = lane & 3;
    int nbase = wid * 48;

    {
        float acc[2][6][4];
        #pragma unroll
        for (int r = 0; r < 2; ++r)
            #pragma unroll
            for (int t = 0; t < 6; ++t)
                #pragma unroll
                for (int c = 0; c < 4; ++c) acc[r][t][c] = 0.f;

        #pragma unroll 1
        for (int k0 = 0; k0 < HH; k0 += 16) {
            int kp = k0 >> 1;
            u32 bh[6][2], bl[6][2];
            #pragma unroll
            for (int t = 0; t < 6; ++t) {
                int col = nbase + t * 8 + gid;
                int i0 = (kp + tig) * H3 + col;
                int i1 = (kp + 4 + tig) * H3 + col;
                bh[t][0] = __ldg(&g_i1h[i0]);
                bh[t][1] = __ldg(&g_i1h[i1]);
                bl[t][0] = __ldg(&g_i1l[i0]);
                bl[t][1] = __ldg(&g_i1l[i1]);
            }
            #pragma unroll
            for (int r = 0; r < 2; ++r) {
                int rb = r * 16;
                float2 f0 = *(const float2*)&sq[(rb + gid)     * SQP + k0 + 2 * tig];
                float2 f1 = *(const float2*)&sq[(rb + gid + 8) * SQP + k0 + 2 * tig];
                float2 f2 = *(const float2*)&sq[(rb + gid)     * SQP + k0 + 8 + 2 * tig];
                float2 f3 = *(const float2*)&sq[(rb + gid + 8) * SQP + k0 + 8 + 2 * tig];
                u32 ah0, al0, ah1, al1, ah2, al2, ah3, al3;
                split_a(f0, ah0, al0); split_a(f1, ah1, al1);
                split_a(f2, ah2, al2); split_a(f3, ah3, al3);
                #pragma unroll
                for (int t = 0; t < 6; ++t) {
                    mma_bf16(acc[r][t][0], acc[r][t][1], acc[r][t][2], acc[r][t][3],
                             ah0, ah1, ah2, ah3, bh[t][0], bh[t][1]);
                    mma_bf16(acc[r][t][0], acc[r][t][1], acc[r][t][2], acc[r][t][3],
                             al0, al1, al2, al3, bh[t][0], bh[t][1]);
                    mma_bf16(acc[r][t][0], acc[r][t][1], acc[r][t][2], acc[r][t][3],
                             ah0, ah1, ah2, ah3, bl[t][0], bl[t][1]);
                }
            }
        }
        #pragma unroll
        for (int r = 0; r < 2; ++r) {
            int row0 = r * 16 + gid;
            int row1 = row0 + 8;
            #pragma unroll
            for (int t = 0; t < 6; ++t) {
                int col = nbase + t * 8 + 2 * tig;
                float b0v = __ldg(&b1[col]);
                float b1v = __ldg(&b1[col + 1]);
                sh[row0 * SH2P + col]     = silu_f(acc[r][t][0] + b0v);
                sh[row0 * SH2P + col + 1] = silu_f(acc[r][t][1] + b1v);
                sh[row1 * SH2P + col]     = silu_f(acc[r][t][2] + b0v);
                sh[row1 * SH2P + col + 1] = silu_f(acc[r][t][3] + b1v);
            }
        }
    }
    __syncthreads();

    {
        float acc[2][6][4];
        #pragma unroll
        for (int r = 0; r < 2; ++r)
            #pragma unroll
            for (int t = 0; t < 6; ++t)
                #pragma unroll
                for (int c = 0; c < 4; ++c) acc[r][t][c] = 0.f;

        #pragma unroll 1
        for (int k0 = 0; k0 < H3; k0 += 16) {
            int kp = k0 >> 1;
            u32 bh[6][2], bl[6][2];
            #pragma unroll
            for (int t = 0; t < 6; ++t) {
                int col = nbase + t * 8 + gid;
                int i0 = (kp + tig) * H3 + col;
                int i1 = (kp + 4 + tig) * H3 + col;
                bh[t][0] = __ldg(&g_i2h[i0]);
                bh[t][1] = __ldg(&g_i2h[i1]);
                bl[t][0] = __ldg(&g_i2l[i0]);
                bl[t][1] = __ldg(&g_i2l[i1]);
            }
            #pragma unroll
            for (int r = 0; r < 2; ++r) {
                int rb = r * 16;
                float2 f0 = *(const float2*)&sh[(rb + gid)     * SH2P + k0 + 2 * tig];
                float2 f1 = *(const float2*)&sh[(rb + gid + 8) * SH2P + k0 + 2 * tig];
                float2 f2 = *(const float2*)&sh[(rb + gid)     * SH2P + k0 + 8 + 2 * tig];
                float2 f3 = *(const float2*)&sh[(rb + gid + 8) * SH2P + k0 + 8 + 2 * tig];
                u32 ah0, al0, ah1, al1, ah2, al2, ah3, al3;
                split_a(f0, ah0, al0); split_a(f1, ah1, al1);
                split_a(f2, ah2, al2); split_a(f3, ah3, al3);
                #pragma unroll
                for (int t = 0; t < 6; ++t) {
                    mma_bf16(acc[r][t][0], acc[r][t][1], acc[r][t][2], acc[r][t][3],
                             ah0, ah1, ah2, ah3, bh[t][0], bh[t][1]);
                    mma_bf16(acc[r][t][0], acc[r][t][1], acc[r][t][2], acc[r][t][3],
                             al0, al1, al2, al3, bh[t][0], bh[t][1]);
                    mma_bf16(acc[r][t][0], acc[r][t][1], acc[r][t][2], acc[r][t][3],
                             ah0, ah1, ah2, ah3, bl[t][0], bl[t][1]);
                }
            }
        }
        #pragma unroll
        for (int r = 0; r < 2; ++r) {
            int row0 = r * 16 + gid;
            int row1 = row0 + 8;
            #pragma unroll
            for (int t = 0; t < 6; ++t) {
                int col = nbase + t * 8 + 2 * tig;
                float b0v = __ldg(&b2[col]);
                float b1v = __ldg(&b2[col + 1]);
                if (n0 + row0 < NN)
                    *(float2*)&g_x[(size_t)(n0 + row0) * H3 + col] =
                        make_float2(acc[r][t][0] + b0v, acc[r][t][1] + b1v);
                if (n0 + row1 < NN)
                    *(float2*)&g_x[(size_t)(n0 + row1) * H3 + col] =
                        make_float2(acc[r][t][2] + b0v, acc[r][t][3] + b1v);
            }
        }
    }
}

// ---------------- edge filter MLP (R7 proven; writes to CSR positions) ----------------
#define SHP 132
__global__ __launch_bounds__(256) void k_edge_filter(
    const float* __restrict__ rbf, const float* __restrict__ cut,
    const float* __restrict__ Wf1, const float* __restrict__ bf1,
    const float* __restrict__ bf2)
{
    __shared__ float srb[64][NR];
    __shared__ float scut[64];
    __shared__ int   spos[64];
    __shared__ __align__(16) float sh[64 * SHP];
    int tid = threadIdx.x;
    int e0 = blockIdx.x * 64;

    for (int i = tid; i < 64 * NR; i += 256)
        srb[i / NR][i % NR] = rbf[(e0 + i / NR) * NR + (i % NR)];
    if (tid < 64) {
        scut[tid] = cut[e0 + tid];
        spos[tid] = g_epos[e0 + tid];
    }
    __syncthreads();

    {
        int rg = tid >> 4;
        int cg = tid & 15;
        int r0 = rg * 4;
        for (int pass = 0; pass < 2; ++pass) {
            int c0 = cg * 4 + pass * 64;
            float acc[4][4] = {};
            for (int k = 0; k < NR; ++k) {
                float4 w = *reinterpret_cast<const float4*>(&Wf1[k * HH + c0]);
                #pragma unroll
                for (int i = 0; i < 4; ++i) {
                    float s = srb[r0 + i][k];
                    acc[i][0] = fmaf(s, w.x, acc[i][0]);
                    acc[i][1] = fmaf(s, w.y, acc[i][1]);
                    acc[i][2] = fmaf(s, w.z, acc[i][2]);
                    acc[i][3] = fmaf(s, w.w, acc[i][3]);
                }
            }
            #pragma unroll
            for (int i = 0; i < 4; ++i)
                #pragma unroll
                for (int j = 0; j < 4; ++j)
                    sh[(r0 + i) * SHP + c0 + j] = silu_f(acc[i][j] + bf1[c0 + j]);
        }
    }
    __syncthreads();

    int wid  = tid >> 5;
    int lane = tid & 31;
    int gid  = lane >> 2;
    int tig  = lane & 3;
    int nbase = wid * 48;

    float acc[4][6][4];
    #pragma unroll
    for (int r = 0; r < 4; ++r)
        #pragma unroll
        for (int t = 0; t < 6; ++t)
            #pragma unroll
            for (int c = 0; c < 4; ++c) acc[r][t][c] = 0.f;

    #pragma unroll 1
    for (int k0 = 0; k0 < HH; k0 += 16) {
        int kp = k0 >> 1;
        u32 bh[6][2], bl[6][2];
        #pragma unroll
        for (int t = 0; t < 6; ++t) {
            int col = nbase + t * 8 + gid;
            int i0 = (kp + tig) * H3 + col;
            int i1 = (kp + 4 + tig) * H3 + col;
            bh[t][0] = __ldg(&g_bhp[i0]);
            bh[t][1] = __ldg(&g_bhp[i1]);
            bl[t][0] = __ldg(&g_blp[i0]);
            bl[t][1] = __ldg(&g_blp[i1]);
        }
        #pragma unroll
        for (int r = 0; r < 4; ++r) {
            int rb = r * 16;
            float2 f0 = *(const float2*)&sh[(rb + gid)     * SHP + k0 + 2 * tig];
            float2 f1 = *(const float2*)&sh[(rb + gid + 8) * SHP + k0 + 2 * tig];
            float2 f2 = *(const float2*)&sh[(rb + gid)     * SHP + k0 + 8 + 2 * tig];
            float2 f3 = *(const float2*)&sh[(rb + gid + 8) * SHP + k0 + 8 + 2 * tig];
            u32 ah0, al0, ah1, al1, ah2, al2, ah3, al3;
            split_a(f0, ah0, al0); split_a(f1, ah1, al1);
            split_a(f2, ah2, al2); split_a(f3, ah3, al3);
            #pragma unroll
            for (int t = 0; t < 6; ++t) {
                mma_bf16(acc[r][t][0], acc[r][t][1], acc[r][t][2], acc[r][t][3],
                         ah0, ah1, ah2, ah3, bh[t][0], bh[t][1]);
                mma_bf16(acc[r][t][0], acc[r][t][1], acc[r][t][2], acc[r][t][3],
                         al0, al1, al2, al3, bh[t][0], bh[t][1]);
                mma_bf16(acc[r][t][0], acc[r][t][1], acc[r][t][2], acc[r][t][3],
                         ah0, ah1, ah2, ah3, bl[t][0], bl[t][1]);
            }
        }
    }

    #pragma unroll
    for (int r = 0; r < 4; ++r) {
        int row0 = r * 16 + gid;
        int row1 = row0 + 8;
        float c0v = scut[row0];
        float c1v = scut[row1];
        size_t p0 = (size_t)spos[row0] * H3;
        size_t p1 = (size_t)spos[row1] * H3;
        #pragma unroll
        for (int t = 0; t < 6; ++t) {
            int col = nbase + t * 8 + 2 * tig;
            float b0v = bf2[col];
            float b1v = bf2[col + 1];
            __half2 v0 = __floats2half2_rn((acc[r][t][0] + b0v) * c0v,
                                           (acc[r][t][1] + b1v) * c0v);
            __half2 v1 = __floats2half2_rn((acc[r][t][2] + b0v) * c1v,
                                           (acc[r][t][3] + b1v) * c1v);
            *(__half2*)&g_filters[p0 + col] = v0;
            *(__half2*)&g_filters[p1 + col] = v1;
        }
    }
}

// ---------------- pull aggregation: fully streaming filters/uv/src ----------------
__global__ __launch_bounds__(128) void k_aggregate(
    const float* __restrict__ q, const float* __restrict__ mu)
{
    int n = blockIdx.x;
    int h = threadIdx.x;
    int beg = g_off[n], end = g_off[n + 1];
    float qa = 0.f, m0 = 0.f, m1 = 0.f, m2 = 0.f;
    for (int i = beg; i < end; ++i) {
        int s = g_src[i];
        const __half* f = &g_filters[(size_t)i * H3];
        float fq = __half2float(f[h]);
        float fr = __half2float(f[HH + h]);
        float fm = __half2float(f[2 * HH + h]);
        const float* xs = &g_x[s * H3];
        float xq = xs[h] * fq;
        float xr = xs[HH + h] * fr;
        float xm = xs[2 * HH + h] * fm;
        float4 u = g_uv4[i];
        const float* ms = &mu[s * 3 * HH];
        qa += xq;
        m0 = fmaf(u.x, xr, fmaf(ms[h],          xm, m0));
        m1 = fmaf(u.y, xr, fmaf(ms[HH + h],     xm, m1));
        m2 = fmaf(u.z, xr, fmaf(ms[2 * HH + h], xm, m2));
    }
    g_qmid[n * HH + h] = q[n * HH + h] + qa;
    g_mumid[n * 3 * HH + h]          = mu[n * 3 * HH + h] + m0;
    g_mumid[n * 3 * HH + HH + h]     = mu[n * 3 * HH + HH + h] + m1;
    g_mumid[n * 3 * HH + 2 * HH + h] = mu[n * 3 * HH + 2 * HH + h] + m2;
}

// ---------------- equivariant linear via bf16 split mma (R7 proven) ----------------
#define EMP 132
#define EOP 260
#define EQ_SMEM ((48 * EMP + 48 * EOP) * 4)
__global__ __launch_bounds__(256) void k_equiv()
{
    extern __shared__ float sme[];
    float* smu  = sme;
    float* sout = sme + 48 * EMP;
    int tid = threadIdx.x;
    int n0 = blockIdx.x * 16;
    int row_base = n0 * 3;

    for (int i = tid; i < 48 * HH; i += 256) {
        int r = i >> 7, c = i & 127;
        int grow = row_base + r;
        smu[r * EMP + c] = (grow < NN * 3) ? g_mumid[grow * HH + c] : 0.f;
    }
    __syncthreads();

    int wid  = tid >> 5;
    int lane = tid & 31;
    int gid  = lane >> 2;
    int tig  = lane & 3;
    int nbase = wid * 32;

    float acc[3][4][4];
    #pragma unroll
    for (int r = 0; r < 3; ++r)
        #pragma unroll
        for (int t = 0; t < 4; ++t)
            #pragma unroll
            for (int c = 0; c < 4; ++c) acc[r][t][c] = 0.f;

    #pragma unroll 1
    for (int k0 = 0; k0 < HH; k0 += 16) {
        int kp = k0 >> 1;
        u32 bh[4][2], bl[4][2];
        #pragma unroll
        for (int t = 0; t < 4; ++t) {
            int col = nbase + t * 8 + gid;
            int i0 = (kp + tig) * H2 + col;
            int i1 = (kp + 4 + tig) * H2 + col;
            bh[t][0] = __ldg(&g_vch[i0]);
            bh[t][1] = __ldg(&g_vch[i1]);
            bl[t][0] = __ldg(&g_vcl[i0]);
            bl[t][1] = __ldg(&g_vcl[i1]);
        }
        #pragma unroll
        for (int r = 0; r < 3; ++r) {
            int rb = r * 16;
            float2 f0 = *(const float2*)&smu[(rb + gid)     * EMP + k0 + 2 * tig];
            float2 f1 = *(const float2*)&smu[(rb + gid + 8) * EMP + k0 + 2 * tig];
            float2 f2 = *(const float2*)&smu[(rb + gid)     * EMP + k0 + 8 + 2 * tig];
            float2 f3 = *(const float2*)&smu[(rb + gid + 8) * EMP + k0 + 8 + 2 * tig];
            u32 ah0, al0, ah1, al1, ah2, al2, ah3, al3;
            split_a(f0, ah0, al0); split_a(f1, ah1, al1);
            split_a(f2, ah2, al2); split_a(f3, ah3, al3);
            #pragma unroll
            for (int t = 0; t < 4; ++t) {
                mma_bf16(acc[r][t][0], acc[r][t][1], acc[r][t][2], acc[r][t][3],
                         ah0, ah1, ah2, ah3, bh[t][0], bh[t][1]);
                mma_bf16(acc[r][t][0], acc[r][t][1], acc[r][t][2], acc[r][t][3],
                         al0, al1, al2, al3, bh[t][0], bh[t][1]);
                mma_bf16(acc[r][t][0], acc[r][t][1], acc[r][t][2], acc[r][t][3],
                         ah0, ah1, ah2, ah3, bl[t][0], bl[t][1]);
            }
        }
    }

    #pragma unroll
    for (int r = 0; r < 3; ++r) {
        int row0 = r * 16 + gid;
        int row1 = row0 + 8;
        #pragma unroll
        for (int t = 0; t < 4; ++t) {
            int col = nbase + t * 8 + 2 * tig;
            sout[row0 * EOP + col]     = acc[r][t][0];
            sout[row0 * EOP + col + 1] = acc[r][t][1];
            sout[row1 * EOP + col]     = acc[r][t][2];
            sout[row1 * EOP + col + 1] = acc[r][t][3];
        }
    }
    __syncthreads();

    for (int slot = tid; slot < 16 * HH; slot += 256) {
        int r = slot >> 7;
        int o = slot & 127;
        int n = n0 + r;
        if (n >= NN) break;
        float v0 = sout[(r * 3 + 0) * EOP + o];
        float v1 = sout[(r * 3 + 1) * EOP + o];
        float v2 = sout[(r * 3 + 2) * EOP + o];
        float w0 = sout[(r * 3 + 0) * EOP + HH + o];
        float w1 = sout[(r * 3 + 1) * EOP + HH + o];
        float w2 = sout[(r * 3 + 2) * EOP + HH + o];
        g_vnorm[n * HH + o] = sqrtf(v0 * v0 + v1 * v1 + v2 * v2 + 1e-8f);
        g_inner[n * HH + o] = v0 * w0 + v1 * w1 + v2 * w2;
        g_muw[n * 3 * HH + o]          = w0;
        g_muw[n * 3 * HH + HH + o]     = w1;
        g_muw[n * 3 * HH + 2 * HH + o] = w2;
    }
}

// ---------------- scalar mix MLP via bf16 split mma + final update (R7 proven) ----------------
#define MXP 388
#define MIX_SMEM ((32 * MXP * 2) * 4)
__global__ __launch_bounds__(256) void k_mix(
    const float* __restrict__ bm1, const float* __restrict__ bm2,
    float* __restrict__ qout, float* __restrict__ muout)
{
    extern __shared__ float smx[];
    float* sA = smx;
    float* sB = smx + 32 * MXP;
    int tid = threadIdx.x;
    int n0 = blockIdx.x * 32;

    for (int i = tid; i < 32 * H2; i += 256) {
        int r = i >> 8, c = i & 255;
        int n = n0 + r;
        float v = 0.f;
        if (n < NN) v = (c < HH) ? g_qmid[n * HH + c] : g_vnorm[n * HH + (c - HH)];
        sA[r * MXP + c] = v;
    }
    __syncthreads();

    int wid  = tid >> 5;
    int lane = tid & 31;
    int gid  = lane >> 2;
    int tig  = lane & 3;
    int nbase = wid * 48;

    {
        float acc[2][6][4];
        #pragma unroll
        for (int r = 0; r < 2; ++r)
            #pragma unroll
            for (int t = 0; t < 6; ++t)
                #pragma unroll
                for (int c = 0; c < 4; ++c) acc[r][t][c] = 0.f;

        #pragma unroll 1
        for (int k0 = 0; k0 < H2; k0 += 16) {
            int kp = k0 >> 1;
            u32 bh[6][2], bl[6][2];
            #pragma unroll
            for (int t = 0; t < 6; ++t) {
                int col = nbase + t * 8 + gid;
                int i0 = (kp + tig) * H3 + col;
                int i1 = (kp + 4 + tig) * H3 + col;
                bh[t][0] = __ldg(&g_m1h[i0]);
                bh[t][1] = __ldg(&g_m1h[i1]);
                bl[t][0] = __ldg(&g_m1l[i0]);
                bl[t][1] = __ldg(&g_m1l[i1]);
            }
            #pragma unroll
            for (int r = 0; r < 2; ++r) {
                int rb = r * 16;
                float2 f0 = *(const float2*)&sA[(rb + gid)     * MXP + k0 + 2 * tig];
                float2 f1 = *(const float2*)&sA[(rb + gid + 8) * MXP + k0 + 2 * tig];
                float2 f2 = *(const float2*)&sA[(rb + gid)     * MXP + k0 + 8 + 2 * tig];
                float2 f3 = *(const float2*)&sA[(rb + gid + 8) * MXP + k0 + 8 + 2 * tig];
                u32 ah0, al0, ah1, al1, ah2, al2, ah3, al3;
                split_a(f0, ah0, al0); split_a(f1, ah1, al1);
                split_a(f2, ah2, al2); split_a(f3, ah3, al3);
                #pragma unroll
                for (int t = 0; t < 6; ++t) {
                    mma_bf16(acc[r][t][0], acc[r][t][1], acc[r][t][2], acc[r][t][3],
                             ah0, ah1, ah2, ah3, bh[t][0], bh[t][1]);
                    mma_bf16(acc[r][t][0], acc[r][t][1], acc[r][t][2], acc[r][t][3],
                             al0, al1, al2, al3, bh[t][0], bh[t][1]);
                    mma_bf16(acc[r][t][0], acc[r][t][1], acc[r][t][2], acc[r][t][3],
                             ah0, ah1, ah2, ah3, bl[t][0], bl[t][1]);
                }
            }
        }
        #pragma unroll
        for (int r = 0; r < 2; ++r) {
            int row0 = r * 16 + gid;
            int row1 = row0 + 8;
            #pragma unroll
            for (int t = 0; t < 6; ++t) {
                int col = nbase + t * 8 + 2 * tig;
                float b0v = __ldg(&bm1[col]);
                float b1v = __ldg(&bm1[col + 1]);
                sB[row0 * MXP + col]     = silu_f(acc[r][t][0] + b0v);
                sB[row0 * MXP + col + 1] = silu_f(acc[r][t][1] + b1v);
                sB[row1 * MXP + col]     = silu_f(acc[r][t][2] + b0v);
                sB[row1 * MXP + col + 1] = silu_f(acc[r][t][3] + b1v);
            }
        }
    }
    __syncthreads();

    {
        float acc[2][6][4];
        #pragma unroll
        for (int r = 0; r < 2; ++r)
            #pragma unroll
            for (int t = 0; t < 6; ++t)
                #pragma unroll
                for (int c = 0; c < 4; ++c) acc[r][t][c] = 0.f;

        #pragma unroll 1
        for (int k0 = 0; k0 < H3; k0 += 16) {
            int kp = k0 >> 1;
            u32 bh[6][2], bl[6][2];
            #pragma unroll
            for (int t = 0; t < 6; ++t) {
                int col = nbase + t * 8 + gid;
                int i0 = (kp + tig) * H3 + col;
                int i1 = (kp + 4 + tig) * H3 + col;
                bh[t][0] = __ldg(&g_m2h[i0]);
                bh[t][1] = __ldg(&g_m2h[i1]);
                bl[t][0] = __ldg(&g_m2l[i0]);
                bl[t][1] = __ldg(&g_m2l[i1]);
            }
            #pragma unroll
            for (int r = 0; r < 2; ++r) {
                int rb = r * 16;
                float2 f0 = *(const float2*)&sB[(rb + gid)     * MXP + k0 + 2 * tig];
                float2 f1 = *(const float2*)&sB[(rb + gid + 8) * MXP + k0 + 2 * tig];
                float2 f2 = *(const float2*)&sB[(rb + gid)     * MXP + k0 + 8 + 2 * tig];
                float2 f3 = *(const float2*)&sB[(rb + gid + 8) * MXP + k0 + 8 + 2 * tig];
                u32 ah0, al0, ah1, al1, ah2, al2, ah3, al3;
                split_a(f0, ah0, al0); split_a(f1, ah1, al1);
                split_a(f2, ah2, al2); split_a(f3, ah3, al3);
                #pragma unroll
                for (int t = 0; t < 6; ++t) {
                    mma_bf16(acc[r][t][0], acc[r][t][1], acc[r][t][2], acc[r][t][3],
                             ah0, ah1, ah2, ah3, bh[t][0], bh[t][1]);
                    mma_bf16(acc[r][t][0], acc[r][t][1], acc[r][t][2], acc[r][t][3],
                             al0, al1, al2, al3, bh[t][0], bh[t][1]);
                    mma_bf16(acc[r][t][0], acc[r][t][1], acc[r][t][2], acc[r][t][3],
                             ah0, ah1, ah2, ah3, bl[t][0], bl[t][1]);
                }
            }
        }
        __syncthreads();
        #pragma unroll
        for (int r = 0; r < 2; ++r) {
            int row0 = r * 16 + gid;
            int row1 = row0 + 8;
            #pragma unroll
            for (int t = 0; t < 6; ++t) {
                int col = nbase + t * 8 + 2 * tig;
                float b0v = __ldg(&bm2[col]);
                float b1v = __ldg(&bm2[col + 1]);
                sA[row0 * MXP + col]     = acc[r][t][0] + b0v;
                sA[row0 * MXP + col + 1] = acc[r][t][1] + b1v;
                sA[row1 * MXP + col]     = acc[r][t][2] + b0v;
                sA[row1 * MXP + col + 1] = acc[r][t][3] + b1v;
            }
        }
    }
    __syncthreads();

    for (int slot = tid; slot < 32 * HH; slot += 256) {
        int r = slot >> 7;
        int o = slot & 127;
        int n = n0 + r;
        if (n >= NN) break;
        float dq  = sA[r * MXP + o];
        float dms = sA[r * MXP + HH + o];
        float dqm = sA[r * MXP + 2 * HH + o];
        qout[n * HH + o] = g_qmid[n * HH + o] + dq + dqm * g_inner[n * HH + o];
        #pragma unroll
        for (int d = 0; d < 3; ++d) {
            int idx = n * 3 * HH + d * HH + o;
            muout[idx] = g_mumid[idx] + g_muw[idx] * dms;
        }
    }
}

// ---------------- launch ----------------
extern "C" void kernel_launch(void* const* d_in, const int* in_sizes, int n_in,
                              void* d_out, int out_size)
{
    const float* q   = (const float*)d_in[0];
    const float* mu  = (const float*)d_in[1];
    const int*   ei  = (const int*)d_in[2];
    const float* rbf = (const float*)d_in[3];
    const float* uv  = (const float*)d_in[4];
    const float* cut = (const float*)d_in[5];
    const float* Wi1 = (const float*)d_in[6];
    const float* bi1 = (const float*)d_in[7];
    const float* Wi2 = (const float*)d_in[8];
    const float* bi2 = (const float*)d_in[9];
    const float* Wf1 = (const float*)d_in[10];
    const float* bf1 = (const float*)d_in[11];
    const float* Wf2 = (const float*)d_in[12];
    const float* bf2 = (const float*)d_in[13];
    const float* Wv  = (const float*)d_in[14];
    const float* Wm1 = (const float*)d_in[15];
    const float* bm1 = (const float*)d_in[16];
    const float* Wm2 = (const float*)d_in[17];
    const float* bm2 = (const float*)d_in[18];

    float* qout  = (float*)d_out;
    float* muout = qout + (size_t)NN * HH;

    cudaFuncSetAttribute(k_node_mlp, cudaFuncAttributeMaxDynamicSharedMemorySize, NODE_SMEM);
    cudaFuncSetAttribute(k_equiv,    cudaFuncAttributeMaxDynamicSharedMemorySize, EQ_SMEM);
    cudaFuncSetAttribute(k_mix,      cudaFuncAttributeMaxDynamicSharedMemorySize, MIX_SMEM);

    // CSR build + weight splits
    k_zero<<<(NN + 255) / 256, 256>>>();
    k_count<<<512, 256>>>(ei);
    {
        u32 *p0, *p1;
        cudaGetSymbolAddress((void**)&p0, g_bhp); cudaGetSymbolAddress((void**)&p1, g_blp);
        k_splitw<<<((HH / 2) * H3 + 255) / 256, 256>>>(Wf2, p0, p1, HH / 2, H3);
        cudaGetSymbolAddress((void**)&p0, g_i1h); cudaGetSymbolAddress((void**)&p1, g_i1l);
        k_splitw<<<((HH / 2) * H3 + 255) / 256, 256>>>(Wi1, p0, p1, HH / 2, H3);
        cudaGetSymbolAddress((void**)&p0, g_i2h); cudaGetSymbolAddress((void**)&p1, g_i2l);
        k_splitw<<<((H3 / 2) * H3 + 255) / 256, 256>>>(Wi2, p0, p1, H3 / 2, H3);
        cudaGetSymbolAddress((void**)&p0, g_vch); cudaGetSymbolAddress((void**)&p1, g_vcl);
        k_splitw<<<((HH / 2) * H2 + 255) / 256, 256>>>(Wv, p0, p1, HH / 2, H2);
        cudaGetSymbolAddress((void**)&p0, g_m1h); cudaGetSymbolAddress((void**)&p1, g_m1l);
        k_splitw<<<((H2 / 2) * H3 + 255) / 256, 256>>>(Wm1, p0, p1, H2 / 2, H3);
        cudaGetSymbolAddress((void**)&p0, g_m2h); cudaGetSymbolAddress((void**)&p1, g_m2l);
        k_splitw<<<((H3 / 2) * H3 + 255) / 256, 256>>>(Wm2, p0, p1, H3 / 2, H3);
    }
    k_scan<<<1, 1024>>>();
    k_fill<<<512, 256>>>(ei, uv);

    // dense stages
    k_node_mlp<<<(NN + 31) / 32, 256, NODE_SMEM>>>(q, bi1, bi2);
    k_edge_filter<<<NE / 64, 256>>>(rbf, cut, Wf1, bf1, bf2);

    // message aggregation
    k_aggregate<<<NN, 128>>>(q, mu);

    // mixing
    k_equiv<<<(NN + 15) / 16, 256, EQ_SMEM>>>();
    k_mix<<<(NN + 31) / 32, 256, MIX_SMEM>>>(bm1, bm2, qout, muout);
}

// round 11
// speedup vs baseline: 1.0467x; 1.0137x over previous
#include <cuda_runtime.h>
#include <cuda_bf16.h>
#include <cuda_fp16.h>
#include <math.h>

#define NN 10000
#define NE 256000
#define HH 128
#define H2 256
#define H3 384
#define NR 20

typedef unsigned int u32;

// ---------------- scratch (static device globals; no allocation) ----------------
__device__ float  g_x[NN * H3];                    // node MLP out (fp32, L2-resident)
__device__ __half g_filters[(size_t)NE * H3];      // fp16 filters in CSR order (196 MB)
__device__ float4 g_uv4[NE];                       // unit vectors in CSR order
__device__ int    g_src[NE];                       // source node in CSR order
__device__ int    g_epos[NE];                      // edge -> CSR position
__device__ u32   g_bhp[(HH / 2) * H3];
__device__ u32   g_blp[(HH / 2) * H3];
__device__ u32   g_i1h[(HH / 2) * H3];
__device__ u32   g_i1l[(HH / 2) * H3];
__device__ u32   g_i2h[(H3 / 2) * H3];
__device__ u32   g_i2l[(H3 / 2) * H3];
__device__ u32   g_vch[(HH / 2) * H2];
__device__ u32   g_vcl[(HH / 2) * H2];
__device__ u32   g_m1h[(H2 / 2) * H3];
__device__ u32   g_m1l[(H2 / 2) * H3];
__device__ u32   g_m2h[(H3 / 2) * H3];
__device__ u32   g_m2l[(H3 / 2) * H3];
__device__ float g_qmid[NN * HH];
__device__ float g_mumid[NN * 3 * HH];
__device__ float g_vnorm[NN * HH];
__device__ float g_inner[NN * HH];
__device__ float g_muw[NN * 3 * HH];
__device__ int   g_count[NN];
__device__ int   g_off[NN + 1];
__device__ int   g_cursor[NN];

__device__ __forceinline__ float silu_f(float x) {
    return x / (1.0f + __expf(-x));
}

__device__ __forceinline__ u32 pack_bf16x2(float lo, float hi) {
    u32 r;
    asm("cvt.rn.bf16x2.f32 %0, %1, %2;" : "=r"(r) : "f"(hi), "f"(lo));
    return r;
}

__device__ __forceinline__ void mma_bf16(float& c0, float& c1, float& c2, float& c3,
                                         u32 a0, u32 a1, u32 a2, u32 a3,
                                         u32 b0, u32 b1) {
    asm("mma.sync.aligned.m16n8k16.row.col.f32.bf16.bf16.f32 "
        "{%0,%1,%2,%3}, {%4,%5,%6,%7}, {%8,%9}, {%0,%1,%2,%3};"
        : "+f"(c0), "+f"(c1), "+f"(c2), "+f"(c3)
        : "r"(a0), "r"(a1), "r"(a2), "r"(a3), "r"(b0), "r"(b1));
}

__device__ __forceinline__ void split_a(float2 f, u32& hi, u32& lo) {
    hi = pack_bf16x2(f.x, f.y);
    lo = pack_bf16x2(f.x - __uint_as_float(hi << 16),
                     f.y - __uint_as_float(hi & 0xFFFF0000u));
}

__device__ __forceinline__ void split_pair(float v0, float v1, u32& hi, u32& lo) {
    hi = pack_bf16x2(v0, v1);
    lo = pack_bf16x2(v0 - __uint_as_float(hi << 16),
                     v1 - __uint_as_float(hi & 0xFFFF0000u));
}

// ---------------- merged prologue: 6 weight splits + count zeroing ----------------
__device__ __forceinline__ void do_split(const float* __restrict__ W,
                                         u32* __restrict__ hi, u32* __restrict__ lo,
                                         int idx, int width) {
    int p = idx / width, col = idx % width;
    float w0 = W[(2 * p) * width + col];
    float w1 = W[(2 * p + 1) * width + col];
    u32 h01 = pack_bf16x2(w0, w1);
    float h0 = __uint_as_float(h01 << 16);
    float h1 = __uint_as_float(h01 & 0xFFFF0000u);
    hi[idx] = h01;
    lo[idx] = pack_bf16x2(w0 - h0, w1 - h1);
}

#define SEG0 24576          // Wf2   (64 x 384)
#define SEG1 49152          // Wi1   (64 x 384)
#define SEG2 122880         // Wi2   (192 x 384)
#define SEG3 139264         // Wv    (64 x 256)
#define SEG4 188416         // Wm1   (128 x 384)
#define SEG5 262144         // Wm2   (192 x 384)
#define SEG6 272144         // count zero (10000)
__global__ void k_prep(const float* __restrict__ Wf2, const float* __restrict__ Wi1,
                       const float* __restrict__ Wi2, const float* __restrict__ Wv,
                       const float* __restrict__ Wm1, const float* __restrict__ Wm2) {
    int i = blockIdx.x * blockDim.x + threadIdx.x;
    if (i < SEG0)       do_split(Wf2, g_bhp, g_blp, i, H3);
    else if (i < SEG1)  do_split(Wi1, g_i1h, g_i1l, i - SEG0, H3);
    else if (i < SEG2)  do_split(Wi2, g_i2h, g_i2l, i - SEG1, H3);
    else if (i < SEG3)  do_split(Wv,  g_vch, g_vcl, i - SEG2, H2);
    else if (i < SEG4)  do_split(Wm1, g_m1h, g_m1l, i - SEG3, H3);
    else if (i < SEG5)  do_split(Wm2, g_m2h, g_m2l, i - SEG4, H3);
    else if (i < SEG6)  g_count[i - SEG5] = 0;
}

// ---------------- CSR build ----------------
__global__ void k_count(const int* __restrict__ ei) {
    for (int e = blockIdx.x * blockDim.x + threadIdx.x; e < NE;
         e += gridDim.x * blockDim.x)
        atomicAdd(&g_count[ei[e]], 1);
}

__global__ __launch_bounds__(1024) void k_scan() {
    __shared__ int ps[1024];
    int tid = threadIdx.x;
    const int CH = (NN + 1023) / 1024;
    int base = tid * CH;
    int s = 0;
    for (int j = 0; j < CH; ++j) {
        int idx = base + j;
        if (idx < NN) s += g_count[idx];
    }
    ps[tid] = s;
    __syncthreads();
    for (int off = 1; off < 1024; off <<= 1) {
        int v = 0;
        if (tid >= off) v = ps[tid - off];
        __syncthreads();
        ps[tid] += v;
        __syncthreads();
    }
    int run = ps[tid] - s;
    for (int j = 0; j < CH; ++j) {
        int idx = base + j;
        if (idx < NN) {
            g_off[idx] = run;
            g_cursor[idx] = run;
            run += g_count[idx];
        }
    }
    if (tid == 1023) g_off[NN] = ps[1023];
}

__global__ void k_fill(const int* __restrict__ ei, const float* __restrict__ uv) {
    for (int e = blockIdx.x * blockDim.x + threadIdx.x; e < NE;
         e += gridDim.x * blockDim.x) {
        int t = ei[e];
        int pos = atomicAdd(&g_cursor[t], 1);
        g_epos[e] = pos;
        g_src[pos] = ei[NE + e];
        g_uv4[pos] = make_float4(uv[3 * e], uv[3 * e + 1], uv[3 * e + 2], 0.f);
    }
}

// ---------------- node inter MLP via bf16 split mma ----------------
#define SQP 132
#define SH2P 388
#define NODE_SMEM ((32 * SQP + 32 * SH2P) * 4)
__global__ __launch_bounds__(256) void k_node_mlp(
    const float* __restrict__ q,
    const float* __restrict__ b1, const float* __restrict__ b2)
{
    extern __shared__ float smn[];
    float* sq = smn;
    float* sh = smn + 32 * SQP;
    int tid = threadIdx.x;
    int n0 = blockIdx.x * 32;

    for (int i = tid; i < 32 * HH; i += 256) {
        int r = i >> 7, c = i & 127;
        int n = n0 + r;
        sq[r * SQP + c] = (n < NN) ? q[n * HH + c] : 0.f;
    }
    __syncthreads();

    int wid  = tid >> 5;
    int lane = tid & 31;
    int gid  = lane >> 2;
    int tig  = lane & 3;
    int nbase = wid * 48;

    {
        float acc[2][6][4];
        #pragma unroll
        for (int r = 0; r < 2; ++r)
            #pragma unroll
            for (int t = 0; t < 6; ++t)
                #pragma unroll
                for (int c = 0; c < 4; ++c) acc[r][t][c] = 0.f;

        #pragma unroll 1
        for (int k0 = 0; k0 < HH; k0 += 16) {
            int kp = k0 >> 1;
            u32 bh[6][2], bl[6][2];
            #pragma unroll
            for (int t = 0; t < 6; ++t) {
                int col = nbase + t * 8 + gid;
                int i0 = (kp + tig) * H3 + col;
                int i1 = (kp + 4 + tig) * H3 + col;
                bh[t][0] = __ldg(&g_i1h[i0]);
                bh[t][1] = __ldg(&g_i1h[i1]);
                bl[t][0] = __ldg(&g_i1l[i0]);
                bl[t][1] = __ldg(&g_i1l[i1]);
            }
            #pragma unroll
            for (int r = 0; r < 2; ++r) {
                int rb = r * 16;
                float2 f0 = *(const float2*)&sq[(rb + gid)     * SQP + k0 + 2 * tig];
                float2 f1 = *(const float2*)&sq[(rb + gid + 8) * SQP + k0 + 2 * tig];
                float2 f2 = *(const float2*)&sq[(rb + gid)     * SQP + k0 + 8 + 2 * tig];
                float2 f3 = *(const float2*)&sq[(rb + gid + 8) * SQP + k0 + 8 + 2 * tig];
                u32 ah0, al0, ah1, al1, ah2, al2, ah3, al3;
                split_a(f0, ah0, al0); split_a(f1, ah1, al1);
                split_a(f2, ah2, al2); split_a(f3, ah3, al3);
                #pragma unroll
                for (int t = 0; t < 6; ++t) {
                    mma_bf16(acc[r][t][0], acc[r][t][1], acc[r][t][2], acc[r][t][3],
                             ah0, ah1, ah2, ah3, bh[t][0], bh[t][1]);
                    mma_bf16(acc[r][t][0], acc[r][t][1], acc[r][t][2], acc[r][t][3],
                             al0, al1, al2, al3, bh[t][0], bh[t][1]);
                    mma_bf16(acc[r][t][0], acc[r][t][1], acc[r][t][2], acc[r][t][3],
                             ah0, ah1, ah2, ah3, bl[t][0], bl[t][1]);
                }
            }
        }
        #pragma unroll
        for (int r = 0; r < 2; ++r) {
            int row0 = r * 16 + gid;
            int row1 = row0 + 8;
            #pragma unroll
            for (int t = 0; t < 6; ++t) {
                int col = nbase + t * 8 + 2 * tig;
                float b0v = __ldg(&b1[col]);
                float b1v = __ldg(&b1[col + 1]);
                sh[row0 * SH2P + col]     = silu_f(acc[r][t][0] + b0v);
                sh[row0 * SH2P + col + 1] = silu_f(acc[r][t][1] + b1v);
                sh[row1 * SH2P + col]     = silu_f(acc[r][t][2] + b0v);
                sh[row1 * SH2P + col + 1] = silu_f(acc[r][t][3] + b1v);
            }
        }
    }
    __syncthreads();

    {
        float acc[2][6][4];
        #pragma unroll
        for (int r = 0; r < 2; ++r)
            #pragma unroll
            for (int t = 0; t < 6; ++t)
                #pragma unroll
                for (int c = 0; c < 4; ++c) acc[r][t][c] = 0.f;

        #pragma unroll 1
        for (int k0 = 0; k0 < H3; k0 += 16) {
            int kp = k0 >> 1;
            u32 bh[6][2], bl[6][2];
            #pragma unroll
            for (int t = 0; t < 6; ++t) {
                int col = nbase + t * 8 + gid;
                int i0 = (kp + tig) * H3 + col;
                int i1 = (kp + 4 + tig) * H3 + col;
                bh[t][0] = __ldg(&g_i2h[i0]);
                bh[t][1] = __ldg(&g_i2h[i1]);
                bl[t][0] = __ldg(&g_i2l[i0]);
                bl[t][1] = __ldg(&g_i2l[i1]);
            }
            #pragma unroll
            for (int r = 0; r < 2; ++r) {
                int rb = r * 16;
                float2 f0 = *(const float2*)&sh[(rb + gid)     * SH2P + k0 + 2 * tig];
                float2 f1 = *(const float2*)&sh[(rb + gid + 8) * SH2P + k0 + 2 * tig];
                float2 f2 = *(const float2*)&sh[(rb + gid)     * SH2P + k0 + 8 + 2 * tig];
                float2 f3 = *(const float2*)&sh[(rb + gid + 8) * SH2P + k0 + 8 + 2 * tig];
                u32 ah0, al0, ah1, al1, ah2, al2, ah3, al3;
                split_a(f0, ah0, al0); split_a(f1, ah1, al1);
                split_a(f2, ah2, al2); split_a(f3, ah3, al3);
                #pragma unroll
                for (int t = 0; t < 6; ++t) {
                    mma_bf16(acc[r][t][0], acc[r][t][1], acc[r][t][2], acc[r][t][3],
                             ah0, ah1, ah2, ah3, bh[t][0], bh[t][1]);
                    mma_bf16(acc[r][t][0], acc[r][t][1], acc[r][t][2], acc[r][t][3],
                             al0, al1, al2, al3, bh[t][0], bh[t][1]);
                    mma_bf16(acc[r][t][0], acc[r][t][1], acc[r][t][2], acc[r][t][3],
                             ah0, ah1, ah2, ah3, bl[t][0], bl[t][1]);
                }
            }
        }
        #pragma unroll
        for (int r = 0; r < 2; ++r) {
            int row0 = r * 16 + gid;
            int row1 = row0 + 8;
            #pragma unroll
            for (int t = 0; t < 6; ++t) {
                int col = nbase + t * 8 + 2 * tig;
                float b0v = __ldg(&b2[col]);
                float b1v = __ldg(&b2[col + 1]);
                if (n0 + row0 < NN)
                    *(float2*)&g_x[(size_t)(n0 + row0) * H3 + col] =
                        make_float2(acc[r][t][0] + b0v, acc[r][t][1] + b1v);
                if (n0 + row1 < NN)
                    *(float2*)&g_x[(size_t)(n0 + row1) * H3 + col] =
                        make_float2(acc[r][t][2] + b0v, acc[r][t][3] + b1v);
            }
        }
    }
}

// ---------------- edge filter MLP: phase1 scalar + pre-split, phase2 bf16 mma ----------------
// hidden stored PRE-SPLIT as packed bf16x2 k-pairs, layout [row][kp], stride 68.
#define KPS 68
__global__ __launch_bounds__(256) void k_edge_filter(
    const float* __restrict__ rbf, const float* __restrict__ cut,
    const float* __restrict__ Wf1, const float* __restrict__ bf1,
    const float* __restrict__ bf2)
{
    __shared__ float srb[64][NR];
    __shared__ float scut[64];
    __shared__ int   spos[64];
    __shared__ u32 shiT[64 * KPS];
    __shared__ u32 sloT[64 * KPS];
    int tid = threadIdx.x;
    int e0 = blockIdx.x * 64;

    for (int i = tid; i < 64 * NR; i += 256)
        srb[i / NR][i % NR] = rbf[(e0 + i / NR) * NR + (i % NR)];
    if (tid < 64) {
        scut[tid] = cut[e0 + tid];
        spos[tid] = g_epos[e0 + tid];
    }
    __syncthreads();

    // phase 1 (scalar, K=20) + split epilogue
    {
        int rg = tid >> 4;
        int cg = tid & 15;
        int r0 = rg * 4;
        for (int pass = 0; pass < 2; ++pass) {
            int c0 = cg * 4 + pass * 64;
            float acc[4][4] = {};
            for (int k = 0; k < NR; ++k) {
                float4 w = *reinterpret_cast<const float4*>(&Wf1[k * HH + c0]);
                #pragma unroll
                for (int i = 0; i < 4; ++i) {
                    float s = srb[r0 + i][k];
                    acc[i][0] = fmaf(s, w.x, acc[i][0]);
                    acc[i][1] = fmaf(s, w.y, acc[i][1]);
                    acc[i][2] = fmaf(s, w.z, acc[i][2]);
                    acc[i][3] = fmaf(s, w.w, acc[i][3]);
                }
            }
            int kp0 = c0 >> 1;
            #pragma unroll
            for (int i = 0; i < 4; ++i) {
                float v0 = silu_f(acc[i][0] + bf1[c0]);
                float v1 = silu_f(acc[i][1] + bf1[c0 + 1]);
                float v2 = silu_f(acc[i][2] + bf1[c0 + 2]);
                float v3 = silu_f(acc[i][3] + bf1[c0 + 3]);
                u32 h0, l0, h1, l1;
                split_pair(v0, v1, h0, l0);
                split_pair(v2, v3, h1, l1);
                shiT[(r0 + i) * KPS + kp0]     = h0;
                sloT[(r0 + i) * KPS + kp0]     = l0;
                shiT[(r0 + i) * KPS + kp0 + 1] = h1;
                sloT[(r0 + i) * KPS + kp0 + 1] = l1;
            }
        }
    }
    __syncthreads();

    // phase 2: A fragments are direct LDS.32 (conflict-free)
    int wid  = tid >> 5;
    int lane = tid & 31;
    int gid  = lane >> 2;
    int tig  = lane & 3;
    int nbase = wid * 48;

    float acc[4][6][4];
    #pragma unroll
    for (int r = 0; r < 4; ++r)
        #pragma unroll
        for (int t = 0; t < 6; ++t)
            #pragma unroll
            for (int c = 0; c < 4; ++c) acc[r][t][c] = 0.f;

    #pragma unroll 1
    for (int k0 = 0; k0 < HH; k0 += 16) {
        int kp = k0 >> 1;
        u32 bh[6][2], bl[6][2];
        #pragma unroll
        for (int t = 0; t < 6; ++t) {
            int col = nbase + t * 8 + gid;
            int i0 = (kp + tig) * H3 + col;
            int i1 = (kp + 4 + tig) * H3 + col;
            bh[t][0] = __ldg(&g_bhp[i0]);
            bh[t][1] = __ldg(&g_bhp[i1]);
            bl[t][0] = __ldg(&g_blp[i0]);
            bl[t][1] = __ldg(&g_blp[i1]);
        }
        #pragma unroll
        for (int r = 0; r < 4; ++r) {
            int rb = r * 16;
            int ra = (rb + gid) * KPS;
            int rc = (rb + gid + 8) * KPS;
            u32 ah0 = shiT[ra + kp + tig];
            u32 ah1 = shiT[rc + kp + tig];
            u32 ah2 = shiT[ra + kp + 4 + tig];
            u32 ah3 = shiT[rc + kp + 4 + tig];
            u32 al0 = sloT[ra + kp + tig];
            u32 al1 = sloT[rc + kp + tig];
            u32 al2 = sloT[ra + kp + 4 + tig];
            u32 al3 = sloT[rc + kp + 4 + tig];
            #pragma unroll
            for (int t = 0; t < 6; ++t) {
                mma_bf16(acc[r][t][0], acc[r][t][1], acc[r][t][2], acc[r][t][3],
                         ah0, ah1, ah2, ah3, bh[t][0], bh[t][1]);
                mma_bf16(acc[r][t][0], acc[r][t][1], acc[r][t][2], acc[r][t][3],
                         al0, al1, al2, al3, bh[t][0], bh[t][1]);
                mma_bf16(acc[r][t][0], acc[r][t][1], acc[r][t][2], acc[r][t][3],
                         ah0, ah1, ah2, ah3, bl[t][0], bl[t][1]);
            }
        }
    }

    #pragma unroll
    for (int r = 0; r < 4; ++r) {
        int row0 = r * 16 + gid;
        int row1 = row0 + 8;
        float c0v = scut[row0];
        float c1v = scut[row1];
        size_t p0 = (size_t)spos[row0] * H3;
        size_t p1 = (size_t)spos[row1] * H3;
        #pragma unroll
        for (int t = 0; t < 6; ++t) {
            int col = nbase + t * 8 + 2 * tig;
            float b0v = bf2[col];
            float b1v = bf2[col + 1];
            __half2 v0 = __floats2half2_rn((acc[r][t][0] + b0v) * c0v,
                                           (acc[r][t][1] + b1v) * c0v);
            __half2 v1 = __floats2half2_rn((acc[r][t][2] + b0v) * c1v,
                                           (acc[r][t][3] + b1v) * c1v);
            *(__half2*)&g_filters[p0 + col] = v0;
            *(__half2*)&g_filters[p1 + col] = v1;
        }
    }
}

// ---------------- pull aggregation: streaming filters/uv/src ----------------
__global__ __launch_bounds__(128) void k_aggregate(
    const float* __restrict__ q, const float* __restrict__ mu)
{
    int n = blockIdx.x;
    int h = threadIdx.x;
    int beg = g_off[n], end = g_off[n + 1];
    float qa = 0.f, m0 = 0.f, m1 = 0.f, m2 = 0.f;
    for (int i = beg; i < end; ++i) {
        int s = g_src[i];
        const __half* f = &g_filters[(size_t)i * H3];
        float fq = __half2float(f[h]);
        float fr = __half2float(f[HH + h]);
        float fm = __half2float(f[2 * HH + h]);
        const float* xs = &g_x[s * H3];
        float xq = xs[h] * fq;
        float xr = xs[HH + h] * fr;
        float xm = xs[2 * HH + h] * fm;
        float4 u = g_uv4[i];
        const float* ms = &mu[s * 3 * HH];
        qa += xq;
        m0 = fmaf(u.x, xr, fmaf(ms[h],          xm, m0));
        m1 = fmaf(u.y, xr, fmaf(ms[HH + h],     xm, m1));
        m2 = fmaf(u.z, xr, fmaf(ms[2 * HH + h], xm, m2));
    }
    g_qmid[n * HH + h] = q[n * HH + h] + qa;
    g_mumid[n * 3 * HH + h]          = mu[n * 3 * HH + h] + m0;
    g_mumid[n * 3 * HH + HH + h]     = mu[n * 3 * HH + HH + h] + m1;
    g_mumid[n * 3 * HH + 2 * HH + h] = mu[n * 3 * HH + 2 * HH + h] + m2;
}

// ---------------- equivariant linear via bf16 split mma ----------------
#define EMP 132
#define EOP 260
#define EQ_SMEM ((48 * EMP + 48 * EOP) * 4)
__global__ __launch_bounds__(256) void k_equiv()
{
    extern __shared__ float sme[];
    float* smu  = sme;
    float* sout = sme + 48 * EMP;
    int tid = threadIdx.x;
    int n0 = blockIdx.x * 16;
    int row_base = n0 * 3;

    for (int i = tid; i < 48 * HH; i += 256) {
        int r = i >> 7, c = i & 127;
        int grow = row_base + r;
        smu[r * EMP + c] = (grow < NN * 3) ? g_mumid[grow * HH + c] : 0.f;
    }
    __syncthreads();

    int wid  = tid >> 5;
    int lane = tid & 31;
    int gid  = lane >> 2;
    int tig  = lane & 3;
    int nbase = wid * 32;

    float acc[3][4][4];
    #pragma unroll
    for (int r = 0; r < 3; ++r)
        #pragma unroll
        for (int t = 0; t < 4; ++t)
            #pragma unroll
            for (int c = 0; c < 4; ++c) acc[r][t][c] = 0.f;

    #pragma unroll 1
    for (int k0 = 0; k0 < HH; k0 += 16) {
        int kp = k0 >> 1;
        u32 bh[4][2], bl[4][2];
        #pragma unroll
        for (int t = 0; t < 4; ++t) {
            int col = nbase + t * 8 + gid;
            int i0 = (kp + tig) * H2 + col;
            int i1 = (kp + 4 + tig) * H2 + col;
            bh[t][0] = __ldg(&g_vch[i0]);
            bh[t][1] = __ldg(&g_vch[i1]);
            bl[t][0] = __ldg(&g_vcl[i0]);
            bl[t][1] = __ldg(&g_vcl[i1]);
        }
        #pragma unroll
        for (int r = 0; r < 3; ++r) {
            int rb = r * 16;
            float2 f0 = *(const float2*)&smu[(rb + gid)     * EMP + k0 + 2 * tig];
            float2 f1 = *(const float2*)&smu[(rb + gid + 8) * EMP + k0 + 2 * tig];
            float2 f2 = *(const float2*)&smu[(rb + gid)     * EMP + k0 + 8 + 2 * tig];
            float2 f3 = *(const float2*)&smu[(rb + gid + 8) * EMP + k0 + 8 + 2 * tig];
            u32 ah0, al0, ah1, al1, ah2, al2, ah3, al3;
            split_a(f0, ah0, al0); split_a(f1, ah1, al1);
            split_a(f2, ah2, al2); split_a(f3, ah3, al3);
            #pragma unroll
            for (int t = 0; t < 4; ++t) {
                mma_bf16(acc[r][t][0], acc[r][t][1], acc[r][t][2], acc[r][t][3],
                         ah0, ah1, ah2, ah3, bh[t][0], bh[t][1]);
                mma_bf16(acc[r][t][0], acc[r][t][1], acc[r][t][2], acc[r][t][3],
                         al0, al1, al2, al3, bh[t][0], bh[t][1]);
                mma_bf16(acc[r][t][0], acc[r][t][1], acc[r][t][2], acc[r][t][3],
                         ah0, ah1, ah2, ah3, bl[t][0], bl[t][1]);
            }
        }
    }

    #pragma unroll
    for (int r = 0; r < 3; ++r) {
        int row0 = r * 16 + gid;
        int row1 = row0 + 8;
        #pragma unroll
        for (int t = 0; t < 4; ++t) {
            int col = nbase + t * 8 + 2 * tig;
            sout[row0 * EOP + col]     = acc[r][t][0];
            sout[row0 * EOP + col + 1] = acc[r][t][1];
            sout[row1 * EOP + col]     = acc[r][t][2];
            sout[row1 * EOP + col + 1] = acc[r][t][3];
        }
    }
    __syncthreads();

    for (int slot = tid; slot < 16 * HH; slot += 256) {
        int r = slot >> 7;
        int o = slot & 127;
        int n = n0 + r;
        if (n >= NN) break;
        float v0 = sout[(r * 3 + 0) * EOP + o];
        float v1 = sout[(r * 3 + 1) * EOP + o];
        float v2 = sout[(r * 3 + 2) * EOP + o];
        float w0 = sout[(r * 3 + 0) * EOP + HH + o];
        float w1 = sout[(r * 3 + 1) * EOP + HH + o];
        float w2 = sout[(r * 3 + 2) * EOP + HH + o];
        g_vnorm[n * HH + o] = sqrtf(v0 * v0 + v1 * v1 + v2 * v2 + 1e-8f);
        g_inner[n * HH + o] = v0 * w0 + v1 * w1 + v2 * w2;
        g_muw[n * 3 * HH + o]          = w0;
        g_muw[n * 3 * HH + HH + o]     = w1;
        g_muw[n * 3 * HH + 2 * HH + o] = w2;
    }
}

// ---------------- scalar mix MLP via bf16 split mma + final update ----------------
#define MXP 388
#define MIX_SMEM ((32 * MXP * 2) * 4)
__global__ __launch_bounds__(256) void k_mix(
    const float* __restrict__ bm1, const float* __restrict__ bm2,
    float* __restrict__ qout, float* __restrict__ muout)
{
    extern __shared__ float smx[];
    float* sA = smx;
    float* sB = smx + 32 * MXP;
    int tid = threadIdx.x;
    int n0 = blockIdx.x * 32;

    for (int i = tid; i < 32 * H2; i += 256) {
        int r = i >> 8, c = i & 255;
        int n = n0 + r;
        float v = 0.f;
        if (n < NN) v = (c < HH) ? g_qmid[n * HH + c] : g_vnorm[n * HH + (c - HH)];
        sA[r * MXP + c] = v;
    }
    __syncthreads();

    int wid  = tid >> 5;
    int lane = tid & 31;
    int gid  = lane >> 2;
    int tig  = lane & 3;
    int nbase = wid * 48;

    {
        float acc[2][6][4];
        #pragma unroll
        for (int r = 0; r < 2; ++r)
            #pragma unroll
            for (int t = 0; t < 6; ++t)
                #pragma unroll
                for (int c = 0; c < 4; ++c) acc[r][t][c] = 0.f;

        #pragma unroll 1
        for (int k0 = 0; k0 < H2; k0 += 16) {
            int kp = k0 >> 1;
            u32 bh[6][2], bl[6][2];
            #pragma unroll
            for (int t = 0; t < 6; ++t) {
                int col = nbase + t * 8 + gid;
                int i0 = (kp + tig) * H3 + col;
                int i1 = (kp + 4 + tig) * H3 + col;
                bh[t][0] = __ldg(&g_m1h[i0]);
                bh[t][1] = __ldg(&g_m1h[i1]);
                bl[t][0] = __ldg(&g_m1l[i0]);
                bl[t][1] = __ldg(&g_m1l[i1]);
            }
            #pragma unroll
            for (int r = 0; r < 2; ++r) {
                int rb = r * 16;
                float2 f0 = *(const float2*)&sA[(rb + gid)     * MXP + k0 + 2 * tig];
                float2 f1 = *(const float2*)&sA[(rb + gid + 8) * MXP + k0 + 2 * tig];
                float2 f2 = *(const float2*)&sA[(rb + gid)     * MXP + k0 + 8 + 2 * tig];
                float2 f3 = *(const float2*)&sA[(rb + gid + 8) * MXP + k0 + 8 + 2 * tig];
                u32 ah0, al0, ah1, al1, ah2, al2, ah3, al3;
                split_a(f0, ah0, al0); split_a(f1, ah1, al1);
                split_a(f2, ah2, al2); split_a(f3, ah3, al3);
                #pragma unroll
                for (int t = 0; t < 6; ++t) {
                    mma_bf16(acc[r][t][0], acc[r][t][1], acc[r][t][2], acc[r][t][3],
                             ah0, ah1, ah2, ah3, bh[t][0], bh[t][1]);
                    mma_bf16(acc[r][t][0], acc[r][t][1], acc[r][t][2], acc[r][t][3],
                             al0, al1, al2, al3, bh[t][0], bh[t][1]);
                    mma_bf16(acc[r][t][0], acc[r][t][1], acc[r][t][2], acc[r][t][3],
                             ah0, ah1, ah2, ah3, bl[t][0], bl[t][1]);
                }
            }
        }
        #pragma unroll
        for (int r = 0; r < 2; ++r) {
            int row0 = r * 16 + gid;
            int row1 = row0 + 8;
            #pragma unroll
            for (int t = 0; t < 6; ++t) {
                int col = nbase + t * 8 + 2 * tig;
                float b0v = __ldg(&bm1[col]);
                float b1v = __ldg(&bm1[col + 1]);
                sB[row0 * MXP + col]     = silu_f(acc[r][t][0] + b0v);
                sB[row0 * MXP + col + 1] = silu_f(acc[r][t][1] + b1v);
                sB[row1 * MXP + col]     = silu_f(acc[r][t][2] + b0v);
                sB[row1 * MXP + col + 1] = silu_f(acc[r][t][3] + b1v);
            }
        }
    }
    __syncthreads();

    {
        float acc[2][6][4];
        #pragma unroll
        for (int r = 0; r < 2; ++r)
            #pragma unroll
            for (int t = 0; t < 6; ++t)
                #pragma unroll
                for (int c = 0; c < 4; ++c) acc[r][t][c] = 0.f;

        #pragma unroll 1
        for (int k0 = 0; k0 < H3; k0 += 16) {
            int kp = k0 >> 1;
            u32 bh[6][2], bl[6][2];
            #pragma unroll
            for (int t = 0; t < 6; ++t) {
                int col = nbase + t * 8 + gid;
                int i0 = (kp + tig) * H3 + col;
                int i1 = (kp + 4 + tig) * H3 + col;
                bh[t][0] = __ldg(&g_m2h[i0]);
                bh[t][1] = __ldg(&g_m2h[i1]);
                bl[t][0] = __ldg(&g_m2l[i0]);
                bl[t][1] = __ldg(&g_m2l[i1]);
            }
            #pragma unroll
            for (int r = 0; r < 2; ++r) {
                int rb = r * 16;
                float2 f0 = *(const float2*)&sB[(rb + gid)     * MXP + k0 + 2 * tig];
                float2 f1 = *(const float2*)&sB[(rb + gid + 8) * MXP + k0 + 2 * tig];
                float2 f2 = *(const float2*)&sB[(rb + gid)     * MXP + k0 + 8 + 2 * tig];
                float2 f3 = *(const float2*)&sB[(rb + gid + 8) * MXP + k0 + 8 + 2 * tig];
                u32 ah0, al0, ah1, al1, ah2, al2, ah3, al3;
                split_a(f0, ah0, al0); split_a(f1, ah1, al1);
                split_a(f2, ah2, al2); split_a(f3, ah3, al3);
                #pragma unroll
                for (int t = 0; t < 6; ++t) {
                    mma_bf16(acc[r][t][0], acc[r][t][1], acc[r][t][2], acc[r][t][3],
                             ah0, ah1, ah2, ah3, bh[t][0], bh[t][1]);
                    mma_bf16(acc[r][t][0], acc[r][t][1], acc[r][t][2], acc[r][t][3],
                             al0, al1, al2, al3, bh[t][0], bh[t][1]);
                    mma_bf16(acc[r][t][0], acc[r][t][1], acc[r][t][2], acc[r][t][3],
                             ah0, ah1, ah2, ah3, bl[t][0], bl[t][1]);
                }
            }
        }
        __syncthreads();
        #pragma unroll
        for (int r = 0; r < 2; ++r) {
            int row0 = r * 16 + gid;
            int row1 = row0 + 8;
            #pragma unroll
            for (int t = 0; t < 6; ++t) {
                int col = nbase + t * 8 + 2 * tig;
                float b0v = __ldg(&bm2[col]);
                float b1v = __ldg(&bm2[col + 1]);
                sA[row0 * MXP + col]     = acc[r][t][0] + b0v;
                sA[row0 * MXP + col + 1] = acc[r][t][1] + b1v;
                sA[row1 * MXP + col]     = acc[r][t][2] + b0v;
                sA[row1 * MXP + col + 1] = acc[r][t][3] + b1v;
            }
        }
    }
    __syncthreads();

    for (int slot = tid; slot < 32 * HH; slot += 256) {
        int r = slot >> 7;
        int o = slot & 127;
        int n = n0 + r;
        if (n >= NN) break;
        float dq  = sA[r * MXP + o];
        float dms = sA[r * MXP + HH + o];
        float dqm = sA[r * MXP + 2 * HH + o];
        qout[n * HH + o] = g_qmid[n * HH + o] + dq + dqm * g_inner[n * HH + o];
        #pragma unroll
        for (int d = 0; d < 3; ++d) {
            int idx = n * 3 * HH + d * HH + o;
            muout[idx] = g_mumid[idx] + g_muw[idx] * dms;
        }
    }
}

// ---------------- launch ----------------
extern "C" void kernel_launch(void* const* d_in, const int* in_sizes, int n_in,
                              void* d_out, int out_size)
{
    const float* q   = (const float*)d_in[0];
    const float* mu  = (const float*)d_in[1];
    const int*   ei  = (const int*)d_in[2];
    const float* rbf = (const float*)d_in[3];
    const float* uv  = (const float*)d_in[4];
    const float* cut = (const float*)d_in[5];
    const float* Wi1 = (const float*)d_in[6];
    const float* bi1 = (const float*)d_in[7];
    const float* Wi2 = (const float*)d_in[8];
    const float* bi2 = (const float*)d_in[9];
    const float* Wf1 = (const float*)d_in[10];
    const float* bf1 = (const float*)d_in[11];
    const float* Wf2 = (const float*)d_in[12];
    const float* bf2 = (const float*)d_in[13];
    const float* Wv  = (const float*)d_in[14];
    const float* Wm1 = (const float*)d_in[15];
    const float* bm1 = (const float*)d_in[16];
    const float* Wm2 = (const float*)d_in[17];
    const float* bm2 = (const float*)d_in[18];

    float* qout  = (float*)d_out;
    float* muout = qout + (size_t)NN * HH;

    cudaFuncSetAttribute(k_node_mlp, cudaFuncAttributeMaxDynamicSharedMemorySize, NODE_SMEM);
    cudaFuncSetAttribute(k_equiv,    cudaFuncAttributeMaxDynamicSharedMemorySize, EQ_SMEM);
    cudaFuncSetAttribute(k_mix,      cudaFuncAttributeMaxDynamicSharedMemorySize, MIX_SMEM);

    // merged prologue: weight splits + count zeroing (one launch)
    k_prep<<<(SEG6 + 255) / 256, 256>>>(Wf2, Wi1, Wi2, Wv, Wm1, Wm2);
    // CSR build
    k_count<<<512, 256>>>(ei);
    k_scan<<<1, 1024>>>();
    k_fill<<<512, 256>>>(ei, uv);

    // dense stages
    k_node_mlp<<<(NN + 31) / 32, 256, NODE_SMEM>>>(q, bi1, bi2);
    k_edge_filter<<<NE / 64, 256>>>(rbf, cut, Wf1, bf1, bf2);

    // message aggregation
    k_aggregate<<<NN, 128>>>(q, mu);

    // mixing
    k_equiv<<<(NN + 15) / 16, 256, EQ_SMEM>>>();
    k_mix<<<(NN + 31) / 32, 256, MIX_SMEM>>>(bm1, bm2, qout, muout);
}

// round 12
// speedup vs baseline: 1.3384x; 1.2786x over previous
#include <cuda_runtime.h>
#include <cuda_bf16.h>
#include <cuda_fp16.h>
#include <math.h>

#define NN 10000
#define NE 256000
#define HH 128
#define H2 256
#define H3 384
#define NR 20

typedef unsigned int u32;

// ---------------- scratch (static device globals; no allocation) ----------------
__device__ float  g_x[NN * H3];                    // node MLP out (fp32, L2-resident)
__device__ __half g_filters[(size_t)NE * H3];      // fp16 filters in CSR order (196 MB)
__device__ float4 g_uv4[NE];                       // unit vectors in CSR order
__device__ int    g_src[NE];                       // source node in CSR order
__device__ int    g_epos[NE];                      // edge -> CSR position
__device__ u32   g_bhp[(HH / 2) * H3];             // Wf2 fp16x2 k-pairs (single term)
__device__ u32   g_i1h[(HH / 2) * H3];
__device__ u32   g_i1l[(HH / 2) * H3];
__device__ u32   g_i2h[(H3 / 2) * H3];
__device__ u32   g_i2l[(H3 / 2) * H3];
__device__ u32   g_vch[(HH / 2) * H2];
__device__ u32   g_vcl[(HH / 2) * H2];
__device__ u32   g_m1h[(H2 / 2) * H3];
__device__ u32   g_m1l[(H2 / 2) * H3];
__device__ u32   g_m2h[(H3 / 2) * H3];
__device__ u32   g_m2l[(H3 / 2) * H3];
__device__ float g_qmid[NN * HH];
__device__ float g_mumid[NN * 3 * HH];
__device__ float g_vnorm[NN * HH];
__device__ float g_inner[NN * HH];
__device__ float g_muw[NN * 3 * HH];
__device__ int   g_count[NN];
__device__ int   g_off[NN + 1];
__device__ int   g_cursor[NN];

__device__ __forceinline__ float silu_f(float x) {
    return x / (1.0f + __expf(-x));
}

__device__ __forceinline__ u32 pack_bf16x2(float lo, float hi) {
    u32 r;
    asm("cvt.rn.bf16x2.f32 %0, %1, %2;" : "=r"(r) : "f"(hi), "f"(lo));
    return r;
}

__device__ __forceinline__ u32 pack_f16x2(float lo, float hi) {
    __half2 h = __floats2half2_rn(lo, hi);
    return *(u32*)&h;
}

__device__ __forceinline__ void mma_bf16(float& c0, float& c1, float& c2, float& c3,
                                         u32 a0, u32 a1, u32 a2, u32 a3,
                                         u32 b0, u32 b1) {
    asm("mma.sync.aligned.m16n8k16.row.col.f32.bf16.bf16.f32 "
        "{%0,%1,%2,%3}, {%4,%5,%6,%7}, {%8,%9}, {%0,%1,%2,%3};"
        : "+f"(c0), "+f"(c1), "+f"(c2), "+f"(c3)
        : "r"(a0), "r"(a1), "r"(a2), "r"(a3), "r"(b0), "r"(b1));
}

__device__ __forceinline__ void mma_f16(float& c0, float& c1, float& c2, float& c3,
                                        u32 a0, u32 a1, u32 a2, u32 a3,
                                        u32 b0, u32 b1) {
    asm("mma.sync.aligned.m16n8k16.row.col.f32.f16.f16.f32 "
        "{%0,%1,%2,%3}, {%4,%5,%6,%7}, {%8,%9}, {%0,%1,%2,%3};"
        : "+f"(c0), "+f"(c1), "+f"(c2), "+f"(c3)
        : "r"(a0), "r"(a1), "r"(a2), "r"(a3), "r"(b0), "r"(b1));
}

__device__ __forceinline__ void split_a(float2 f, u32& hi, u32& lo) {
    hi = pack_bf16x2(f.x, f.y);
    lo = pack_bf16x2(f.x - __uint_as_float(hi << 16),
                     f.y - __uint_as_float(hi & 0xFFFF0000u));
}

// fp16 2-term split: hi = rn(v), lo = rn(v - hi)
__device__ __forceinline__ void split_pair_f16(float v0, float v1, u32& hi, u32& lo) {
    __half2 h = __floats2half2_rn(v0, v1);
    hi = *(u32*)&h;
    float r0 = v0 - __half2float(__low2half(h));
    float r1 = v1 - __half2float(__high2half(h));
    lo = pack_f16x2(r0, r1);
}

// ---------------- merged prologue: weight splits + count zeroing ----------------
__device__ __forceinline__ void do_split(const float* __restrict__ W,
                                         u32* __restrict__ hi, u32* __restrict__ lo,
                                         int idx, int width) {
    int p = idx / width, col = idx % width;
    float w0 = W[(2 * p) * width + col];
    float w1 = W[(2 * p + 1) * width + col];
    u32 h01 = pack_bf16x2(w0, w1);
    float h0 = __uint_as_float(h01 << 16);
    float h1 = __uint_as_float(h01 & 0xFFFF0000u);
    hi[idx] = h01;
    lo[idx] = pack_bf16x2(w0 - h0, w1 - h1);
}

#define SEG0 24576          // Wf2   (64 x 384)  -> fp16x2 single term
#define SEG1 49152          // Wi1
#define SEG2 122880         // Wi2
#define SEG3 139264         // Wv
#define SEG4 188416         // Wm1
#define SEG5 262144         // Wm2
#define SEG6 272144         // count zero
__global__ void k_prep(const float* __restrict__ Wf2, const float* __restrict__ Wi1,
                       const float* __restrict__ Wi2, const float* __restrict__ Wv,
                       const float* __restrict__ Wm1, const float* __restrict__ Wm2) {
    int i = blockIdx.x * blockDim.x + threadIdx.x;
    if (i < SEG0) {
        int p = i / H3, col = i % H3;
        g_bhp[i] = pack_f16x2(Wf2[(2 * p) * H3 + col], Wf2[(2 * p + 1) * H3 + col]);
    }
    else if (i < SEG1)  do_split(Wi1, g_i1h, g_i1l, i - SEG0, H3);
    else if (i < SEG2)  do_split(Wi2, g_i2h, g_i2l, i - SEG1, H3);
    else if (i < SEG3)  do_split(Wv,  g_vch, g_vcl, i - SEG2, H2);
    else if (i < SEG4)  do_split(Wm1, g_m1h, g_m1l, i - SEG3, H3);
    else if (i < SEG5)  do_split(Wm2, g_m2h, g_m2l, i - SEG4, H3);
    else if (i < SEG6)  g_count[i - SEG5] = 0;
}

// ---------------- CSR build ----------------
__global__ void k_count(const int* __restrict__ ei) {
    for (int e = blockIdx.x * blockDim.x + threadIdx.x; e < NE;
         e += gridDim.x * blockDim.x)
        atomicAdd(&g_count[ei[e]], 1);
}

__global__ __launch_bounds__(1024) void k_scan() {
    __shared__ int ps[1024];
    int tid = threadIdx.x;
    const int CH = (NN + 1023) / 1024;
    int base = tid * CH;
    int s = 0;
    for (int j = 0; j < CH; ++j) {
        int idx = base + j;
        if (idx < NN) s += g_count[idx];
    }
    ps[tid] = s;
    __syncthreads();
    for (int off = 1; off < 1024; off <<= 1) {
        int v = 0;
        if (tid >= off) v = ps[tid - off];
        __syncthreads();
        ps[tid] += v;
        __syncthreads();
    }
    int run = ps[tid] - s;
    for (int j = 0; j < CH; ++j) {
        int idx = base + j;
        if (idx < NN) {
            g_off[idx] = run;
            g_cursor[idx] = run;
            run += g_count[idx];
        }
    }
    if (tid == 1023) g_off[NN] = ps[1023];
}

__global__ void k_fill(const int* __restrict__ ei, const float* __restrict__ uv) {
    for (int e = blockIdx.x * blockDim.x + threadIdx.x; e < NE;
         e += gridDim.x * blockDim.x) {
        int t = ei[e];
        int pos = atomicAdd(&g_cursor[t], 1);
        g_epos[e] = pos;
        g_src[pos] = ei[NE + e];
        g_uv4[pos] = make_float4(uv[3 * e], uv[3 * e + 1], uv[3 * e + 2], 0.f);
    }
}

// ---------------- node inter MLP via bf16 split mma (proven) ----------------
#define SQP 132
#define SH2P 388
#define NODE_SMEM ((32 * SQP + 32 * SH2P) * 4)
__global__ __launch_bounds__(256) void k_node_mlp(
    const float* __restrict__ q,
    const float* __restrict__ b1, const float* __restrict__ b2)
{
    extern __shared__ float smn[];
    float* sq = smn;
    float* sh = smn + 32 * SQP;
    int tid = threadIdx.x;
    int n0 = blockIdx.x * 32;

    for (int i = tid; i < 32 * HH; i += 256) {
        int r = i >> 7, c = i & 127;
        int n = n0 + r;
        sq[r * SQP + c] = (n < NN) ? q[n * HH + c] : 0.f;
    }
    __syncthreads();

    int wid  = tid >> 5;
    int lane = tid & 31;
    int gid  = lane >> 2;
    int tig  = lane & 3;
    int nbase = wid * 48;

    {
        float acc[2][6][4];
        #pragma unroll
        for (int r = 0; r < 2; ++r)
            #pragma unroll
            for (int t = 0; t < 6; ++t)
                #pragma unroll
                for (int c = 0; c < 4; ++c) acc[r][t][c] = 0.f;

        #pragma unroll 1
        for (int k0 = 0; k0 < HH; k0 += 16) {
            int kp = k0 >> 1;
            u32 bh[6][2], bl[6][2];
            #pragma unroll
            for (int t = 0; t < 6; ++t) {
                int col = nbase + t * 8 + gid;
                int i0 = (kp + tig) * H3 + col;
                int i1 = (kp + 4 + tig) * H3 + col;
                bh[t][0] = __ldg(&g_i1h[i0]);
                bh[t][1] = __ldg(&g_i1h[i1]);
                bl[t][0] = __ldg(&g_i1l[i0]);
                bl[t][1] = __ldg(&g_i1l[i1]);
            }
            #pragma unroll
            for (int r = 0; r < 2; ++r) {
                int rb = r * 16;
                float2 f0 = *(const float2*)&sq[(rb + gid)     * SQP + k0 + 2 * tig];
                float2 f1 = *(const float2*)&sq[(rb + gid + 8) * SQP + k0 + 2 * tig];
                float2 f2 = *(const float2*)&sq[(rb + gid)     * SQP + k0 + 8 + 2 * tig];
                float2 f3 = *(const float2*)&sq[(rb + gid + 8) * SQP + k0 + 8 + 2 * tig];
                u32 ah0, al0, ah1, al1, ah2, al2, ah3, al3;
                split_a(f0, ah0, al0); split_a(f1, ah1, al1);
                split_a(f2, ah2, al2); split_a(f3, ah3, al3);
                #pragma unroll
                for (int t = 0; t < 6; ++t) {
                    mma_bf16(acc[r][t][0], acc[r][t][1], acc[r][t][2], acc[r][t][3],
                             ah0, ah1, ah2, ah3, bh[t][0], bh[t][1]);
                    mma_bf16(acc[r][t][0], acc[r][t][1], acc[r][t][2], acc[r][t][3],
                             al0, al1, al2, al3, bh[t][0], bh[t][1]);
                    mma_bf16(acc[r][t][0], acc[r][t][1], acc[r][t][2], acc[r][t][3],
                             ah0, ah1, ah2, ah3, bl[t][0], bl[t][1]);
                }
            }
        }
        #pragma unroll
        for (int r = 0; r < 2; ++r) {
            int row0 = r * 16 + gid;
            int row1 = row0 + 8;
            #pragma unroll
            for (int t = 0; t < 6; ++t) {
                int col = nbase + t * 8 + 2 * tig;
                float b0v = __ldg(&b1[col]);
                float b1v = __ldg(&b1[col + 1]);
                sh[row0 * SH2P + col]     = silu_f(acc[r][t][0] + b0v);
                sh[row0 * SH2P + col + 1] = silu_f(acc[r][t][1] + b1v);
                sh[row1 * SH2P + col]     = silu_f(acc[r][t][2] + b0v);
                sh[row1 * SH2P + col + 1] = silu_f(acc[r][t][3] + b1v);
            }
        }
    }
    __syncthreads();

    {
        float acc[2][6][4];
        #pragma unroll
        for (int r = 0; r < 2; ++r)
            #pragma unroll
            for (int t = 0; t < 6; ++t)
                #pragma unroll
                for (int c = 0; c < 4; ++c) acc[r][t][c] = 0.f;

        #pragma unroll 1
        for (int k0 = 0; k0 < H3; k0 += 16) {
            int kp = k0 >> 1;
            u32 bh[6][2], bl[6][2];
            #pragma unroll
            for (int t = 0; t < 6; ++t) {
                int col = nbase + t * 8 + gid;
                int i0 = (kp + tig) * H3 + col;
                int i1 = (kp + 4 + tig) * H3 + col;
                bh[t][0] = __ldg(&g_i2h[i0]);
                bh[t][1] = __ldg(&g_i2h[i1]);
                bl[t][0] = __ldg(&g_i2l[i0]);
                bl[t][1] = __ldg(&g_i2l[i1]);
            }
            #pragma unroll
            for (int r = 0; r < 2; ++r) {
                int rb = r * 16;
                float2 f0 = *(const float2*)&sh[(rb + gid)     * SH2P + k0 + 2 * tig];
                float2 f1 = *(const float2*)&sh[(rb + gid + 8) * SH2P + k0 + 2 * tig];
                float2 f2 = *(const float2*)&sh[(rb + gid)     * SH2P + k0 + 8 + 2 * tig];
                float2 f3 = *(const float2*)&sh[(rb + gid + 8) * SH2P + k0 + 8 + 2 * tig];
                u32 ah0, al0, ah1, al1, ah2, al2, ah3, al3;
                split_a(f0, ah0, al0); split_a(f1, ah1, al1);
                split_a(f2, ah2, al2); split_a(f3, ah3, al3);
                #pragma unroll
                for (int t = 0; t < 6; ++t) {
                    mma_bf16(acc[r][t][0], acc[r][t][1], acc[r][t][2], acc[r][t][3],
                             ah0, ah1, ah2, ah3, bh[t][0], bh[t][1]);
                    mma_bf16(acc[r][t][0], acc[r][t][1], acc[r][t][2], acc[r][t][3],
                             al0, al1, al2, al3, bh[t][0], bh[t][1]);
                    mma_bf16(acc[r][t][0], acc[r][t][1], acc[r][t][2], acc[r][t][3],
                             ah0, ah1, ah2, ah3, bl[t][0], bl[t][1]);
                }
            }
        }
        #pragma unroll
        for (int r = 0; r < 2; ++r) {
            int row0 = r * 16 + gid;
            int row1 = row0 + 8;
            #pragma unroll
            for (int t = 0; t < 6; ++t) {
                int col = nbase + t * 8 + 2 * tig;
                float b0v = __ldg(&b2[col]);
                float b1v = __ldg(&b2[col + 1]);
                if (n0 + row0 < NN)
                    *(float2*)&g_x[(size_t)(n0 + row0) * H3 + col] =
                        make_float2(acc[r][t][0] + b0v, acc[r][t][1] + b1v);
                if (n0 + row1 < NN)
                    *(float2*)&g_x[(size_t)(n0 + row1) * H3 + col] =
                        make_float2(acc[r][t][2] + b0v, acc[r][t][3] + b1v);
            }
        }
    }
}

// ---------------- edge filter MLP: phase1 scalar + fp16 pre-split, phase2 fp16 2-term mma ----------------
#define KPS 68
__global__ __launch_bounds__(256) void k_edge_filter(
    const float* __restrict__ rbf, const float* __restrict__ cut,
    const float* __restrict__ Wf1, const float* __restrict__ bf1,
    const float* __restrict__ bf2)
{
    __shared__ float srb[64][NR];
    __shared__ float scut[64];
    __shared__ int   spos[64];
    __shared__ u32 shiT[64 * KPS];   // hidden fp16x2 hi, [row][kp]
    __shared__ u32 sloT[64 * KPS];   // hidden fp16x2 residual
    int tid = threadIdx.x;
    int e0 = blockIdx.x * 64;

    for (int i = tid; i < 64 * NR; i += 256)
        srb[i / NR][i % NR] = rbf[(e0 + i / NR) * NR + (i % NR)];
    if (tid < 64) {
        scut[tid] = cut[e0 + tid];
        spos[tid] = g_epos[e0 + tid];
    }
    __syncthreads();

    // phase 1 (scalar, K=20) + fp16 split epilogue
    {
        int rg = tid >> 4;
        int cg = tid & 15;
        int r0 = rg * 4;
        for (int pass = 0; pass < 2; ++pass) {
            int c0 = cg * 4 + pass * 64;
            float acc[4][4] = {};
            for (int k = 0; k < NR; ++k) {
                float4 w = *reinterpret_cast<const float4*>(&Wf1[k * HH + c0]);
                #pragma unroll
                for (int i = 0; i < 4; ++i) {
                    float s = srb[r0 + i][k];
                    acc[i][0] = fmaf(s, w.x, acc[i][0]);
                    acc[i][1] = fmaf(s, w.y, acc[i][1]);
                    acc[i][2] = fmaf(s, w.z, acc[i][2]);
                    acc[i][3] = fmaf(s, w.w, acc[i][3]);
                }
            }
            int kp0 = c0 >> 1;
            #pragma unroll
            for (int i = 0; i < 4; ++i) {
                float v0 = silu_f(acc[i][0] + bf1[c0]);
                float v1 = silu_f(acc[i][1] + bf1[c0 + 1]);
                float v2 = silu_f(acc[i][2] + bf1[c0 + 2]);
                float v3 = silu_f(acc[i][3] + bf1[c0 + 3]);
                u32 h0, l0, h1, l1;
                split_pair_f16(v0, v1, h0, l0);
                split_pair_f16(v2, v3, h1, l1);
                shiT[(r0 + i) * KPS + kp0]     = h0;
                sloT[(r0 + i) * KPS + kp0]     = l0;
                shiT[(r0 + i) * KPS + kp0 + 1] = h1;
                sloT[(r0 + i) * KPS + kp0 + 1] = l1;
            }
        }
    }
    __syncthreads();

    // phase 2: fp16 2-term split mma (B single fp16)
    int wid  = tid >> 5;
    int lane = tid & 31;
    int gid  = lane >> 2;
    int tig  = lane & 3;
    int nbase = wid * 48;

    float acc[4][6][4];
    #pragma unroll
    for (int r = 0; r < 4; ++r)
        #pragma unroll
        for (int t = 0; t < 6; ++t)
            #pragma unroll
            for (int c = 0; c < 4; ++c) acc[r][t][c] = 0.f;

    #pragma unroll 1
    for (int k0 = 0; k0 < HH; k0 += 16) {
        int kp = k0 >> 1;
        u32 bh[6][2];
        #pragma unroll
        for (int t = 0; t < 6; ++t) {
            int col = nbase + t * 8 + gid;
            bh[t][0] = __ldg(&g_bhp[(kp + tig) * H3 + col]);
            bh[t][1] = __ldg(&g_bhp[(kp + 4 + tig) * H3 + col]);
        }
        #pragma unroll
        for (int r = 0; r < 4; ++r) {
            int rb = r * 16;
            int ra = (rb + gid) * KPS;
            int rc = (rb + gid + 8) * KPS;
            u32 ah0 = shiT[ra + kp + tig];
            u32 ah1 = shiT[rc + kp + tig];
            u32 ah2 = shiT[ra + kp + 4 + tig];
            u32 ah3 = shiT[rc + kp + 4 + tig];
            u32 al0 = sloT[ra + kp + tig];
            u32 al1 = sloT[rc + kp + tig];
            u32 al2 = sloT[ra + kp + 4 + tig];
            u32 al3 = sloT[rc + kp + 4 + tig];
            #pragma unroll
            for (int t = 0; t < 6; ++t) {
                mma_f16(acc[r][t][0], acc[r][t][1], acc[r][t][2], acc[r][t][3],
                        ah0, ah1, ah2, ah3, bh[t][0], bh[t][1]);
                mma_f16(acc[r][t][0], acc[r][t][1], acc[r][t][2], acc[r][t][3],
                        al0, al1, al2, al3, bh[t][0], bh[t][1]);
            }
        }
    }

    #pragma unroll
    for (int r = 0; r < 4; ++r) {
        int row0 = r * 16 + gid;
        int row1 = row0 + 8;
        float c0v = scut[row0];
        float c1v = scut[row1];
        size_t p0 = (size_t)spos[row0] * H3;
        size_t p1 = (size_t)spos[row1] * H3;
        #pragma unroll
        for (int t = 0; t < 6; ++t) {
            int col = nbase + t * 8 + 2 * tig;
            float b0v = bf2[col];
            float b1v = bf2[col + 1];
            __half2 v0 = __floats2half2_rn((acc[r][t][0] + b0v) * c0v,
                                           (acc[r][t][1] + b1v) * c0v);
            __half2 v1 = __floats2half2_rn((acc[r][t][2] + b0v) * c1v,
                                           (acc[r][t][3] + b1v) * c1v);
            *(__half2*)&g_filters[p0 + col] = v0;
            *(__half2*)&g_filters[p1 + col] = v1;
        }
    }
}

// ---------------- pull aggregation: streaming filters/uv/src ----------------
__global__ __launch_bounds__(128) void k_aggregate(
    const float* __restrict__ q, const float* __restrict__ mu)
{
    int n = blockIdx.x;
    int h = threadIdx.x;
    int beg = g_off[n], end = g_off[n + 1];
    float qa = 0.f, m0 = 0.f, m1 = 0.f, m2 = 0.f;
    for (int i = beg; i < end; ++i) {
        int s = g_src[i];
        const __half* f = &g_filters[(size_t)i * H3];
        float fq = __half2float(f[h]);
        float fr = __half2float(f[HH + h]);
        float fm = __half2float(f[2 * HH + h]);
        const float* xs = &g_x[s * H3];
        float xq = xs[h] * fq;
        float xr = xs[HH + h] * fr;
        float xm = xs[2 * HH + h] * fm;
        float4 u = g_uv4[i];
        const float* ms = &mu[s * 3 * HH];
        qa += xq;
        m0 = fmaf(u.x, xr, fmaf(ms[h],          xm, m0));
        m1 = fmaf(u.y, xr, fmaf(ms[HH + h],     xm, m1));
        m2 = fmaf(u.z, xr, fmaf(ms[2 * HH + h], xm, m2));
    }
    g_qmid[n * HH + h] = q[n * HH + h] + qa;
    g_mumid[n * 3 * HH + h]          = mu[n * 3 * HH + h] + m0;
    g_mumid[n * 3 * HH + HH + h]     = mu[n * 3 * HH + HH + h] + m1;
    g_mumid[n * 3 * HH + 2 * HH + h] = mu[n * 3 * HH + 2 * HH + h] + m2;
}

// ---------------- equivariant linear via bf16 split mma ----------------
#define EMP 132
#define EOP 260
#define EQ_SMEM ((48 * EMP + 48 * EOP) * 4)
__global__ __launch_bounds__(256) void k_equiv()
{
    extern __shared__ float sme[];
    float* smu  = sme;
    float* sout = sme + 48 * EMP;
    int tid = threadIdx.x;
    int n0 = blockIdx.x * 16;
    int row_base = n0 * 3;

    for (int i = tid; i < 48 * HH; i += 256) {
        int r = i >> 7, c = i & 127;
        int grow = row_base + r;
        smu[r * EMP + c] = (grow < NN * 3) ? g_mumid[grow * HH + c] : 0.f;
    }
    __syncthreads();

    int wid  = tid >> 5;
    int lane = tid & 31;
    int gid  = lane >> 2;
    int tig  = lane & 3;
    int nbase = wid * 32;

    float acc[3][4][4];
    #pragma unroll
    for (int r = 0; r < 3; ++r)
        #pragma unroll
        for (int t = 0; t < 4; ++t)
            #pragma unroll
            for (int c = 0; c < 4; ++c) acc[r][t][c] = 0.f;

    #pragma unroll 1
    for (int k0 = 0; k0 < HH; k0 += 16) {
        int kp = k0 >> 1;
        u32 bh[4][2], bl[4][2];
        #pragma unroll
        for (int t = 0; t < 4; ++t) {
            int col = nbase + t * 8 + gid;
            int i0 = (kp + tig) * H2 + col;
            int i1 = (kp + 4 + tig) * H2 + col;
            bh[t][0] = __ldg(&g_vch[i0]);
            bh[t][1] = __ldg(&g_vch[i1]);
            bl[t][0] = __ldg(&g_vcl[i0]);
            bl[t][1] = __ldg(&g_vcl[i1]);
        }
        #pragma unroll
        for (int r = 0; r < 3; ++r) {
            int rb = r * 16;
            float2 f0 = *(const float2*)&smu[(rb + gid)     * EMP + k0 + 2 * tig];
            float2 f1 = *(const float2*)&smu[(rb + gid + 8) * EMP + k0 + 2 * tig];
            float2 f2 = *(const float2*)&smu[(rb + gid)     * EMP + k0 + 8 + 2 * tig];
            float2 f3 = *(const float2*)&smu[(rb + gid + 8) * EMP + k0 + 8 + 2 * tig];
            u32 ah0, al0, ah1, al1, ah2, al2, ah3, al3;
            split_a(f0, ah0, al0); split_a(f1, ah1, al1);
            split_a(f2, ah2, al2); split_a(f3, ah3, al3);
            #pragma unroll
            for (int t = 0; t < 4; ++t) {
                mma_bf16(acc[r][t][0], acc[r][t][1], acc[r][t][2], acc[r][t][3],
                         ah0, ah1, ah2, ah3, bh[t][0], bh[t][1]);
                mma_bf16(acc[r][t][0], acc[r][t][1], acc[r][t][2], acc[r][t][3],
                         al0, al1, al2, al3, bh[t][0], bh[t][1]);
                mma_bf16(acc[r][t][0], acc[r][t][1], acc[r][t][2], acc[r][t][3],
                         ah0, ah1, ah2, ah3, bl[t][0], bl[t][1]);
            }
        }
    }

    #pragma unroll
    for (int r = 0; r < 3; ++r) {
        int row0 = r * 16 + gid;
        int row1 = row0 + 8;
        #pragma unroll
        for (int t = 0; t < 4; ++t) {
            int col = nbase + t * 8 + 2 * tig;
            sout[row0 * EOP + col]     = acc[r][t][0];
            sout[row0 * EOP + col + 1] = acc[r][t][1];
            sout[row1 * EOP + col]     = acc[r][t][2];
            sout[row1 * EOP + col + 1] = acc[r][t][3];
        }
    }
    __syncthreads();

    for (int slot = tid; slot < 16 * HH; slot += 256) {
        int r = slot >> 7;
        int o = slot & 127;
        int n = n0 + r;
        if (n >= NN) break;
        float v0 = sout[(r * 3 + 0) * EOP + o];
        float v1 = sout[(r * 3 + 1) * EOP + o];
        float v2 = sout[(r * 3 + 2) * EOP + o];
        float w0 = sout[(r * 3 + 0) * EOP + HH + o];
        float w1 = sout[(r * 3 + 1) * EOP + HH + o];
        float w2 = sout[(r * 3 + 2) * EOP + HH + o];
        g_vnorm[n * HH + o] = sqrtf(v0 * v0 + v1 * v1 + v2 * v2 + 1e-8f);
        g_inner[n * HH + o] = v0 * w0 + v1 * w1 + v2 * w2;
        g_muw[n * 3 * HH + o]          = w0;
        g_muw[n * 3 * HH + HH + o]     = w1;
        g_muw[n * 3 * HH + 2 * HH + o] = w2;
    }
}

// ---------------- scalar mix MLP via bf16 split mma + final update ----------------
#define MXP 388
#define MIX_SMEM ((32 * MXP * 2) * 4)
__global__ __launch_bounds__(256) void k_mix(
    const float* __restrict__ bm1, const float* __restrict__ bm2,
    float* __restrict__ qout, float* __restrict__ muout)
{
    extern __shared__ float smx[];
    float* sA = smx;
    float* sB = smx + 32 * MXP;
    int tid = threadIdx.x;
    int n0 = blockIdx.x * 32;

    for (int i = tid; i < 32 * H2; i += 256) {
        int r = i >> 8, c = i & 255;
        int n = n0 + r;
        float v = 0.f;
        if (n < NN) v = (c < HH) ? g_qmid[n * HH + c] : g_vnorm[n * HH + (c - HH)];
        sA[r * MXP + c] = v;
    }
    __syncthreads();

    int wid  = tid >> 5;
    int lane = tid & 31;
    int gid  = lane >> 2;
    int tig  = lane & 3;
    int nbase = wid * 48;

    {
        float acc[2][6][4];
        #pragma unroll
        for (int r = 0; r < 2; ++r)
            #pragma unroll
            for (int t = 0; t < 6; ++t)
                #pragma unroll
                for (int c = 0; c < 4; ++c) acc[r][t][c] = 0.f;

        #pragma unroll 1
        for (int k0 = 0; k0 < H2; k0 += 16) {
            int kp = k0 >> 1;
            u32 bh[6][2], bl[6][2];
            #pragma unroll
            for (int t = 0; t < 6; ++t) {
                int col = nbase + t * 8 + gid;
                int i0 = (kp + tig) * H3 + col;
                int i1 = (kp + 4 + tig) * H3 + col;
                bh[t][0] = __ldg(&g_m1h[i0]);
                bh[t][1] = __ldg(&g_m1h[i1]);
                bl[t][0] = __ldg(&g_m1l[i0]);
                bl[t][1] = __ldg(&g_m1l[i1]);
            }
            #pragma unroll
            for (int r = 0; r < 2; ++r) {
                int rb = r * 16;
                float2 f0 = *(const float2*)&sA[(rb + gid)     * MXP + k0 + 2 * tig];
                float2 f1 = *(const float2*)&sA[(rb + gid + 8) * MXP + k0 + 2 * tig];
                float2 f2 = *(const float2*)&sA[(rb + gid)     * MXP + k0 + 8 + 2 * tig];
                float2 f3 = *(const float2*)&sA[(rb + gid + 8) * MXP + k0 + 8 + 2 * tig];
                u32 ah0, al0, ah1, al1, ah2, al2, ah3, al3;
                split_a(f0, ah0, al0); split_a(f1, ah1, al1);
                split_a(f2, ah2, al2); split_a(f3, ah3, al3);
                #pragma unroll
                for (int t = 0; t < 6; ++t) {
                    mma_bf16(acc[r][t][0], acc[r][t][1], acc[r][t][2], acc[r][t][3],
                             ah0, ah1, ah2, ah3, bh[t][0], bh[t][1]);
                    mma_bf16(acc[r][t][0], acc[r][t][1], acc[r][t][2], acc[r][t][3],
                             al0, al1, al2, al3, bh[t][0], bh[t][1]);
                    mma_bf16(acc[r][t][0], acc[r][t][1], acc[r][t][2], acc[r][t][3],
                             ah0, ah1, ah2, ah3, bl[t][0], bl[t][1]);
                }
            }
        }
        #pragma unroll
        for (int r = 0; r < 2; ++r) {
            int row0 = r * 16 + gid;
            int row1 = row0 + 8;
            #pragma unroll
            for (int t = 0; t < 6; ++t) {
                int col = nbase + t * 8 + 2 * tig;
                float b0v = __ldg(&bm1[col]);
                float b1v = __ldg(&bm1[col + 1]);
                sB[row0 * MXP + col]     = silu_f(acc[r][t][0] + b0v);
                sB[row0 * MXP + col + 1] = silu_f(acc[r][t][1] + b1v);
                sB[row1 * MXP + col]     = silu_f(acc[r][t][2] + b0v);
                sB[row1 * MXP + col + 1] = silu_f(acc[r][t][3] + b1v);
            }
        }
    }
    __syncthreads();

    {
        float acc[2][6][4];
        #pragma unroll
        for (int r = 0; r < 2; ++r)
            #pragma unroll
            for (int t = 0; t < 6; ++t)
                #pragma unroll
                for (int c = 0; c < 4; ++c) acc[r][t][c] = 0.f;

        #pragma unroll 1
        for (int k0 = 0; k0 < H3; k0 += 16) {
            int kp = k0 >> 1;
            u32 bh[6][2], bl[6][2];
            #pragma unroll
            for (int t = 0; t < 6; ++t) {
                int col = nbase + t * 8 + gid;
                int i0 = (kp + tig) * H3 + col;
                int i1 = (kp + 4 + tig) * H3 + col;
                bh[t][0] = __ldg(&g_m2h[i0]);
                bh[t][1] = __ldg(&g_m2h[i1]);
                bl[t][0] = __ldg(&g_m2l[i0]);
                bl[t][1] = __ldg(&g_m2l[i1]);
            }
            #pragma unroll
            for (int r = 0; r < 2; ++r) {
                int rb = r * 16;
                float2 f0 = *(const float2*)&sB[(rb + gid)     * MXP + k0 + 2 * tig];
                float2 f1 = *(const float2*)&sB[(rb + gid + 8) * MXP + k0 + 2 * tig];
                float2 f2 = *(const float2*)&sB[(rb + gid)     * MXP + k0 + 8 + 2 * tig];
                float2 f3 = *(const float2*)&sB[(rb + gid + 8) * MXP + k0 + 8 + 2 * tig];
                u32 ah0, al0, ah1, al1, ah2, al2, ah3, al3;
                split_a(f0, ah0, al0); split_a(f1, ah1, al1);
                split_a(f2, ah2, al2); split_a(f3, ah3, al3);
                #pragma unroll
                for (int t = 0; t < 6; ++t) {
                    mma_bf16(acc[r][t][0], acc[r][t][1], acc[r][t][2], acc[r][t][3],
                             ah0, ah1, ah2, ah3, bh[t][0], bh[t][1]);
                    mma_bf16(acc[r][t][0], acc[r][t][1], acc[r][t][2], acc[r][t][3],
                             al0, al1, al2, al3, bh[t][0], bh[t][1]);
                    mma_bf16(acc[r][t][0], acc[r][t][1], acc[r][t][2], acc[r][t][3],
                             ah0, ah1, ah2, ah3, bl[t][0], bl[t][1]);
                }
            }
        }
        __syncthreads();
        #pragma unroll
        for (int r = 0; r < 2; ++r) {
            int row0 = r * 16 + gid;
            int row1 = row0 + 8;
            #pragma unroll
            for (int t = 0; t < 6; ++t) {
                int col = nbase + t * 8 + 2 * tig;
                float b0v = __ldg(&bm2[col]);
                float b1v = __ldg(&bm2[col + 1]);
                sA[row0 * MXP + col]     = acc[r][t][0] + b0v;
                sA[row0 * MXP + col + 1] = acc[r][t][1] + b1v;
                sA[row1 * MXP + col]     = acc[r][t][2] + b0v;
                sA[row1 * MXP + col + 1] = acc[r][t][3] + b1v;
            }
        }
    }
    __syncthreads();

    for (int slot = tid; slot < 32 * HH; slot += 256) {
        int r = slot >> 7;
        int o = slot & 127;
        int n = n0 + r;
        if (n >= NN) break;
        float dq  = sA[r * MXP + o];
        float dms = sA[r * MXP + HH + o];
        float dqm = sA[r * MXP + 2 * HH + o];
        qout[n * HH + o] = g_qmid[n * HH + o] + dq + dqm * g_inner[n * HH + o];
        #pragma unroll
        for (int d = 0; d < 3; ++d) {
            int idx = n * 3 * HH + d * HH + o;
            muout[idx] = g_mumid[idx] + g_muw[idx] * dms;
        }
    }
}

// ---------------- launch ----------------
extern "C" void kernel_launch(void* const* d_in, const int* in_sizes, int n_in,
                              void* d_out, int out_size)
{
    const float* q   = (const float*)d_in[0];
    const float* mu  = (const float*)d_in[1];
    const int*   ei  = (const int*)d_in[2];
    const float* rbf = (const float*)d_in[3];
    const float* uv  = (const float*)d_in[4];
    const float* cut = (const float*)d_in[5];
    const float* Wi1 = (const float*)d_in[6];
    const float* bi1 = (const float*)d_in[7];
    const float* Wi2 = (const float*)d_in[8];
    const float* bi2 = (const float*)d_in[9];
    const float* Wf1 = (const float*)d_in[10];
    const float* bf1 = (const float*)d_in[11];
    const float* Wf2 = (const float*)d_in[12];
    const float* bf2 = (const float*)d_in[13];
    const float* Wv  = (const float*)d_in[14];
    const float* Wm1 = (const float*)d_in[15];
    const float* bm1 = (const float*)d_in[16];
    const float* Wm2 = (const float*)d_in[17];
    const float* bm2 = (const float*)d_in[18];

    float* qout  = (float*)d_out;
    float* muout = qout + (size_t)NN * HH;

    cudaFuncSetAttribute(k_node_mlp, cudaFuncAttributeMaxDynamicSharedMemorySize, NODE_SMEM);
    cudaFuncSetAttribute(k_equiv,    cudaFuncAttributeMaxDynamicSharedMemorySize, EQ_SMEM);
    cudaFuncSetAttribute(k_mix,      cudaFuncAttributeMaxDynamicSharedMemorySize, MIX_SMEM);

    // merged prologue: weight splits + count zeroing (one launch)
    k_prep<<<(SEG6 + 255) / 256, 256>>>(Wf2, Wi1, Wi2, Wv, Wm1, Wm2);
    // CSR build
    k_count<<<512, 256>>>(ei);
    k_scan<<<1, 1024>>>();
    k_fill<<<512, 256>>>(ei, uv);

    // dense stages
    k_node_mlp<<<(NN + 31) / 32, 256, NODE_SMEM>>>(q, bi1, bi2);
    k_edge_filter<<<NE / 64, 256>>>(rbf, cut, Wf1, bf1, bf2);

    // message aggregation
    k_aggregate<<<NN, 128>>>(q, mu);

    // mixing
    k_equiv<<<(NN + 15) / 16, 256, EQ_SMEM>>>();
    k_mix<<<(NN + 31) / 32, 256, MIX_SMEM>>>(bm1, bm2, qout, muout);
}

// round 13
// speedup vs baseline: 1.4475x; 1.0816x over previous
#include <cuda_runtime.h>
#include <cuda_bf16.h>
#include <cuda_fp16.h>
#include <math.h>

#define NN 10000
#define NE 256000
#define HH 128
#define H2 256
#define H3 384
#define NR 20

typedef unsigned int u32;

// ---------------- scratch (static device globals; no allocation) ----------------
__device__ float  g_x[NN * H3];                    // node MLP out (fp32, L2-resident)
__device__ __half g_filters[(size_t)NE * H3];      // fp16 filters in CSR order (196 MB)
__device__ float4 g_uv4[NE];                       // unit vectors in CSR order
__device__ int    g_src[NE];                       // source node in CSR order
__device__ int    g_epos[NE];                      // edge -> CSR position
__device__ u32   g_bhp[(HH / 2) * H3];             // Wf2 fp16x2 k-pairs
__device__ u32   g_i1h[(HH / 2) * H3];             // Wi1 fp16x2 k-pairs
__device__ u32   g_i2h[(H3 / 2) * H3];             // Wi2 fp16x2 k-pairs
__device__ u32   g_vch[(HH / 2) * H2];             // Wvec fp16x2 k-pairs
__device__ u32   g_m1h[(H2 / 2) * H3];             // Wm1 fp16x2 k-pairs
__device__ u32   g_m2h[(H3 / 2) * H3];             // Wm2 fp16x2 k-pairs
__device__ float g_qmid[NN * HH];
__device__ float g_mumid[NN * 3 * HH];
__device__ float g_vnorm[NN * HH];
__device__ float g_inner[NN * HH];
__device__ float g_muw[NN * 3 * HH];
__device__ int   g_count[NN];
__device__ int   g_off[NN + 1];
__device__ int   g_cursor[NN];

__device__ __forceinline__ float silu_f(float x) {
    return x / (1.0f + __expf(-x));
}

__device__ __forceinline__ u32 pack_f16x2(float lo, float hi) {
    __half2 h = __floats2half2_rn(lo, hi);
    return *(u32*)&h;
}

__device__ __forceinline__ void mma_f16(float& c0, float& c1, float& c2, float& c3,
                                        u32 a0, u32 a1, u32 a2, u32 a3,
                                        u32 b0, u32 b1) {
    asm("mma.sync.aligned.m16n8k16.row.col.f32.f16.f16.f32 "
        "{%0,%1,%2,%3}, {%4,%5,%6,%7}, {%8,%9}, {%0,%1,%2,%3};"
        : "+f"(c0), "+f"(c1), "+f"(c2), "+f"(c3)
        : "r"(a0), "r"(a1), "r"(a2), "r"(a3), "r"(b0), "r"(b1));
}

// fp16 2-term split of a float2: hi = rn(v), lo = rn(v - hi)
__device__ __forceinline__ void split_a16(float2 f, u32& hi, u32& lo) {
    __half2 h = __floats2half2_rn(f.x, f.y);
    hi = *(u32*)&h;
    lo = pack_f16x2(f.x - __half2float(__low2half(h)),
                    f.y - __half2float(__high2half(h)));
}

__device__ __forceinline__ void split_pair_f16(float v0, float v1, u32& hi, u32& lo) {
    __half2 h = __floats2half2_rn(v0, v1);
    hi = *(u32*)&h;
    lo = pack_f16x2(v0 - __half2float(__low2half(h)),
                    v1 - __half2float(__high2half(h)));
}

// ---------------- merged prologue: fp16 weight packs + count zeroing ----------------
__device__ __forceinline__ void do_pack16(const float* __restrict__ W,
                                          u32* __restrict__ dst, int idx, int width) {
    int p = idx / width, col = idx % width;
    dst[idx] = pack_f16x2(W[(2 * p) * width + col], W[(2 * p + 1) * width + col]);
}

#define SEG0 24576          // Wf2   (64 x 384)
#define SEG1 49152          // Wi1   (64 x 384)
#define SEG2 122880         // Wi2   (192 x 384)
#define SEG3 139264         // Wv    (64 x 256)
#define SEG4 188416         // Wm1   (128 x 384)
#define SEG5 262144         // Wm2   (192 x 384)
#define SEG6 272144         // count zero
__global__ void k_prep(const float* __restrict__ Wf2, const float* __restrict__ Wi1,
                       const float* __restrict__ Wi2, const float* __restrict__ Wv,
                       const float* __restrict__ Wm1, const float* __restrict__ Wm2) {
    int i = blockIdx.x * blockDim.x + threadIdx.x;
    if (i < SEG0)       do_pack16(Wf2, g_bhp, i, H3);
    else if (i < SEG1)  do_pack16(Wi1, g_i1h, i - SEG0, H3);
    else if (i < SEG2)  do_pack16(Wi2, g_i2h, i - SEG1, H3);
    else if (i < SEG3)  do_pack16(Wv,  g_vch, i - SEG2, H2);
    else if (i < SEG4)  do_pack16(Wm1, g_m1h, i - SEG3, H3);
    else if (i < SEG5)  do_pack16(Wm2, g_m2h, i - SEG4, H3);
    else if (i < SEG6)  g_count[i - SEG5] = 0;
}

// ---------------- CSR build ----------------
__global__ void k_count(const int* __restrict__ ei) {
    for (int e = blockIdx.x * blockDim.x + threadIdx.x; e < NE;
         e += gridDim.x * blockDim.x)
        atomicAdd(&g_count[ei[e]], 1);
}

__global__ __launch_bounds__(1024) void k_scan() {
    __shared__ int ps[1024];
    int tid = threadIdx.x;
    const int CH = (NN + 1023) / 1024;
    int base = tid * CH;
    int s = 0;
    for (int j = 0; j < CH; ++j) {
        int idx = base + j;
        if (idx < NN) s += g_count[idx];
    }
    ps[tid] = s;
    __syncthreads();
    for (int off = 1; off < 1024; off <<= 1) {
        int v = 0;
        if (tid >= off) v = ps[tid - off];
        __syncthreads();
        ps[tid] += v;
        __syncthreads();
    }
    int run = ps[tid] - s;
    for (int j = 0; j < CH; ++j) {
        int idx = base + j;
        if (idx < NN) {
            g_off[idx] = run;
            g_cursor[idx] = run;
            run += g_count[idx];
        }
    }
    if (tid == 1023) g_off[NN] = ps[1023];
}

__global__ void k_fill(const int* __restrict__ ei, const float* __restrict__ uv) {
    for (int e = blockIdx.x * blockDim.x + threadIdx.x; e < NE;
         e += gridDim.x * blockDim.x) {
        int t = ei[e];
        int pos = atomicAdd(&g_cursor[t], 1);
        g_epos[e] = pos;
        g_src[pos] = ei[NE + e];
        g_uv4[pos] = make_float4(uv[3 * e], uv[3 * e + 1], uv[3 * e + 2], 0.f);
    }
}

// ---------------- node inter MLP via fp16 2-term mma ----------------
#define SQP 132
#define SH2P 388
#define NODE_SMEM ((32 * SQP + 32 * SH2P) * 4)
__global__ __launch_bounds__(256) void k_node_mlp(
    const float* __restrict__ q,
    const float* __restrict__ b1, const float* __restrict__ b2)
{
    extern __shared__ float smn[];
    float* sq = smn;
    float* sh = smn + 32 * SQP;
    int tid = threadIdx.x;
    int n0 = blockIdx.x * 32;

    for (int i = tid; i < 32 * HH; i += 256) {
        int r = i >> 7, c = i & 127;
        int n = n0 + r;
        sq[r * SQP + c] = (n < NN) ? q[n * HH + c] : 0.f;
    }
    __syncthreads();

    int wid  = tid >> 5;
    int lane = tid & 31;
    int gid  = lane >> 2;
    int tig  = lane & 3;
    int nbase = wid * 48;

    {
        float acc[2][6][4];
        #pragma unroll
        for (int r = 0; r < 2; ++r)
            #pragma unroll
            for (int t = 0; t < 6; ++t)
                #pragma unroll
                for (int c = 0; c < 4; ++c) acc[r][t][c] = 0.f;

        #pragma unroll 1
        for (int k0 = 0; k0 < HH; k0 += 16) {
            int kp = k0 >> 1;
            u32 bh[6][2];
            #pragma unroll
            for (int t = 0; t < 6; ++t) {
                int col = nbase + t * 8 + gid;
                bh[t][0] = __ldg(&g_i1h[(kp + tig) * H3 + col]);
                bh[t][1] = __ldg(&g_i1h[(kp + 4 + tig) * H3 + col]);
            }
            #pragma unroll
            for (int r = 0; r < 2; ++r) {
                int rb = r * 16;
                float2 f0 = *(const float2*)&sq[(rb + gid)     * SQP + k0 + 2 * tig];
                float2 f1 = *(const float2*)&sq[(rb + gid + 8) * SQP + k0 + 2 * tig];
                float2 f2 = *(const float2*)&sq[(rb + gid)     * SQP + k0 + 8 + 2 * tig];
                float2 f3 = *(const float2*)&sq[(rb + gid + 8) * SQP + k0 + 8 + 2 * tig];
                u32 ah0, al0, ah1, al1, ah2, al2, ah3, al3;
                split_a16(f0, ah0, al0); split_a16(f1, ah1, al1);
                split_a16(f2, ah2, al2); split_a16(f3, ah3, al3);
                #pragma unroll
                for (int t = 0; t < 6; ++t) {
                    mma_f16(acc[r][t][0], acc[r][t][1], acc[r][t][2], acc[r][t][3],
                            ah0, ah1, ah2, ah3, bh[t][0], bh[t][1]);
                    mma_f16(acc[r][t][0], acc[r][t][1], acc[r][t][2], acc[r][t][3],
                            al0, al1, al2, al3, bh[t][0], bh[t][1]);
                }
            }
        }
        #pragma unroll
        for (int r = 0; r < 2; ++r) {
            int row0 = r * 16 + gid;
            int row1 = row0 + 8;
            #pragma unroll
            for (int t = 0; t < 6; ++t) {
                int col = nbase + t * 8 + 2 * tig;
                float b0v = __ldg(&b1[col]);
                float b1v = __ldg(&b1[col + 1]);
                sh[row0 * SH2P + col]     = silu_f(acc[r][t][0] + b0v);
                sh[row0 * SH2P + col + 1] = silu_f(acc[r][t][1] + b1v);
                sh[row1 * SH2P + col]     = silu_f(acc[r][t][2] + b0v);
                sh[row1 * SH2P + col + 1] = silu_f(acc[r][t][3] + b1v);
            }
        }
    }
    __syncthreads();

    {
        float acc[2][6][4];
        #pragma unroll
        for (int r = 0; r < 2; ++r)
            #pragma unroll
            for (int t = 0; t < 6; ++t)
                #pragma unroll
                for (int c = 0; c < 4; ++c) acc[r][t][c] = 0.f;

        #pragma unroll 1
        for (int k0 = 0; k0 < H3; k0 += 16) {
            int kp = k0 >> 1;
            u32 bh[6][2];
            #pragma unroll
            for (int t = 0; t < 6; ++t) {
                int col = nbase + t * 8 + gid;
                bh[t][0] = __ldg(&g_i2h[(kp + tig) * H3 + col]);
                bh[t][1] = __ldg(&g_i2h[(kp + 4 + tig) * H3 + col]);
            }
            #pragma unroll
            for (int r = 0; r < 2; ++r) {
                int rb = r * 16;
                float2 f0 = *(const float2*)&sh[(rb + gid)     * SH2P + k0 + 2 * tig];
                float2 f1 = *(const float2*)&sh[(rb + gid + 8) * SH2P + k0 + 2 * tig];
                float2 f2 = *(const float2*)&sh[(rb + gid)     * SH2P + k0 + 8 + 2 * tig];
                float2 f3 = *(const float2*)&sh[(rb + gid + 8) * SH2P + k0 + 8 + 2 * tig];
                u32 ah0, al0, ah1, al1, ah2, al2, ah3, al3;
                split_a16(f0, ah0, al0); split_a16(f1, ah1, al1);
                split_a16(f2, ah2, al2); split_a16(f3, ah3, al3);
                #pragma unroll
                for (int t = 0; t < 6; ++t) {
                    mma_f16(acc[r][t][0], acc[r][t][1], acc[r][t][2], acc[r][t][3],
                            ah0, ah1, ah2, ah3, bh[t][0], bh[t][1]);
                    mma_f16(acc[r][t][0], acc[r][t][1], acc[r][t][2], acc[r][t][3],
                            al0, al1, al2, al3, bh[t][0], bh[t][1]);
                }
            }
        }
        #pragma unroll
        for (int r = 0; r < 2; ++r) {
            int row0 = r * 16 + gid;
            int row1 = row0 + 8;
            #pragma unroll
            for (int t = 0; t < 6; ++t) {
                int col = nbase + t * 8 + 2 * tig;
                float b0v = __ldg(&b2[col]);
                float b1v = __ldg(&b2[col + 1]);
                if (n0 + row0 < NN)
                    *(float2*)&g_x[(size_t)(n0 + row0) * H3 + col] =
                        make_float2(acc[r][t][0] + b0v, acc[r][t][1] + b1v);
                if (n0 + row1 < NN)
                    *(float2*)&g_x[(size_t)(n0 + row1) * H3 + col] =
                        make_float2(acc[r][t][2] + b0v, acc[r][t][3] + b1v);
            }
        }
    }
}

// ---------------- edge filter MLP (R12 proven: fp16 2-term) ----------------
#define KPS 68
__global__ __launch_bounds__(256) void k_edge_filter(
    const float* __restrict__ rbf, const float* __restrict__ cut,
    const float* __restrict__ Wf1, const float* __restrict__ bf1,
    const float* __restrict__ bf2)
{
    __shared__ float srb[64][NR];
    __shared__ float scut[64];
    __shared__ int   spos[64];
    __shared__ u32 shiT[64 * KPS];
    __shared__ u32 sloT[64 * KPS];
    int tid = threadIdx.x;
    int e0 = blockIdx.x * 64;

    for (int i = tid; i < 64 * NR; i += 256)
        srb[i / NR][i % NR] = rbf[(e0 + i / NR) * NR + (i % NR)];
    if (tid < 64) {
        scut[tid] = cut[e0 + tid];
        spos[tid] = g_epos[e0 + tid];
    }
    __syncthreads();

    {
        int rg = tid >> 4;
        int cg = tid & 15;
        int r0 = rg * 4;
        for (int pass = 0; pass < 2; ++pass) {
            int c0 = cg * 4 + pass * 64;
            float acc[4][4] = {};
            for (int k = 0; k < NR; ++k) {
                float4 w = *reinterpret_cast<const float4*>(&Wf1[k * HH + c0]);
                #pragma unroll
                for (int i = 0; i < 4; ++i) {
                    float s = srb[r0 + i][k];
                    acc[i][0] = fmaf(s, w.x, acc[i][0]);
                    acc[i][1] = fmaf(s, w.y, acc[i][1]);
                    acc[i][2] = fmaf(s, w.z, acc[i][2]);
                    acc[i][3] = fmaf(s, w.w, acc[i][3]);
                }
            }
            int kp0 = c0 >> 1;
            #pragma unroll
            for (int i = 0; i < 4; ++i) {
                float v0 = silu_f(acc[i][0] + bf1[c0]);
                float v1 = silu_f(acc[i][1] + bf1[c0 + 1]);
                float v2 = silu_f(acc[i][2] + bf1[c0 + 2]);
                float v3 = silu_f(acc[i][3] + bf1[c0 + 3]);
                u32 h0, l0, h1, l1;
                split_pair_f16(v0, v1, h0, l0);
                split_pair_f16(v2, v3, h1, l1);
                shiT[(r0 + i) * KPS + kp0]     = h0;
                sloT[(r0 + i) * KPS + kp0]     = l0;
                shiT[(r0 + i) * KPS + kp0 + 1] = h1;
                sloT[(r0 + i) * KPS + kp0 + 1] = l1;
            }
        }
    }
    __syncthreads();

    int wid  = tid >> 5;
    int lane = tid & 31;
    int gid  = lane >> 2;
    int tig  = lane & 3;
    int nbase = wid * 48;

    float acc[4][6][4];
    #pragma unroll
    for (int r = 0; r < 4; ++r)
        #pragma unroll
        for (int t = 0; t < 6; ++t)
            #pragma unroll
            for (int c = 0; c < 4; ++c) acc[r][t][c] = 0.f;

    #pragma unroll 1
    for (int k0 = 0; k0 < HH; k0 += 16) {
        int kp = k0 >> 1;
        u32 bh[6][2];
        #pragma unroll
        for (int t = 0; t < 6; ++t) {
            int col = nbase + t * 8 + gid;
            bh[t][0] = __ldg(&g_bhp[(kp + tig) * H3 + col]);
            bh[t][1] = __ldg(&g_bhp[(kp + 4 + tig) * H3 + col]);
        }
        #pragma unroll
        for (int r = 0; r < 4; ++r) {
            int rb = r * 16;
            int ra = (rb + gid) * KPS;
            int rc = (rb + gid + 8) * KPS;
            u32 ah0 = shiT[ra + kp + tig];
            u32 ah1 = shiT[rc + kp + tig];
            u32 ah2 = shiT[ra + kp + 4 + tig];
            u32 ah3 = shiT[rc + kp + 4 + tig];
            u32 al0 = sloT[ra + kp + tig];
            u32 al1 = sloT[rc + kp + tig];
            u32 al2 = sloT[ra + kp + 4 + tig];
            u32 al3 = sloT[rc + kp + 4 + tig];
            #pragma unroll
            for (int t = 0; t < 6; ++t) {
                mma_f16(acc[r][t][0], acc[r][t][1], acc[r][t][2], acc[r][t][3],
                        ah0, ah1, ah2, ah3, bh[t][0], bh[t][1]);
                mma_f16(acc[r][t][0], acc[r][t][1], acc[r][t][2], acc[r][t][3],
                        al0, al1, al2, al3, bh[t][0], bh[t][1]);
            }
        }
    }

    #pragma unroll
    for (int r = 0; r < 4; ++r) {
        int row0 = r * 16 + gid;
        int row1 = row0 + 8;
        float c0v = scut[row0];
        float c1v = scut[row1];
        size_t p0 = (size_t)spos[row0] * H3;
        size_t p1 = (size_t)spos[row1] * H3;
        #pragma unroll
        for (int t = 0; t < 6; ++t) {
            int col = nbase + t * 8 + 2 * tig;
            float b0v = bf2[col];
            float b1v = bf2[col + 1];
            __half2 v0 = __floats2half2_rn((acc[r][t][0] + b0v) * c0v,
                                           (acc[r][t][1] + b1v) * c0v);
            __half2 v1 = __floats2half2_rn((acc[r][t][2] + b0v) * c1v,
                                           (acc[r][t][3] + b1v) * c1v);
            *(__half2*)&g_filters[p0 + col] = v0;
            *(__half2*)&g_filters[p1 + col] = v1;
        }
    }
}

// ---------------- pull aggregation: streaming filters/uv/src ----------------
__global__ __launch_bounds__(128) void k_aggregate(
    const float* __restrict__ q, const float* __restrict__ mu)
{
    int n = blockIdx.x;
    int h = threadIdx.x;
    int beg = g_off[n], end = g_off[n + 1];
    float qa = 0.f, m0 = 0.f, m1 = 0.f, m2 = 0.f;
    for (int i = beg; i < end; ++i) {
        int s = g_src[i];
        const __half* f = &g_filters[(size_t)i * H3];
        float fq = __half2float(f[h]);
        float fr = __half2float(f[HH + h]);
        float fm = __half2float(f[2 * HH + h]);
        const float* xs = &g_x[s * H3];
        float xq = xs[h] * fq;
        float xr = xs[HH + h] * fr;
        float xm = xs[2 * HH + h] * fm;
        float4 u = g_uv4[i];
        const float* ms = &mu[s * 3 * HH];
        qa += xq;
        m0 = fmaf(u.x, xr, fmaf(ms[h],          xm, m0));
        m1 = fmaf(u.y, xr, fmaf(ms[HH + h],     xm, m1));
        m2 = fmaf(u.z, xr, fmaf(ms[2 * HH + h], xm, m2));
    }
    g_qmid[n * HH + h] = q[n * HH + h] + qa;
    g_mumid[n * 3 * HH + h]          = mu[n * 3 * HH + h] + m0;
    g_mumid[n * 3 * HH + HH + h]     = mu[n * 3 * HH + HH + h] + m1;
    g_mumid[n * 3 * HH + 2 * HH + h] = mu[n * 3 * HH + 2 * HH + h] + m2;
}

// ---------------- equivariant linear via fp16 2-term mma ----------------
#define EMP 132
#define EOP 260
#define EQ_SMEM ((48 * EMP + 48 * EOP) * 4)
__global__ __launch_bounds__(256) void k_equiv()
{
    extern __shared__ float sme[];
    float* smu  = sme;
    float* sout = sme + 48 * EMP;
    int tid = threadIdx.x;
    int n0 = blockIdx.x * 16;
    int row_base = n0 * 3;

    for (int i = tid; i < 48 * HH; i += 256) {
        int r = i >> 7, c = i & 127;
        int grow = row_base + r;
        smu[r * EMP + c] = (grow < NN * 3) ? g_mumid[grow * HH + c] : 0.f;
    }
    __syncthreads();

    int wid  = tid >> 5;
    int lane = tid & 31;
    int gid  = lane >> 2;
    int tig  = lane & 3;
    int nbase = wid * 32;

    float acc[3][4][4];
    #pragma unroll
    for (int r = 0; r < 3; ++r)
        #pragma unroll
        for (int t = 0; t < 4; ++t)
            #pragma unroll
            for (int c = 0; c < 4; ++c) acc[r][t][c] = 0.f;

    #pragma unroll 1
    for (int k0 = 0; k0 < HH; k0 += 16) {
        int kp = k0 >> 1;
        u32 bh[4][2];
        #pragma unroll
        for (int t = 0; t < 4; ++t) {
            int col = nbase + t * 8 + gid;
            bh[t][0] = __ldg(&g_vch[(kp + tig) * H2 + col]);
            bh[t][1] = __ldg(&g_vch[(kp + 4 + tig) * H2 + col]);
        }
        #pragma unroll
        for (int r = 0; r < 3; ++r) {
            int rb = r * 16;
            float2 f0 = *(const float2*)&smu[(rb + gid)     * EMP + k0 + 2 * tig];
            float2 f1 = *(const float2*)&smu[(rb + gid + 8) * EMP + k0 + 2 * tig];
            float2 f2 = *(const float2*)&smu[(rb + gid)     * EMP + k0 + 8 + 2 * tig];
            float2 f3 = *(const float2*)&smu[(rb + gid + 8) * EMP + k0 + 8 + 2 * tig];
            u32 ah0, al0, ah1, al1, ah2, al2, ah3, al3;
            split_a16(f0, ah0, al0); split_a16(f1, ah1, al1);
            split_a16(f2, ah2, al2); split_a16(f3, ah3, al3);
            #pragma unroll
            for (int t = 0; t < 4; ++t) {
                mma_f16(acc[r][t][0], acc[r][t][1], acc[r][t][2], acc[r][t][3],
                        ah0, ah1, ah2, ah3, bh[t][0], bh[t][1]);
                mma_f16(acc[r][t][0], acc[r][t][1], acc[r][t][2], acc[r][t][3],
                        al0, al1, al2, al3, bh[t][0], bh[t][1]);
            }
        }
    }

    #pragma unroll
    for (int r = 0; r < 3; ++r) {
        int row0 = r * 16 + gid;
        int row1 = row0 + 8;
        #pragma unroll
        for (int t = 0; t < 4; ++t) {
            int col = nbase + t * 8 + 2 * tig;
            sout[row0 * EOP + col]     = acc[r][t][0];
            sout[row0 * EOP + col + 1] = acc[r][t][1];
            sout[row1 * EOP + col]     = acc[r][t][2];
            sout[row1 * EOP + col + 1] = acc[r][t][3];
        }
    }
    __syncthreads();

    for (int slot = tid; slot < 16 * HH; slot += 256) {
        int r = slot >> 7;
        int o = slot & 127;
        int n = n0 + r;
        if (n >= NN) break;
        float v0 = sout[(r * 3 + 0) * EOP + o];
        float v1 = sout[(r * 3 + 1) * EOP + o];
        float v2 = sout[(r * 3 + 2) * EOP + o];
        float w0 = sout[(r * 3 + 0) * EOP + HH + o];
        float w1 = sout[(r * 3 + 1) * EOP + HH + o];
        float w2 = sout[(r * 3 + 2) * EOP + HH + o];
        g_vnorm[n * HH + o] = sqrtf(v0 * v0 + v1 * v1 + v2 * v2 + 1e-8f);
        g_inner[n * HH + o] = v0 * w0 + v1 * w1 + v2 * w2;
        g_muw[n * 3 * HH + o]          = w0;
        g_muw[n * 3 * HH + HH + o]     = w1;
        g_muw[n * 3 * HH + 2 * HH + o] = w2;
    }
}

// ---------------- scalar mix MLP via fp16 2-term mma + final update ----------------
#define MXP 388
#define MIX_SMEM ((32 * MXP * 2) * 4)
__global__ __launch_bounds__(256) void k_mix(
    const float* __restrict__ bm1, const float* __restrict__ bm2,
    float* __restrict__ qout, float* __restrict__ muout)
{
    extern __shared__ float smx[];
    float* sA = smx;
    float* sB = smx + 32 * MXP;
    int tid = threadIdx.x;
    int n0 = blockIdx.x * 32;

    for (int i = tid; i < 32 * H2; i += 256) {
        int r = i >> 8, c = i & 255;
        int n = n0 + r;
        float v = 0.f;
        if (n < NN) v = (c < HH) ? g_qmid[n * HH + c] : g_vnorm[n * HH + (c - HH)];
        sA[r * MXP + c] = v;
    }
    __syncthreads();

    int wid  = tid >> 5;
    int lane = tid & 31;
    int gid  = lane >> 2;
    int tig  = lane & 3;
    int nbase = wid * 48;

    {
        float acc[2][6][4];
        #pragma unroll
        for (int r = 0; r < 2; ++r)
            #pragma unroll
            for (int t = 0; t < 6; ++t)
                #pragma unroll
                for (int c = 0; c < 4; ++c) acc[r][t][c] = 0.f;

        #pragma unroll 1
        for (int k0 = 0; k0 < H2; k0 += 16) {
            int kp = k0 >> 1;
            u32 bh[6][2];
            #pragma unroll
            for (int t = 0; t < 6; ++t) {
                int col = nbase + t * 8 + gid;
                bh[t][0] = __ldg(&g_m1h[(kp + tig) * H3 + col]);
                bh[t][1] = __ldg(&g_m1h[(kp + 4 + tig) * H3 + col]);
            }
            #pragma unroll
            for (int r = 0; r < 2; ++r) {
                int rb = r * 16;
                float2 f0 = *(const float2*)&sA[(rb + gid)     * MXP + k0 + 2 * tig];
                float2 f1 = *(const float2*)&sA[(rb + gid + 8) * MXP + k0 + 2 * tig];
                float2 f2 = *(const float2*)&sA[(rb + gid)     * MXP + k0 + 8 + 2 * tig];
                float2 f3 = *(const float2*)&sA[(rb + gid + 8) * MXP + k0 + 8 + 2 * tig];
                u32 ah0, al0, ah1, al1, ah2, al2, ah3, al3;
                split_a16(f0, ah0, al0); split_a16(f1, ah1, al1);
                split_a16(f2, ah2, al2); split_a16(f3, ah3, al3);
                #pragma unroll
                for (int t = 0; t < 6; ++t) {
                    mma_f16(acc[r][t][0], acc[r][t][1], acc[r][t][2], acc[r][t][3],
                            ah0, ah1, ah2, ah3, bh[t][0], bh[t][1]);
                    mma_f16(acc[r][t][0], acc[r][t][1], acc[r][t][2], acc[r][t][3],
                            al0, al1, al2, al3, bh[t][0], bh[t][1]);
                }
            }
        }
        #pragma unroll
        for (int r = 0; r < 2; ++r) {
            int row0 = r * 16 + gid;
            int row1 = row0 + 8;
            #pragma unroll
            for (int t = 0; t < 6; ++t) {
                int col = nbase + t * 8 + 2 * tig;
                float b0v = __ldg(&bm1[col]);
                float b1v = __ldg(&bm1[col + 1]);
                sB[row0 * MXP + col]     = silu_f(acc[r][t][0] + b0v);
                sB[row0 * MXP + col + 1] = silu_f(acc[r][t][1] + b1v);
                sB[row1 * MXP + col]     = silu_f(acc[r][t][2] + b0v);
                sB[row1 * MXP + col + 1] = silu_f(acc[r][t][3] + b1v);
            }
        }
    }
    __syncthreads();

    {
        float acc[2][6][4];
        #pragma unroll
        for (int r = 0; r < 2; ++r)
            #pragma unroll
            for (int t = 0; t < 6; ++t)
                #pragma unroll
                for (int c = 0; c < 4; ++c) acc[r][t][c] = 0.f;

        #pragma unroll 1
        for (int k0 = 0; k0 < H3; k0 += 16) {
            int kp = k0 >> 1;
            u32 bh[6][2];
            #pragma unroll
            for (int t = 0; t < 6; ++t) {
                int col = nbase + t * 8 + gid;
                bh[t][0] = __ldg(&g_m2h[(kp + tig) * H3 + col]);
                bh[t][1] = __ldg(&g_m2h[(kp + 4 + tig) * H3 + col]);
            }
            #pragma unroll
            for (int r = 0; r < 2; ++r) {
                int rb = r * 16;
                float2 f0 = *(const float2*)&sB[(rb + gid)     * MXP + k0 + 2 * tig];
                float2 f1 = *(const float2*)&sB[(rb + gid + 8) * MXP + k0 + 2 * tig];
                float2 f2 = *(const float2*)&sB[(rb + gid)     * MXP + k0 + 8 + 2 * tig];
                float2 f3 = *(const float2*)&sB[(rb + gid + 8) * MXP + k0 + 8 + 2 * tig];
                u32 ah0, al0, ah1, al1, ah2, al2, ah3, al3;
                split_a16(f0, ah0, al0); split_a16(f1, ah1, al1);
                split_a16(f2, ah2, al2); split_a16(f3, ah3, al3);
                #pragma unroll
                for (int t = 0; t < 6; ++t) {
                    mma_f16(acc[r][t][0], acc[r][t][1], acc[r][t][2], acc[r][t][3],
                            ah0, ah1, ah2, ah3, bh[t][0], bh[t][1]);
                    mma_f16(acc[r][t][0], acc[r][t][1], acc[r][t][2], acc[r][t][3],
                            al0, al1, al2, al3, bh[t][0], bh[t][1]);
                }
            }
        }
        __syncthreads();
        #pragma unroll
        for (int r = 0; r < 2; ++r) {
            int row0 = r * 16 + gid;
            int row1 = row0 + 8;
            #pragma unroll
            for (int t = 0; t < 6; ++t) {
                int col = nbase + t * 8 + 2 * tig;
                float b0v = __ldg(&bm2[col]);
                float b1v = __ldg(&bm2[col + 1]);
                sA[row0 * MXP + col]     = acc[r][t][0] + b0v;
                sA[row0 * MXP + col + 1] = acc[r][t][1] + b1v;
                sA[row1 * MXP + col]     = acc[r][t][2] + b0v;
                sA[row1 * MXP + col + 1] = acc[r][t][3] + b1v;
            }
        }
    }
    __syncthreads();

    for (int slot = tid; slot < 32 * HH; slot += 256) {
        int r = slot >> 7;
        int o = slot & 127;
        int n = n0 + r;
        if (n >= NN) break;
        float dq  = sA[r * MXP + o];
        float dms = sA[r * MXP + HH + o];
        float dqm = sA[r * MXP + 2 * HH + o];
        qout[n * HH + o] = g_qmid[n * HH + o] + dq + dqm * g_inner[n * HH + o];
        #pragma unroll
        for (int d = 0; d < 3; ++d) {
            int idx = n * 3 * HH + d * HH + o;
            muout[idx] = g_mumid[idx] + g_muw[idx] * dms;
        }
    }
}

// ---------------- launch ----------------
extern "C" void kernel_launch(void* const* d_in, const int* in_sizes, int n_in,
                              void* d_out, int out_size)
{
    const float* q   = (const float*)d_in[0];
    const float* mu  = (const float*)d_in[1];
    const int*   ei  = (const int*)d_in[2];
    const float* rbf = (const float*)d_in[3];
    const float* uv  = (const float*)d_in[4];
    const float* cut = (const float*)d_in[5];
    const float* Wi1 = (const float*)d_in[6];
    const float* bi1 = (const float*)d_in[7];
    const float* Wi2 = (const float*)d_in[8];
    const float* bi2 = (const float*)d_in[9];
    const float* Wf1 = (const float*)d_in[10];
    const float* bf1 = (const float*)d_in[11];
    const float* Wf2 = (const float*)d_in[12];
    const float* bf2 = (const float*)d_in[13];
    const float* Wv  = (const float*)d_in[14];
    const float* Wm1 = (const float*)d_in[15];
    const float* bm1 = (const float*)d_in[16];
    const float* Wm2 = (const float*)d_in[17];
    const float* bm2 = (const float*)d_in[18];

    float* qout  = (float*)d_out;
    float* muout = qout + (size_t)NN * HH;

    cudaFuncSetAttribute(k_node_mlp, cudaFuncAttributeMaxDynamicSharedMemorySize, NODE_SMEM);
    cudaFuncSetAttribute(k_equiv,    cudaFuncAttributeMaxDynamicSharedMemorySize, EQ_SMEM);
    cudaFuncSetAttribute(k_mix,      cudaFuncAttributeMaxDynamicSharedMemorySize, MIX_SMEM);

    // merged prologue: fp16 weight packs + count zeroing (one launch)
    k_prep<<<(SEG6 + 255) / 256, 256>>>(Wf2, Wi1, Wi2, Wv, Wm1, Wm2);
    // CSR build
    k_count<<<512, 256>>>(ei);
    k_scan<<<1, 1024>>>();
    k_fill<<<512, 256>>>(ei, uv);

    // dense stages
    k_node_mlp<<<(NN + 31) / 32, 256, NODE_SMEM>>>(q, bi1, bi2);
    k_edge_filter<<<NE / 64, 256>>>(rbf, cut, Wf1, bf1, bf2);

    // message aggregation
    k_aggregate<<<NN, 128>>>(q, mu);

    // mixing
    k_equiv<<<(NN + 15) / 16, 256, EQ_SMEM>>>();
    k_mix<<<(NN + 31) / 32, 256, MIX_SMEM>>>(bm1, bm2, qout, muout);
}

// round 14
// speedup vs baseline: 1.5229x; 1.0521x over previous
#include <cuda_runtime.h>
#include <cuda_bf16.h>
#include <cuda_fp16.h>
#include <math.h>

#define NN 10000
#define NE 256000
#define HH 128
#define H2 256
#define H3 384
#define NR 20

typedef unsigned int u32;

// ---------------- scratch (static device globals; no allocation) ----------------
__device__ float  g_x[NN * H3];                    // node MLP out (fp32, L2-resident)
__device__ __half g_filters[(size_t)NE * H3];      // fp16 filters in CSR order (196 MB)
__device__ float4 g_uv4[NE];                       // unit vectors in CSR order
__device__ int    g_src[NE];                       // source node in CSR order
__device__ int    g_epos[NE];                      // edge -> CSR position
__device__ u32   g_bhp[(HH / 2) * H3];             // Wf2 fp16x2 k-pairs
__device__ u32   g_i1h[(HH / 2) * H3];             // Wi1 fp16x2 k-pairs
__device__ u32   g_i2h[(H3 / 2) * H3];             // Wi2 fp16x2 k-pairs
__device__ u32   g_vch[(HH / 2) * H2];             // Wvec fp16x2 k-pairs
__device__ u32   g_m1h[(H2 / 2) * H3];             // Wm1 fp16x2 k-pairs
__device__ u32   g_m2h[(H3 / 2) * H3];             // Wm2 fp16x2 k-pairs
__device__ float g_qmid[NN * HH];
__device__ float g_mumid[NN * 3 * HH];
__device__ float g_vnorm[NN * HH];
__device__ float g_inner[NN * HH];
__device__ float g_muw[NN * 3 * HH];
__device__ int   g_count[NN];
__device__ int   g_off[NN + 1];
__device__ int   g_cursor[NN];

__device__ __forceinline__ float silu_f(float x) {
    return x / (1.0f + __expf(-x));
}

__device__ __forceinline__ u32 pack_f16x2(float lo, float hi) {
    __half2 h = __floats2half2_rn(lo, hi);
    return *(u32*)&h;
}

__device__ __forceinline__ void mma_f16(float& c0, float& c1, float& c2, float& c3,
                                        u32 a0, u32 a1, u32 a2, u32 a3,
                                        u32 b0, u32 b1) {
    asm("mma.sync.aligned.m16n8k16.row.col.f32.f16.f16.f32 "
        "{%0,%1,%2,%3}, {%4,%5,%6,%7}, {%8,%9}, {%0,%1,%2,%3};"
        : "+f"(c0), "+f"(c1), "+f"(c2), "+f"(c3)
        : "r"(a0), "r"(a1), "r"(a2), "r"(a3), "r"(b0), "r"(b1));
}

__device__ __forceinline__ void split_a16(float2 f, u32& hi, u32& lo) {
    __half2 h = __floats2half2_rn(f.x, f.y);
    hi = *(u32*)&h;
    lo = pack_f16x2(f.x - __half2float(__low2half(h)),
                    f.y - __half2float(__high2half(h)));
}

__device__ __forceinline__ void split_pair_f16(float v0, float v1, u32& hi, u32& lo) {
    __half2 h = __floats2half2_rn(v0, v1);
    hi = *(u32*)&h;
    lo = pack_f16x2(v0 - __half2float(__low2half(h)),
                    v1 - __half2float(__high2half(h)));
}

// ---------------- merged prologue: fp16 weight packs + count zeroing ----------------
__device__ __forceinline__ void do_pack16(const float* __restrict__ W,
                                          u32* __restrict__ dst, int idx, int width) {
    int p = idx / width, col = idx % width;
    dst[idx] = pack_f16x2(W[(2 * p) * width + col], W[(2 * p + 1) * width + col]);
}

#define SEG0 24576
#define SEG1 49152
#define SEG2 122880
#define SEG3 139264
#define SEG4 188416
#define SEG5 262144
#define SEG6 272144
__global__ void k_prep(const float* __restrict__ Wf2, const float* __restrict__ Wi1,
                       const float* __restrict__ Wi2, const float* __restrict__ Wv,
                       const float* __restrict__ Wm1, const float* __restrict__ Wm2) {
    int i = blockIdx.x * blockDim.x + threadIdx.x;
    if (i < SEG0)       do_pack16(Wf2, g_bhp, i, H3);
    else if (i < SEG1)  do_pack16(Wi1, g_i1h, i - SEG0, H3);
    else if (i < SEG2)  do_pack16(Wi2, g_i2h, i - SEG1, H3);
    else if (i < SEG3)  do_pack16(Wv,  g_vch, i - SEG2, H2);
    else if (i < SEG4)  do_pack16(Wm1, g_m1h, i - SEG3, H3);
    else if (i < SEG5)  do_pack16(Wm2, g_m2h, i - SEG4, H3);
    else if (i < SEG6)  g_count[i - SEG5] = 0;
}

// ---------------- CSR build ----------------
__global__ void k_count(const int* __restrict__ ei) {
    for (int e = blockIdx.x * blockDim.x + threadIdx.x; e < NE;
         e += gridDim.x * blockDim.x)
        atomicAdd(&g_count[ei[e]], 1);
}

// warp-shuffle two-level scan over 10000 counts (1 block, 1024 threads)
__global__ __launch_bounds__(1024) void k_scan() {
    __shared__ int wsum[32];
    int tid = threadIdx.x;
    const int CH = 10;
    int base = tid * CH;
    int vals[CH];
    int s = 0;
    #pragma unroll
    for (int j = 0; j < CH; ++j) {
        int idx = base + j;
        vals[j] = (idx < NN) ? g_count[idx] : 0;
        s += vals[j];
    }
    int lane = tid & 31, w = tid >> 5;
    int x = s;
    #pragma unroll
    for (int o = 1; o < 32; o <<= 1) {
        int v = __shfl_up_sync(0xFFFFFFFFu, x, o);
        if (lane >= o) x += v;
    }
    if (lane == 31) wsum[w] = x;
    __syncthreads();
    if (w == 0) {
        int y = wsum[lane];
        #pragma unroll
        for (int o = 1; o < 32; o <<= 1) {
            int v = __shfl_up_sync(0xFFFFFFFFu, y, o);
            if (lane >= o) y += v;
        }
        wsum[lane] = y;
    }
    __syncthreads();
    int run = x - s + (w > 0 ? wsum[w - 1] : 0);   // exclusive prefix
    #pragma unroll
    for (int j = 0; j < CH; ++j) {
        int idx = base + j;
        if (idx < NN) {
            g_off[idx] = run;
            g_cursor[idx] = run;
            run += vals[j];
        }
    }
    if (tid == 1023) g_off[NN] = run;
}

__global__ void k_fill(const int* __restrict__ ei, const float* __restrict__ uv) {
    for (int e = blockIdx.x * blockDim.x + threadIdx.x; e < NE;
         e += gridDim.x * blockDim.x) {
        int t = ei[e];
        int pos = atomicAdd(&g_cursor[t], 1);
        g_epos[e] = pos;
        g_src[pos] = ei[NE + e];
        g_uv4[pos] = make_float4(uv[3 * e], uv[3 * e + 1], uv[3 * e + 2], 0.f);
    }
}

// ---------------- node inter MLP via fp16 2-term mma (R13 proven) ----------------
#define SQP 132
#define SH2P 388
#define NODE_SMEM ((32 * SQP + 32 * SH2P) * 4)
__global__ __launch_bounds__(256) void k_node_mlp(
    const float* __restrict__ q,
    const float* __restrict__ b1, const float* __restrict__ b2)
{
    extern __shared__ float smn[];
    float* sq = smn;
    float* sh = smn + 32 * SQP;
    int tid = threadIdx.x;
    int n0 = blockIdx.x * 32;

    for (int i = tid; i < 32 * HH; i += 256) {
        int r = i >> 7, c = i & 127;
        int n = n0 + r;
        sq[r * SQP + c] = (n < NN) ? q[n * HH + c] : 0.f;
    }
    __syncthreads();

    int wid  = tid >> 5;
    int lane = tid & 31;
    int gid  = lane >> 2;
    int tig  = lane & 3;
    int nbase = wid * 48;

    {
        float acc[2][6][4];
        #pragma unroll
        for (int r = 0; r < 2; ++r)
            #pragma unroll
            for (int t = 0; t < 6; ++t)
                #pragma unroll
                for (int c = 0; c < 4; ++c) acc[r][t][c] = 0.f;

        #pragma unroll 1
        for (int k0 = 0; k0 < HH; k0 += 16) {
            int kp = k0 >> 1;
            u32 bh[6][2];
            #pragma unroll
            for (int t = 0; t < 6; ++t) {
                int col = nbase + t * 8 + gid;
                bh[t][0] = __ldg(&g_i1h[(kp + tig) * H3 + col]);
                bh[t][1] = __ldg(&g_i1h[(kp + 4 + tig) * H3 + col]);
            }
            #pragma unroll
            for (int r = 0; r < 2; ++r) {
                int rb = r * 16;
                float2 f0 = *(const float2*)&sq[(rb + gid)     * SQP + k0 + 2 * tig];
                float2 f1 = *(const float2*)&sq[(rb + gid + 8) * SQP + k0 + 2 * tig];
                float2 f2 = *(const float2*)&sq[(rb + gid)     * SQP + k0 + 8 + 2 * tig];
                float2 f3 = *(const float2*)&sq[(rb + gid + 8) * SQP + k0 + 8 + 2 * tig];
                u32 ah0, al0, ah1, al1, ah2, al2, ah3, al3;
                split_a16(f0, ah0, al0); split_a16(f1, ah1, al1);
                split_a16(f2, ah2, al2); split_a16(f3, ah3, al3);
                #pragma unroll
                for (int t = 0; t < 6; ++t) {
                    mma_f16(acc[r][t][0], acc[r][t][1], acc[r][t][2], acc[r][t][3],
                            ah0, ah1, ah2, ah3, bh[t][0], bh[t][1]);
                    mma_f16(acc[r][t][0], acc[r][t][1], acc[r][t][2], acc[r][t][3],
                            al0, al1, al2, al3, bh[t][0], bh[t][1]);
                }
            }
        }
        #pragma unroll
        for (int r = 0; r < 2; ++r) {
            int row0 = r * 16 + gid;
            int row1 = row0 + 8;
            #pragma unroll
            for (int t = 0; t < 6; ++t) {
                int col = nbase + t * 8 + 2 * tig;
                float b0v = __ldg(&b1[col]);
                float b1v = __ldg(&b1[col + 1]);
                sh[row0 * SH2P + col]     = silu_f(acc[r][t][0] + b0v);
                sh[row0 * SH2P + col + 1] = silu_f(acc[r][t][1] + b1v);
                sh[row1 * SH2P + col]     = silu_f(acc[r][t][2] + b0v);
                sh[row1 * SH2P + col + 1] = silu_f(acc[r][t][3] + b1v);
            }
        }
    }
    __syncthreads();

    {
        float acc[2][6][4];
        #pragma unroll
        for (int r = 0; r < 2; ++r)
            #pragma unroll
            for (int t = 0; t < 6; ++t)
                #pragma unroll
                for (int c = 0; c < 4; ++c) acc[r][t][c] = 0.f;

        #pragma unroll 1
        for (int k0 = 0; k0 < H3; k0 += 16) {
            int kp = k0 >> 1;
            u32 bh[6][2];
            #pragma unroll
            for (int t = 0; t < 6; ++t) {
                int col = nbase + t * 8 + gid;
                bh[t][0] = __ldg(&g_i2h[(kp + tig) * H3 + col]);
                bh[t][1] = __ldg(&g_i2h[(kp + 4 + tig) * H3 + col]);
            }
            #pragma unroll
            for (int r = 0; r < 2; ++r) {
                int rb = r * 16;
                float2 f0 = *(const float2*)&sh[(rb + gid)     * SH2P + k0 + 2 * tig];
                float2 f1 = *(const float2*)&sh[(rb + gid + 8) * SH2P + k0 + 2 * tig];
                float2 f2 = *(const float2*)&sh[(rb + gid)     * SH2P + k0 + 8 + 2 * tig];
                float2 f3 = *(const float2*)&sh[(rb + gid + 8) * SH2P + k0 + 8 + 2 * tig];
                u32 ah0, al0, ah1, al1, ah2, al2, ah3, al3;
                split_a16(f0, ah0, al0); split_a16(f1, ah1, al1);
                split_a16(f2, ah2, al2); split_a16(f3, ah3, al3);
                #pragma unroll
                for (int t = 0; t < 6; ++t) {
                    mma_f16(acc[r][t][0], acc[r][t][1], acc[r][t][2], acc[r][t][3],
                            ah0, ah1, ah2, ah3, bh[t][0], bh[t][1]);
                    mma_f16(acc[r][t][0], acc[r][t][1], acc[r][t][2], acc[r][t][3],
                            al0, al1, al2, al3, bh[t][0], bh[t][1]);
                }
            }
        }
        #pragma unroll
        for (int r = 0; r < 2; ++r) {
            int row0 = r * 16 + gid;
            int row1 = row0 + 8;
            #pragma unroll
            for (int t = 0; t < 6; ++t) {
                int col = nbase + t * 8 + 2 * tig;
                float b0v = __ldg(&b2[col]);
                float b1v = __ldg(&b2[col + 1]);
                if (n0 + row0 < NN)
                    *(float2*)&g_x[(size_t)(n0 + row0) * H3 + col] =
                        make_float2(acc[r][t][0] + b0v, acc[r][t][1] + b1v);
                if (n0 + row1 < NN)
                    *(float2*)&g_x[(size_t)(n0 + row1) * H3 + col] =
                        make_float2(acc[r][t][2] + b0v, acc[r][t][3] + b1v);
            }
        }
    }
}

// ---------------- edge filter MLP (R12/R13 proven: fp16 2-term) ----------------
#define KPS 68
__global__ __launch_bounds__(256) void k_edge_filter(
    const float* __restrict__ rbf, const float* __restrict__ cut,
    const float* __restrict__ Wf1, const float* __restrict__ bf1,
    const float* __restrict__ bf2)
{
    __shared__ float srb[64][NR];
    __shared__ float scut[64];
    __shared__ int   spos[64];
    __shared__ u32 shiT[64 * KPS];
    __shared__ u32 sloT[64 * KPS];
    int tid = threadIdx.x;
    int e0 = blockIdx.x * 64;

    for (int i = tid; i < 64 * NR; i += 256)
        srb[i / NR][i % NR] = rbf[(e0 + i / NR) * NR + (i % NR)];
    if (tid < 64) {
        scut[tid] = cut[e0 + tid];
        spos[tid] = g_epos[e0 + tid];
    }
    __syncthreads();

    {
        int rg = tid >> 4;
        int cg = tid & 15;
        int r0 = rg * 4;
        for (int pass = 0; pass < 2; ++pass) {
            int c0 = cg * 4 + pass * 64;
            float acc[4][4] = {};
            for (int k = 0; k < NR; ++k) {
                float4 w = *reinterpret_cast<const float4*>(&Wf1[k * HH + c0]);
                #pragma unroll
                for (int i = 0; i < 4; ++i) {
                    float s = srb[r0 + i][k];
                    acc[i][0] = fmaf(s, w.x, acc[i][0]);
                    acc[i][1] = fmaf(s, w.y, acc[i][1]);
                    acc[i][2] = fmaf(s, w.z, acc[i][2]);
                    acc[i][3] = fmaf(s, w.w, acc[i][3]);
                }
            }
            int kp0 = c0 >> 1;
            #pragma unroll
            for (int i = 0; i < 4; ++i) {
                float v0 = silu_f(acc[i][0] + bf1[c0]);
                float v1 = silu_f(acc[i][1] + bf1[c0 + 1]);
                float v2 = silu_f(acc[i][2] + bf1[c0 + 2]);
                float v3 = silu_f(acc[i][3] + bf1[c0 + 3]);
                u32 h0, l0, h1, l1;
                split_pair_f16(v0, v1, h0, l0);
                split_pair_f16(v2, v3, h1, l1);
                shiT[(r0 + i) * KPS + kp0]     = h0;
                sloT[(r0 + i) * KPS + kp0]     = l0;
                shiT[(r0 + i) * KPS + kp0 + 1] = h1;
                sloT[(r0 + i) * KPS + kp0 + 1] = l1;
            }
        }
    }
    __syncthreads();

    int wid  = tid >> 5;
    int lane = tid & 31;
    int gid  = lane >> 2;
    int tig  = lane & 3;
    int nbase = wid * 48;

    float acc[4][6][4];
    #pragma unroll
    for (int r = 0; r < 4; ++r)
        #pragma unroll
        for (int t = 0; t < 6; ++t)
            #pragma unroll
            for (int c = 0; c < 4; ++c) acc[r][t][c] = 0.f;

    #pragma unroll 1
    for (int k0 = 0; k0 < HH; k0 += 16) {
        int kp = k0 >> 1;
        u32 bh[6][2];
        #pragma unroll
        for (int t = 0; t < 6; ++t) {
            int col = nbase + t * 8 + gid;
            bh[t][0] = __ldg(&g_bhp[(kp + tig) * H3 + col]);
            bh[t][1] = __ldg(&g_bhp[(kp + 4 + tig) * H3 + col]);
        }
        #pragma unroll
        for (int r = 0; r < 4; ++r) {
            int rb = r * 16;
            int ra = (rb + gid) * KPS;
            int rc = (rb + gid + 8) * KPS;
            u32 ah0 = shiT[ra + kp + tig];
            u32 ah1 = shiT[rc + kp + tig];
            u32 ah2 = shiT[ra + kp + 4 + tig];
            u32 ah3 = shiT[rc + kp + 4 + tig];
            u32 al0 = sloT[ra + kp + tig];
            u32 al1 = sloT[rc + kp + tig];
            u32 al2 = sloT[ra + kp + 4 + tig];
            u32 al3 = sloT[rc + kp + 4 + tig];
            #pragma unroll
            for (int t = 0; t < 6; ++t) {
                mma_f16(acc[r][t][0], acc[r][t][1], acc[r][t][2], acc[r][t][3],
                        ah0, ah1, ah2, ah3, bh[t][0], bh[t][1]);
                mma_f16(acc[r][t][0], acc[r][t][1], acc[r][t][2], acc[r][t][3],
                        al0, al1, al2, al3, bh[t][0], bh[t][1]);
            }
        }
    }

    #pragma unroll
    for (int r = 0; r < 4; ++r) {
        int row0 = r * 16 + gid;
        int row1 = row0 + 8;
        float c0v = scut[row0];
        float c1v = scut[row1];
        size_t p0 = (size_t)spos[row0] * H3;
        size_t p1 = (size_t)spos[row1] * H3;
        #pragma unroll
        for (int t = 0; t < 6; ++t) {
            int col = nbase + t * 8 + 2 * tig;
            float b0v = bf2[col];
            float b1v = bf2[col + 1];
            __half2 v0 = __floats2half2_rn((acc[r][t][0] + b0v) * c0v,
                                           (acc[r][t][1] + b1v) * c0v);
            __half2 v1 = __floats2half2_rn((acc[r][t][2] + b0v) * c1v,
                                           (acc[r][t][3] + b1v) * c1v);
            *(__half2*)&g_filters[p0 + col] = v0;
            *(__half2*)&g_filters[p1 + col] = v1;
        }
    }
}

// ---------------- pull aggregation: vectorized (2 nodes/block, 64 thr/node) ----------------
__global__ __launch_bounds__(128) void k_aggregate(
    const float* __restrict__ q, const float* __restrict__ mu)
{
    int node = blockIdx.x * 2 + (threadIdx.x >> 6);
    int hp = threadIdx.x & 63;                 // channel-pair index
    if (node >= NN) return;
    int beg = g_off[node], end = g_off[node + 1];
    float2 qa = {0.f, 0.f};
    float2 m0 = {0.f, 0.f}, m1 = {0.f, 0.f}, m2 = {0.f, 0.f};
    for (int i = beg; i < end; ++i) {
        int s = g_src[i];
        const __half2* f = (const __half2*)&g_filters[(size_t)i * H3];
        float2 fq = __half22float2(f[hp]);
        float2 fr = __half22float2(f[64 + hp]);
        float2 fm = __half22float2(f[128 + hp]);
        const float2* xs = (const float2*)&g_x[s * H3];
        float2 x0 = xs[hp], x1 = xs[64 + hp], x2 = xs[128 + hp];
        float4 u = g_uv4[i];
        const float2* ms = (const float2*)&mu[s * 3 * HH];
        float2 u0 = ms[hp], u1v = ms[64 + hp], u2v = ms[128 + hp];
        float xrx = x1.x * fr.x, xry = x1.y * fr.y;
        float xmx = x2.x * fm.x, xmy = x2.y * fm.y;
        qa.x += x0.x * fq.x;
        qa.y += x0.y * fq.y;
        m0.x = fmaf(u.x, xrx, fmaf(u0.x,  xmx, m0.x));
        m0.y = fmaf(u.x, xry, fmaf(u0.y,  xmy, m0.y));
        m1.x = fmaf(u.y, xrx, fmaf(u1v.x, xmx, m1.x));
        m1.y = fmaf(u.y, xry, fmaf(u1v.y, xmy, m1.y));
        m2.x = fmaf(u.z, xrx, fmaf(u2v.x, xmx, m2.x));
        m2.y = fmaf(u.z, xry, fmaf(u2v.y, xmy, m2.y));
    }
    {
        float2 qv = *(const float2*)&q[node * HH + 2 * hp];
        *(float2*)&g_qmid[node * HH + 2 * hp] = make_float2(qv.x + qa.x, qv.y + qa.y);
        const float2* mb = (const float2*)&mu[node * 3 * HH];
        float2 b0 = mb[hp], b1 = mb[64 + hp], b2 = mb[128 + hp];
        float2* out = (float2*)&g_mumid[node * 3 * HH];
        out[hp]       = make_float2(b0.x + m0.x, b0.y + m0.y);
        out[64 + hp]  = make_float2(b1.x + m1.x, b1.y + m1.y);
        out[128 + hp] = make_float2(b2.x + m2.x, b2.y + m2.y);
    }
}

// ---------------- equivariant linear via fp16 2-term mma (R13 proven) ----------------
#define EMP 132
#define EOP 260
#define EQ_SMEM ((48 * EMP + 48 * EOP) * 4)
__global__ __launch_bounds__(256) void k_equiv()
{
    extern __shared__ float sme[];
    float* smu  = sme;
    float* sout = sme + 48 * EMP;
    int tid = threadIdx.x;
    int n0 = blockIdx.x * 16;
    int row_base = n0 * 3;

    for (int i = tid; i < 48 * HH; i += 256) {
        int r = i >> 7, c = i & 127;
        int grow = row_base + r;
        smu[r * EMP + c] = (grow < NN * 3) ? g_mumid[grow * HH + c] : 0.f;
    }
    __syncthreads();

    int wid  = tid >> 5;
    int lane = tid & 31;
    int gid  = lane >> 2;
    int tig  = lane & 3;
    int nbase = wid * 32;

    float acc[3][4][4];
    #pragma unroll
    for (int r = 0; r < 3; ++r)
        #pragma unroll
        for (int t = 0; t < 4; ++t)
            #pragma unroll
            for (int c = 0; c < 4; ++c) acc[r][t][c] = 0.f;

    #pragma unroll 1
    for (int k0 = 0; k0 < HH; k0 += 16) {
        int kp = k0 >> 1;
        u32 bh[4][2];
        #pragma unroll
        for (int t = 0; t < 4; ++t) {
            int col = nbase + t * 8 + gid;
            bh[t][0] = __ldg(&g_vch[(kp + tig) * H2 + col]);
            bh[t][1] = __ldg(&g_vch[(kp + 4 + tig) * H2 + col]);
        }
        #pragma unroll
        for (int r = 0; r < 3; ++r) {
            int rb = r * 16;
            float2 f0 = *(const float2*)&smu[(rb + gid)     * EMP + k0 + 2 * tig];
            float2 f1 = *(const float2*)&smu[(rb + gid + 8) * EMP + k0 + 2 * tig];
            float2 f2 = *(const float2*)&smu[(rb + gid)     * EMP + k0 + 8 + 2 * tig];
            float2 f3 = *(const float2*)&smu[(rb + gid + 8) * EMP + k0 + 8 + 2 * tig];
            u32 ah0, al0, ah1, al1, ah2, al2, ah3, al3;
            split_a16(f0, ah0, al0); split_a16(f1, ah1, al1);
            split_a16(f2, ah2, al2); split_a16(f3, ah3, al3);
            #pragma unroll
            for (int t = 0; t < 4; ++t) {
                mma_f16(acc[r][t][0], acc[r][t][1], acc[r][t][2], acc[r][t][3],
                        ah0, ah1, ah2, ah3, bh[t][0], bh[t][1]);
                mma_f16(acc[r][t][0], acc[r][t][1], acc[r][t][2], acc[r][t][3],
                        al0, al1, al2, al3, bh[t][0], bh[t][1]);
            }
        }
    }

    #pragma unroll
    for (int r = 0; r < 3; ++r) {
        int row0 = r * 16 + gid;
        int row1 = row0 + 8;
        #pragma unroll
        for (int t = 0; t < 4; ++t) {
            int col = nbase + t * 8 + 2 * tig;
            sout[row0 * EOP + col]     = acc[r][t][0];
            sout[row0 * EOP + col + 1] = acc[r][t][1];
            sout[row1 * EOP + col]     = acc[r][t][2];
            sout[row1 * EOP + col + 1] = acc[r][t][3];
        }
    }
    __syncthreads();

    for (int slot = tid; slot < 16 * HH; slot += 256) {
        int r = slot >> 7;
        int o = slot & 127;
        int n = n0 + r;
        if (n >= NN) break;
        float v0 = sout[(r * 3 + 0) * EOP + o];
        float v1 = sout[(r * 3 + 1) * EOP + o];
        float v2 = sout[(r * 3 + 2) * EOP + o];
        float w0 = sout[(r * 3 + 0) * EOP + HH + o];
        float w1 = sout[(r * 3 + 1) * EOP + HH + o];
        float w2 = sout[(r * 3 + 2) * EOP + HH + o];
        g_vnorm[n * HH + o] = sqrtf(v0 * v0 + v1 * v1 + v2 * v2 + 1e-8f);
        g_inner[n * HH + o] = v0 * w0 + v1 * w1 + v2 * w2;
        g_muw[n * 3 * HH + o]          = w0;
        g_muw[n * 3 * HH + HH + o]     = w1;
        g_muw[n * 3 * HH + 2 * HH + o] = w2;
    }
}

// ---------------- scalar mix MLP via fp16 2-term mma + final update (R13 proven) ----------------
#define MXP 388
#define MIX_SMEM ((32 * MXP * 2) * 4)
__global__ __launch_bounds__(256) void k_mix(
    const float* __restrict__ bm1, const float* __restrict__ bm2,
    float* __restrict__ qout, float* __restrict__ muout)
{
    extern __shared__ float smx[];
    float* sA = smx;
    float* sB = smx + 32 * MXP;
    int tid = threadIdx.x;
    int n0 = blockIdx.x * 32;

    for (int i = tid; i < 32 * H2; i += 256) {
        int r = i >> 8, c = i & 255;
        int n = n0 + r;
        float v = 0.f;
        if (n < NN) v = (c < HH) ? g_qmid[n * HH + c] : g_vnorm[n * HH + (c - HH)];
        sA[r * MXP + c] = v;
    }
    __syncthreads();

    int wid  = tid >> 5;
    int lane = tid & 31;
    int gid  = lane >> 2;
    int tig  = lane & 3;
    int nbase = wid * 48;

    {
        float acc[2][6][4];
        #pragma unroll
        for (int r = 0; r < 2; ++r)
            #pragma unroll
            for (int t = 0; t < 6; ++t)
                #pragma unroll
                for (int c = 0; c < 4; ++c) acc[r][t][c] = 0.f;

        #pragma unroll 1
        for (int k0 = 0; k0 < H2; k0 += 16) {
            int kp = k0 >> 1;
            u32 bh[6][2];
            #pragma unroll
            for (int t = 0; t < 6; ++t) {
                int col = nbase + t * 8 + gid;
                bh[t][0] = __ldg(&g_m1h[(kp + tig) * H3 + col]);
                bh[t][1] = __ldg(&g_m1h[(kp + 4 + tig) * H3 + col]);
            }
            #pragma unroll
            for (int r = 0; r < 2; ++r) {
                int rb = r * 16;
                float2 f0 = *(const float2*)&sA[(rb + gid)     * MXP + k0 + 2 * tig];
                float2 f1 = *(const float2*)&sA[(rb + gid + 8) * MXP + k0 + 2 * tig];
                float2 f2 = *(const float2*)&sA[(rb + gid)     * MXP + k0 + 8 + 2 * tig];
                float2 f3 = *(const float2*)&sA[(rb + gid + 8) * MXP + k0 + 8 + 2 * tig];
                u32 ah0, al0, ah1, al1, ah2, al2, ah3, al3;
                split_a16(f0, ah0, al0); split_a16(f1, ah1, al1);
                split_a16(f2, ah2, al2); split_a16(f3, ah3, al3);
                #pragma unroll
                for (int t = 0; t < 6; ++t) {
                    mma_f16(acc[r][t][0], acc[r][t][1], acc[r][t][2], acc[r][t][3],
                            ah0, ah1, ah2, ah3, bh[t][0], bh[t][1]);
                    mma_f16(acc[r][t][0], acc[r][t][1], acc[r][t][2], acc[r][t][3],
                            al0, al1, al2, al3, bh[t][0], bh[t][1]);
                }
            }
        }
        #pragma unroll
        for (int r = 0; r < 2; ++r) {
            int row0 = r * 16 + gid;
            int row1 = row0 + 8;
            #pragma unroll
            for (int t = 0; t < 6; ++t) {
                int col = nbase + t * 8 + 2 * tig;
                float b0v = __ldg(&bm1[col]);
                float b1v = __ldg(&bm1[col + 1]);
                sB[row0 * MXP + col]     = silu_f(acc[r][t][0] + b0v);
                sB[row0 * MXP + col + 1] = silu_f(acc[r][t][1] + b1v);
                sB[row1 * MXP + col]     = silu_f(acc[r][t][2] + b0v);
                sB[row1 * MXP + col + 1] = silu_f(acc[r][t][3] + b1v);
            }
        }
    }
    __syncthreads();

    {
        float acc[2][6][4];
        #pragma unroll
        for (int r = 0; r < 2; ++r)
            #pragma unroll
            for (int t = 0; t < 6; ++t)
                #pragma unroll
                for (int c = 0; c < 4; ++c) acc[r][t][c] = 0.f;

        #pragma unroll 1
        for (int k0 = 0; k0 < H3; k0 += 16) {
            int kp = k0 >> 1;
            u32 bh[6][2];
            #pragma unroll
            for (int t = 0; t < 6; ++t) {
                int col = nbase + t * 8 + gid;
                bh[t][0] = __ldg(&g_m2h[(kp + tig) * H3 + col]);
                bh[t][1] = __ldg(&g_m2h[(kp + 4 + tig) * H3 + col]);
            }
            #pragma unroll
            for (int r = 0; r < 2; ++r) {
                int rb = r * 16;
                float2 f0 = *(const float2*)&sB[(rb + gid)     * MXP + k0 + 2 * tig];
                float2 f1 = *(const float2*)&sB[(rb + gid + 8) * MXP + k0 + 2 * tig];
                float2 f2 = *(const float2*)&sB[(rb + gid)     * MXP + k0 + 8 + 2 * tig];
                float2 f3 = *(const float2*)&sB[(rb + gid + 8) * MXP + k0 + 8 + 2 * tig];
                u32 ah0, al0, ah1, al1, ah2, al2, ah3, al3;
                split_a16(f0, ah0, al0); split_a16(f1, ah1, al1);
                split_a16(f2, ah2, al2); split_a16(f3, ah3, al3);
                #pragma unroll
                for (int t = 0; t < 6; ++t) {
                    mma_f16(acc[r][t][0], acc[r][t][1], acc[r][t][2], acc[r][t][3],
                            ah0, ah1, ah2, ah3, bh[t][0], bh[t][1]);
                    mma_f16(acc[r][t][0], acc[r][t][1], acc[r][t][2], acc[r][t][3],
                            al0, al1, al2, al3, bh[t][0], bh[t][1]);
                }
            }
        }
        __syncthreads();
        #pragma unroll
        for (int r = 0; r < 2; ++r) {
            int row0 = r * 16 + gid;
            int row1 = row0 + 8;
            #pragma unroll
            for (int t = 0; t < 6; ++t) {
                int col = nbase + t * 8 + 2 * tig;
                float b0v = __ldg(&bm2[col]);
                float b1v = __ldg(&bm2[col + 1]);
                sA[row0 * MXP + col]     = acc[r][t][0] + b0v;
                sA[row0 * MXP + col + 1] = acc[r][t][1] + b1v;
                sA[row1 * MXP + col]     = acc[r][t][2] + b0v;
                sA[row1 * MXP + col + 1] = acc[r][t][3] + b1v;
            }
        }
    }
    __syncthreads();

    for (int slot = tid; slot < 32 * HH; slot += 256) {
        int r = slot >> 7;
        int o = slot & 127;
        int n = n0 + r;
        if (n >= NN) break;
        float dq  = sA[r * MXP + o];
        float dms = sA[r * MXP + HH + o];
        float dqm = sA[r * MXP + 2 * HH + o];
        qout[n * HH + o] = g_qmid[n * HH + o] + dq + dqm * g_inner[n * HH + o];
        #pragma unroll
        for (int d = 0; d < 3; ++d) {
            int idx = n * 3 * HH + d * HH + o;
            muout[idx] = g_mumid[idx] + g_muw[idx] * dms;
        }
    }
}

// ---------------- launch ----------------
extern "C" void kernel_launch(void* const* d_in, const int* in_sizes, int n_in,
                              void* d_out, int out_size)
{
    const float* q   = (const float*)d_in[0];
    const float* mu  = (const float*)d_in[1];
    const int*   ei  = (const int*)d_in[2];
    const float* rbf = (const float*)d_in[3];
    const float* uv  = (const float*)d_in[4];
    const float* cut = (const float*)d_in[5];
    const float* Wi1 = (const float*)d_in[6];
    const float* bi1 = (const float*)d_in[7];
    const float* Wi2 = (const float*)d_in[8];
    const float* bi2 = (const float*)d_in[9];
    const float* Wf1 = (const float*)d_in[10];
    const float* bf1 = (const float*)d_in[11];
    const float* Wf2 = (const float*)d_in[12];
    const float* bf2 = (const float*)d_in[13];
    const float* Wv  = (const float*)d_in[14];
    const float* Wm1 = (const float*)d_in[15];
    const float* bm1 = (const float*)d_in[16];
    const float* Wm2 = (const float*)d_in[17];
    const float* bm2 = (const float*)d_in[18];

    float* qout  = (float*)d_out;
    float* muout = qout + (size_t)NN * HH;

    cudaFuncSetAttribute(k_node_mlp, cudaFuncAttributeMaxDynamicSharedMemorySize, NODE_SMEM);
    cudaFuncSetAttribute(k_equiv,    cudaFuncAttributeMaxDynamicSharedMemorySize, EQ_SMEM);
    cudaFuncSetAttribute(k_mix,      cudaFuncAttributeMaxDynamicSharedMemorySize, MIX_SMEM);

    // merged prologue: fp16 weight packs + count zeroing (one launch)
    k_prep<<<(SEG6 + 255) / 256, 256>>>(Wf2, Wi1, Wi2, Wv, Wm1, Wm2);
    // CSR build
    k_count<<<512, 256>>>(ei);
    k_scan<<<1, 1024>>>();
    k_fill<<<512, 256>>>(ei, uv);

    // dense stages
    k_node_mlp<<<(NN + 31) / 32, 256, NODE_SMEM>>>(q, bi1, bi2);
    k_edge_filter<<<NE / 64, 256>>>(rbf, cut, Wf1, bf1, bf2);

    // message aggregation (2 nodes/block)
    k_aggregate<<<(NN + 1) / 2, 128>>>(q, mu);

    // mixing
    k_equiv<<<(NN + 15) / 16, 256, EQ_SMEM>>>();
    k_mix<<<(NN + 31) / 32, 256, MIX_SMEM>>>(bm1, bm2, qout, muout);
}

// round 15
// speedup vs baseline: 1.6586x; 1.0891x over previous
#include <cuda_runtime.h>
#include <cuda_bf16.h>
#include <cuda_fp16.h>
#include <math.h>

#define NN 10000
#define NE 256000
#define HH 128
#define H2 256
#define H3 384
#define NR 20

typedef unsigned int u32;

// ---------------- scratch (static device globals; no allocation) ----------------
__device__ float  g_x[NN * H3];
__device__ __half g_filters[(size_t)NE * H3];
__device__ float4 g_uv4[NE];
__device__ int    g_src[NE];
__device__ int    g_epos[NE];
__device__ u32   g_bhp[(HH / 2) * H3];             // Wf2 fp16x2 k-pairs
__device__ u32   g_f1h[16 * HH];                   // Wf1 fp16x2 k-pairs (K padded to 32)
__device__ u32   g_i1h[(HH / 2) * H3];
__device__ u32   g_i2h[(H3 / 2) * H3];
__device__ u32   g_vch[(HH / 2) * H2];
__device__ u32   g_m1h[(H2 / 2) * H3];
__device__ u32   g_m2h[(H3 / 2) * H3];
__device__ float g_qmid[NN * HH];
__device__ float g_mumid[NN * 3 * HH];
__device__ float g_vnorm[NN * HH];
__device__ float g_inner[NN * HH];
__device__ float g_muw[NN * 3 * HH];
__device__ int   g_count[NN];
__device__ int   g_off[NN + 1];
__device__ int   g_cursor[NN];

__device__ __forceinline__ float silu_f(float x) {
    return x / (1.0f + __expf(-x));
}

__device__ __forceinline__ u32 pack_f16x2(float lo, float hi) {
    __half2 h = __floats2half2_rn(lo, hi);
    return *(u32*)&h;
}

__device__ __forceinline__ void mma_f16(float& c0, float& c1, float& c2, float& c3,
                                        u32 a0, u32 a1, u32 a2, u32 a3,
                                        u32 b0, u32 b1) {
    asm("mma.sync.aligned.m16n8k16.row.col.f32.f16.f16.f32 "
        "{%0,%1,%2,%3}, {%4,%5,%6,%7}, {%8,%9}, {%0,%1,%2,%3};"
        : "+f"(c0), "+f"(c1), "+f"(c2), "+f"(c3)
        : "r"(a0), "r"(a1), "r"(a2), "r"(a3), "r"(b0), "r"(b1));
}

__device__ __forceinline__ void ldsm_x4(u32& r0, u32& r1, u32& r2, u32& r3,
                                        const u32* p) {
    u32 addr = (u32)__cvta_generic_to_shared(p);
    asm volatile("ldmatrix.sync.aligned.m8n8.x4.shared.b16 {%0,%1,%2,%3}, [%4];"
                 : "=r"(r0), "=r"(r1), "=r"(r2), "=r"(r3) : "r"(addr));
}

__device__ __forceinline__ void split_a16(float2 f, u32& hi, u32& lo) {
    __half2 h = __floats2half2_rn(f.x, f.y);
    hi = *(u32*)&h;
    lo = pack_f16x2(f.x - __half2float(__low2half(h)),
                    f.y - __half2float(__high2half(h)));
}

__device__ __forceinline__ void split_pair_f16(float v0, float v1, u32& hi, u32& lo) {
    __half2 h = __floats2half2_rn(v0, v1);
    hi = *(u32*)&h;
    lo = pack_f16x2(v0 - __half2float(__low2half(h)),
                    v1 - __half2float(__high2half(h)));
}

// ---------------- merged prologue: fp16 weight packs + count zeroing ----------------
__device__ __forceinline__ void do_pack16(const float* __restrict__ W,
                                          u32* __restrict__ dst, int idx, int width) {
    int p = idx / width, col = idx % width;
    dst[idx] = pack_f16x2(W[(2 * p) * width + col], W[(2 * p + 1) * width + col]);
}

#define SEG0 24576
#define SEG1 49152
#define SEG2 122880
#define SEG3 139264
#define SEG4 188416
#define SEG5 262144
#define SEGW 264192          // Wf1 padded pack (16 x 128)
#define SEG7 274192          // count zero
__global__ void k_prep(const float* __restrict__ Wf2, const float* __restrict__ Wi1,
                       const float* __restrict__ Wi2, const float* __restrict__ Wv,
                       const float* __restrict__ Wm1, const float* __restrict__ Wm2,
                       const float* __restrict__ Wf1) {
    int i = blockIdx.x * blockDim.x + threadIdx.x;
    if (i < SEG0)       do_pack16(Wf2, g_bhp, i, H3);
    else if (i < SEG1)  do_pack16(Wi1, g_i1h, i - SEG0, H3);
    else if (i < SEG2)  do_pack16(Wi2, g_i2h, i - SEG1, H3);
    else if (i < SEG3)  do_pack16(Wv,  g_vch, i - SEG2, H2);
    else if (i < SEG4)  do_pack16(Wm1, g_m1h, i - SEG3, H3);
    else if (i < SEG5)  do_pack16(Wm2, g_m2h, i - SEG4, H3);
    else if (i < SEGW) {
        int j = i - SEG5;
        int p = j >> 7, col = j & 127;
        float w0 = (2 * p < NR)     ? Wf1[(2 * p) * HH + col]     : 0.f;
        float w1 = (2 * p + 1 < NR) ? Wf1[(2 * p + 1) * HH + col] : 0.f;
        g_f1h[j] = pack_f16x2(w0, w1);
    }
    else if (i < SEG7)  g_count[i - SEGW] = 0;
}

// ---------------- CSR build ----------------
__global__ void k_count(const int* __restrict__ ei) {
    for (int e = blockIdx.x * blockDim.x + threadIdx.x; e < NE;
         e += gridDim.x * blockDim.x)
        atomicAdd(&g_count[ei[e]], 1);
}

__global__ __launch_bounds__(1024) void k_scan() {
    __shared__ int wsum[32];
    int tid = threadIdx.x;
    const int CH = 10;
    int base = tid * CH;
    int vals[CH];
    int s = 0;
    #pragma unroll
    for (int j = 0; j < CH; ++j) {
        int idx = base + j;
        vals[j] = (idx < NN) ? g_count[idx] : 0;
        s += vals[j];
    }
    int lane = tid & 31, w = tid >> 5;
    int x = s;
    #pragma unroll
    for (int o = 1; o < 32; o <<= 1) {
        int v = __shfl_up_sync(0xFFFFFFFFu, x, o);
        if (lane >= o) x += v;
    }
    if (lane == 31) wsum[w] = x;
    __syncthreads();
    if (w == 0) {
        int y = wsum[lane];
        #pragma unroll
        for (int o = 1; o < 32; o <<= 1) {
            int v = __shfl_up_sync(0xFFFFFFFFu, y, o);
            if (lane >= o) y += v;
        }
        wsum[lane] = y;
    }
    __syncthreads();
    int run = x - s + (w > 0 ? wsum[w - 1] : 0);
    #pragma unroll
    for (int j = 0; j < CH; ++j) {
        int idx = base + j;
        if (idx < NN) {
            g_off[idx] = run;
            g_cursor[idx] = run;
            run += vals[j];
        }
    }
    if (tid == 1023) g_off[NN] = run;
}

__global__ void k_fill(const int* __restrict__ ei, const float* __restrict__ uv) {
    for (int e = blockIdx.x * blockDim.x + threadIdx.x; e < NE;
         e += gridDim.x * blockDim.x) {
        int t = ei[e];
        int pos = atomicAdd(&g_cursor[t], 1);
        g_epos[e] = pos;
        g_src[pos] = ei[NE + e];
        g_uv4[pos] = make_float4(uv[3 * e], uv[3 * e + 1], uv[3 * e + 2], 0.f);
    }
}

// ---------------- node inter MLP via fp16 2-term mma (R13 proven) ----------------
#define SQP 132
#define SH2P 388
#define NODE_SMEM ((32 * SQP + 32 * SH2P) * 4)
__global__ __launch_bounds__(256) void k_node_mlp(
    const float* __restrict__ q,
    const float* __restrict__ b1, const float* __restrict__ b2)
{
    extern __shared__ float smn[];
    float* sq = smn;
    float* sh = smn + 32 * SQP;
    int tid = threadIdx.x;
    int n0 = blockIdx.x * 32;

    for (int i = tid; i < 32 * HH; i += 256) {
        int r = i >> 7, c = i & 127;
        int n = n0 + r;
        sq[r * SQP + c] = (n < NN) ? q[n * HH + c] : 0.f;
    }
    __syncthreads();

    int wid  = tid >> 5;
    int lane = tid & 31;
    int gid  = lane >> 2;
    int tig  = lane & 3;
    int nbase = wid * 48;

    {
        float acc[2][6][4];
        #pragma unroll
        for (int r = 0; r < 2; ++r)
            #pragma unroll
            for (int t = 0; t < 6; ++t)
                #pragma unroll
                for (int c = 0; c < 4; ++c) acc[r][t][c] = 0.f;

        #pragma unroll 1
        for (int k0 = 0; k0 < HH; k0 += 16) {
            int kp = k0 >> 1;
            u32 bh[6][2];
            #pragma unroll
            for (int t = 0; t < 6; ++t) {
                int col = nbase + t * 8 + gid;
                bh[t][0] = __ldg(&g_i1h[(kp + tig) * H3 + col]);
                bh[t][1] = __ldg(&g_i1h[(kp + 4 + tig) * H3 + col]);
            }
            #pragma unroll
            for (int r = 0; r < 2; ++r) {
                int rb = r * 16;
                float2 f0 = *(const float2*)&sq[(rb + gid)     * SQP + k0 + 2 * tig];
                float2 f1 = *(const float2*)&sq[(rb + gid + 8) * SQP + k0 + 2 * tig];
                float2 f2 = *(const float2*)&sq[(rb + gid)     * SQP + k0 + 8 + 2 * tig];
                float2 f3 = *(const float2*)&sq[(rb + gid + 8) * SQP + k0 + 8 + 2 * tig];
                u32 ah0, al0, ah1, al1, ah2, al2, ah3, al3;
                split_a16(f0, ah0, al0); split_a16(f1, ah1, al1);
                split_a16(f2, ah2, al2); split_a16(f3, ah3, al3);
                #pragma unroll
                for (int t = 0; t < 6; ++t) {
                    mma_f16(acc[r][t][0], acc[r][t][1], acc[r][t][2], acc[r][t][3],
                            ah0, ah1, ah2, ah3, bh[t][0], bh[t][1]);
                    mma_f16(acc[r][t][0], acc[r][t][1], acc[r][t][2], acc[r][t][3],
                            al0, al1, al2, al3, bh[t][0], bh[t][1]);
                }
            }
        }
        #pragma unroll
        for (int r = 0; r < 2; ++r) {
            int row0 = r * 16 + gid;
            int row1 = row0 + 8;
            #pragma unroll
            for (int t = 0; t < 6; ++t) {
                int col = nbase + t * 8 + 2 * tig;
                float b0v = __ldg(&b1[col]);
                float b1v = __ldg(&b1[col + 1]);
                sh[row0 * SH2P + col]     = silu_f(acc[r][t][0] + b0v);
                sh[row0 * SH2P + col + 1] = silu_f(acc[r][t][1] + b1v);
                sh[row1 * SH2P + col]     = silu_f(acc[r][t][2] + b0v);
                sh[row1 * SH2P + col + 1] = silu_f(acc[r][t][3] + b1v);
            }
        }
    }
    __syncthreads();

    {
        float acc[2][6][4];
        #pragma unroll
        for (int r = 0; r < 2; ++r)
            #pragma unroll
            for (int t = 0; t < 6; ++t)
                #pragma unroll
                for (int c = 0; c < 4; ++c) acc[r][t][c] = 0.f;

        #pragma unroll 1
        for (int k0 = 0; k0 < H3; k0 += 16) {
            int kp = k0 >> 1;
            u32 bh[6][2];
            #pragma unroll
            for (int t = 0; t < 6; ++t) {
                int col = nbase + t * 8 + gid;
                bh[t][0] = __ldg(&g_i2h[(kp + tig) * H3 + col]);
                bh[t][1] = __ldg(&g_i2h[(kp + 4 + tig) * H3 + col]);
            }
            #pragma unroll
            for (int r = 0; r < 2; ++r) {
                int rb = r * 16;
                float2 f0 = *(const float2*)&sh[(rb + gid)     * SH2P + k0 + 2 * tig];
                float2 f1 = *(const float2*)&sh[(rb + gid + 8) * SH2P + k0 + 2 * tig];
                float2 f2 = *(const float2*)&sh[(rb + gid)     * SH2P + k0 + 8 + 2 * tig];
                float2 f3 = *(const float2*)&sh[(rb + gid + 8) * SH2P + k0 + 8 + 2 * tig];
                u32 ah0, al0, ah1, al1, ah2, al2, ah3, al3;
                split_a16(f0, ah0, al0); split_a16(f1, ah1, al1);
                split_a16(f2, ah2, al2); split_a16(f3, ah3, al3);
                #pragma unroll
                for (int t = 0; t < 6; ++t) {
                    mma_f16(acc[r][t][0], acc[r][t][1], acc[r][t][2], acc[r][t][3],
                            ah0, ah1, ah2, ah3, bh[t][0], bh[t][1]);
                    mma_f16(acc[r][t][0], acc[r][t][1], acc[r][t][2], acc[r][t][3],
                            al0, al1, al2, al3, bh[t][0], bh[t][1]);
                }
            }
        }
        #pragma unroll
        for (int r = 0; r < 2; ++r) {
            int row0 = r * 16 + gid;
            int row1 = row0 + 8;
            #pragma unroll
            for (int t = 0; t < 6; ++t) {
                int col = nbase + t * 8 + 2 * tig;
                float b0v = __ldg(&b2[col]);
                float b1v = __ldg(&b2[col + 1]);
                if (n0 + row0 < NN)
                    *(float2*)&g_x[(size_t)(n0 + row0) * H3 + col] =
                        make_float2(acc[r][t][0] + b0v, acc[r][t][1] + b1v);
                if (n0 + row1 < NN)
                    *(float2*)&g_x[(size_t)(n0 + row1) * H3 + col] =
                        make_float2(acc[r][t][2] + b0v, acc[r][t][3] + b1v);
            }
        }
    }
}

// ---------------- edge filter MLP: both phases fp16 2-term mma + ldmatrix ----------------
#define KPS 68
#define RKP 20
__global__ __launch_bounds__(256) void k_edge_filter(
    const float* __restrict__ rbf, const float* __restrict__ cut,
    const float* __restrict__ bf1, const float* __restrict__ bf2)
{
    __shared__ float scut[64];
    __shared__ int   spos[64];
    __shared__ u32 srbh[64 * RKP];   // rbf hi, [row][kp], K padded to 32
    __shared__ u32 srbl[64 * RKP];   // rbf lo
    __shared__ u32 shiT[64 * KPS];   // hidden hi
    __shared__ u32 sloT[64 * KPS];   // hidden lo
    int tid = threadIdx.x;
    int e0 = blockIdx.x * 64;

    // load rbf, split to fp16 hi/lo k-pairs (pairs 10..15 zero)
    for (int i = tid; i < 64 * 16; i += 256) {
        int r = i >> 4, kp = i & 15;
        float v0 = 0.f, v1 = 0.f;
        if (kp < 10) {
            v0 = rbf[(e0 + r) * NR + 2 * kp];
            v1 = rbf[(e0 + r) * NR + 2 * kp + 1];
        }
        u32 h, l;
        split_pair_f16(v0, v1, h, l);
        srbh[r * RKP + kp] = h;
        srbl[r * RKP + kp] = l;
    }
    if (tid < 64) {
        scut[tid] = cut[e0 + tid];
        spos[tid] = g_epos[e0 + tid];
    }
    __syncthreads();

    int wid  = tid >> 5;
    int lane = tid & 31;
    int gid  = lane >> 2;
    int tig  = lane & 3;

    // ---- phase 1: hidden[64][128] = silu(rbf @ Wf1 + bf1), K=32 padded ----
    {
        int rb1 = (wid >> 1) * 16;      // 4 row tiles
        int cb  = (wid & 1) * 64;       // 2 col halves, 8 n-tiles each
        float a1[8][4];
        #pragma unroll
        for (int t = 0; t < 8; ++t)
            #pragma unroll
            for (int c = 0; c < 4; ++c) a1[t][c] = 0.f;

        #pragma unroll
        for (int ks = 0; ks < 2; ++ks) {
            int kp = ks * 8;
            u32 bh1[8][2];
            #pragma unroll
            for (int t = 0; t < 8; ++t) {
                int col = cb + t * 8 + gid;
                bh1[t][0] = __ldg(&g_f1h[(kp + tig) * HH + col]);
                bh1[t][1] = __ldg(&g_f1h[(kp + 4 + tig) * HH + col]);
            }
            int lrow = rb1 + (lane & 15);
            int loff = lrow * RKP + kp + ((lane >> 4) << 2);
            u32 ah0, ah1, ah2, ah3, al0, al1, al2, al3;
            ldsm_x4(ah0, ah1, ah2, ah3, &srbh[loff]);
            ldsm_x4(al0, al1, al2, al3, &srbl[loff]);
            #pragma unroll
            for (int t = 0; t < 8; ++t) {
                mma_f16(a1[t][0], a1[t][1], a1[t][2], a1[t][3],
                        ah0, ah1, ah2, ah3, bh1[t][0], bh1[t][1]);
                mma_f16(a1[t][0], a1[t][1], a1[t][2], a1[t][3],
                        al0, al1, al2, al3, bh1[t][0], bh1[t][1]);
            }
        }
        #pragma unroll
        for (int t = 0; t < 8; ++t) {
            int col = cb + t * 8 + 2 * tig;
            int kpo = col >> 1;
            float b0v = __ldg(&bf1[col]);
            float b1v = __ldg(&bf1[col + 1]);
            int row0 = rb1 + gid;
            int row1 = row0 + 8;
            u32 h, l;
            split_pair_f16(silu_f(a1[t][0] + b0v), silu_f(a1[t][1] + b1v), h, l);
            shiT[row0 * KPS + kpo] = h;
            sloT[row0 * KPS + kpo] = l;
            split_pair_f16(silu_f(a1[t][2] + b0v), silu_f(a1[t][3] + b1v), h, l);
            shiT[row1 * KPS + kpo] = h;
            sloT[row1 * KPS + kpo] = l;
        }
    }
    __syncthreads();

    // ---- phase 2: filters[64][384] = hidden @ Wf2, fp16 2-term, ldmatrix A ----
    int nbase = wid * 48;

    float acc[4][6][4];
    #pragma unroll
    for (int r = 0; r < 4; ++r)
        #pragma unroll
        for (int t = 0; t < 6; ++t)
            #pragma unroll
            for (int c = 0; c < 4; ++c) acc[r][t][c] = 0.f;

    #pragma unroll 1
    for (int k0 = 0; k0 < HH; k0 += 16) {
        int kp = k0 >> 1;
        u32 bh[6][2];
        #pragma unroll
        for (int t = 0; t < 6; ++t) {
            int col = nbase + t * 8 + gid;
            bh[t][0] = __ldg(&g_bhp[(kp + tig) * H3 + col]);
            bh[t][1] = __ldg(&g_bhp[(kp + 4 + tig) * H3 + col]);
        }
        #pragma unroll
        for (int r = 0; r < 4; ++r) {
            int rb = r * 16;
            int lrow = rb + (lane & 15);
            int loff = lrow * KPS + kp + ((lane >> 4) << 2);
            u32 ah0, ah1, ah2, ah3, al0, al1, al2, al3;
            ldsm_x4(ah0, ah1, ah2, ah3, &shiT[loff]);
            ldsm_x4(al0, al1, al2, al3, &sloT[loff]);
            #pragma unroll
            for (int t = 0; t < 6; ++t) {
                mma_f16(acc[r][t][0], acc[r][t][1], acc[r][t][2], acc[r][t][3],
                        ah0, ah1, ah2, ah3, bh[t][0], bh[t][1]);
                mma_f16(acc[r][t][0], acc[r][t][1], acc[r][t][2], acc[r][t][3],
                        al0, al1, al2, al3, bh[t][0], bh[t][1]);
            }
        }
    }

    #pragma unroll
    for (int r = 0; r < 4; ++r) {
        int row0 = r * 16 + gid;
        int row1 = row0 + 8;
        float c0v = scut[row0];
        float c1v = scut[row1];
        size_t p0 = (size_t)spos[row0] * H3;
        size_t p1 = (size_t)spos[row1] * H3;
        #pragma unroll
        for (int t = 0; t < 6; ++t) {
            int col = nbase + t * 8 + 2 * tig;
            float b0v = bf2[col];
            float b1v = bf2[col + 1];
            __half2 v0 = __floats2half2_rn((acc[r][t][0] + b0v) * c0v,
                                           (acc[r][t][1] + b1v) * c0v);
            __half2 v1 = __floats2half2_rn((acc[r][t][2] + b0v) * c1v,
                                           (acc[r][t][3] + b1v) * c1v);
            *(__half2*)&g_filters[p0 + col] = v0;
            *(__half2*)&g_filters[p1 + col] = v1;
        }
    }
}

// ---------------- pull aggregation: vectorized (R14 proven) ----------------
__global__ __launch_bounds__(128) void k_aggregate(
    const float* __restrict__ q, const float* __restrict__ mu)
{
    int node = blockIdx.x * 2 + (threadIdx.x >> 6);
    int hp = threadIdx.x & 63;
    if (node >= NN) return;
    int beg = g_off[node], end = g_off[node + 1];
    float2 qa = {0.f, 0.f};
    float2 m0 = {0.f, 0.f}, m1 = {0.f, 0.f}, m2 = {0.f, 0.f};
    for (int i = beg; i < end; ++i) {
        int s = g_src[i];
        const __half2* f = (const __half2*)&g_filters[(size_t)i * H3];
        float2 fq = __half22float2(f[hp]);
        float2 fr = __half22float2(f[64 + hp]);
        float2 fm = __half22float2(f[128 + hp]);
        const float2* xs = (const float2*)&g_x[s * H3];
        float2 x0 = xs[hp], x1 = xs[64 + hp], x2 = xs[128 + hp];
        float4 u = g_uv4[i];
        const float2* ms = (const float2*)&mu[s * 3 * HH];
        float2 u0 = ms[hp], u1v = ms[64 + hp], u2v = ms[128 + hp];
        float xrx = x1.x * fr.x, xry = x1.y * fr.y;
        float xmx = x2.x * fm.x, xmy = x2.y * fm.y;
        qa.x += x0.x * fq.x;
        qa.y += x0.y * fq.y;
        m0.x = fmaf(u.x, xrx, fmaf(u0.x,  xmx, m0.x));
        m0.y = fmaf(u.x, xry, fmaf(u0.y,  xmy, m0.y));
        m1.x = fmaf(u.y, xrx, fmaf(u1v.x, xmx, m1.x));
        m1.y = fmaf(u.y, xry, fmaf(u1v.y, xmy, m1.y));
        m2.x = fmaf(u.z, xrx, fmaf(u2v.x, xmx, m2.x));
        m2.y = fmaf(u.z, xry, fmaf(u2v.y, xmy, m2.y));
    }
    {
        float2 qv = *(const float2*)&q[node * HH + 2 * hp];
        *(float2*)&g_qmid[node * HH + 2 * hp] = make_float2(qv.x + qa.x, qv.y + qa.y);
        const float2* mb = (const float2*)&mu[node * 3 * HH];
        float2 b0 = mb[hp], b1 = mb[64 + hp], b2 = mb[128 + hp];
        float2* out = (float2*)&g_mumid[node * 3 * HH];
        out[hp]       = make_float2(b0.x + m0.x, b0.y + m0.y);
        out[64 + hp]  = make_float2(b1.x + m1.x, b1.y + m1.y);
        out[128 + hp] = make_float2(b2.x + m2.x, b2.y + m2.y);
    }
}

// ---------------- equivariant linear via fp16 2-term mma (R13 proven) ----------------
#define EMP 132
#define EOP 260
#define EQ_SMEM ((48 * EMP + 48 * EOP) * 4)
__global__ __launch_bounds__(256) void k_equiv()
{
    extern __shared__ float sme[];
    float* smu  = sme;
    float* sout = sme + 48 * EMP;
    int tid = threadIdx.x;
    int n0 = blockIdx.x * 16;
    int row_base = n0 * 3;

    for (int i = tid; i < 48 * HH; i += 256) {
        int r = i >> 7, c = i & 127;
        int grow = row_base + r;
        smu[r * EMP + c] = (grow < NN * 3) ? g_mumid[grow * HH + c] : 0.f;
    }
    __syncthreads();

    int wid  = tid >> 5;
    int lane = tid & 31;
    int gid  = lane >> 2;
    int tig  = lane & 3;
    int nbase = wid * 32;

    float acc[3][4][4];
    #pragma unroll
    for (int r = 0; r < 3; ++r)
        #pragma unroll
        for (int t = 0; t < 4; ++t)
            #pragma unroll
            for (int c = 0; c < 4; ++c) acc[r][t][c] = 0.f;

    #pragma unroll 1
    for (int k0 = 0; k0 < HH; k0 += 16) {
        int kp = k0 >> 1;
        u32 bh[4][2];
        #pragma unroll
        for (int t = 0; t < 4; ++t) {
            int col = nbase + t * 8 + gid;
            bh[t][0] = __ldg(&g_vch[(kp + tig) * H2 + col]);
            bh[t][1] = __ldg(&g_vch[(kp + 4 + tig) * H2 + col]);
        }
        #pragma unroll
        for (int r = 0; r < 3; ++r) {
            int rb = r * 16;
            float2 f0 = *(const float2*)&smu[(rb + gid)     * EMP + k0 + 2 * tig];
            float2 f1 = *(const float2*)&smu[(rb + gid + 8) * EMP + k0 + 2 * tig];
            float2 f2 = *(const float2*)&smu[(rb + gid)     * EMP + k0 + 8 + 2 * tig];
            float2 f3 = *(const float2*)&smu[(rb + gid + 8) * EMP + k0 + 8 + 2 * tig];
            u32 ah0, al0, ah1, al1, ah2, al2, ah3, al3;
            split_a16(f0, ah0, al0); split_a16(f1, ah1, al1);
            split_a16(f2, ah2, al2); split_a16(f3, ah3, al3);
            #pragma unroll
            for (int t = 0; t < 4; ++t) {
                mma_f16(acc[r][t][0], acc[r][t][1], acc[r][t][2], acc[r][t][3],
                        ah0, ah1, ah2, ah3, bh[t][0], bh[t][1]);
                mma_f16(acc[r][t][0], acc[r][t][1], acc[r][t][2], acc[r][t][3],
                        al0, al1, al2, al3, bh[t][0], bh[t][1]);
            }
        }
    }

    #pragma unroll
    for (int r = 0; r < 3; ++r) {
        int row0 = r * 16 + gid;
        int row1 = row0 + 8;
        #pragma unroll
        for (int t = 0; t < 4; ++t) {
            int col = nbase + t * 8 + 2 * tig;
            sout[row0 * EOP + col]     = acc[r][t][0];
            sout[row0 * EOP + col + 1] = acc[r][t][1];
            sout[row1 * EOP + col]     = acc[r][t][2];
            sout[row1 * EOP + col + 1] = acc[r][t][3];
        }
    }
    __syncthreads();

    for (int slot = tid; slot < 16 * HH; slot += 256) {
        int r = slot >> 7;
        int o = slot & 127;
        int n = n0 + r;
        if (n >= NN) break;
        float v0 = sout[(r * 3 + 0) * EOP + o];
        float v1 = sout[(r * 3 + 1) * EOP + o];
        float v2 = sout[(r * 3 + 2) * EOP + o];
        float w0 = sout[(r * 3 + 0) * EOP + HH + o];
        float w1 = sout[(r * 3 + 1) * EOP + HH + o];
        float w2 = sout[(r * 3 + 2) * EOP + HH + o];
        g_vnorm[n * HH + o] = sqrtf(v0 * v0 + v1 * v1 + v2 * v2 + 1e-8f);
        g_inner[n * HH + o] = v0 * w0 + v1 * w1 + v2 * w2;
        g_muw[n * 3 * HH + o]          = w0;
        g_muw[n * 3 * HH + HH + o]     = w1;
        g_muw[n * 3 * HH + 2 * HH + o] = w2;
    }
}

// ---------------- scalar mix MLP via fp16 2-term mma + final update (R13 proven) ----------------
#define MXP 388
#define MIX_SMEM ((32 * MXP * 2) * 4)
__global__ __launch_bounds__(256) void k_mix(
    const float* __restrict__ bm1, const float* __restrict__ bm2,
    float* __restrict__ qout, float* __restrict__ muout)
{
    extern __shared__ float smx[];
    float* sA = smx;
    float* sB = smx + 32 * MXP;
    int tid = threadIdx.x;
    int n0 = blockIdx.x * 32;

    for (int i = tid; i < 32 * H2; i += 256) {
        int r = i >> 8, c = i & 255;
        int n = n0 + r;
        float v = 0.f;
        if (n < NN) v = (c < HH) ? g_qmid[n * HH + c] : g_vnorm[n * HH + (c - HH)];
        sA[r * MXP + c] = v;
    }
    __syncthreads();

    int wid  = tid >> 5;
    int lane = tid & 31;
    int gid  = lane >> 2;
    int tig  = lane & 3;
    int nbase = wid * 48;

    {
        float acc[2][6][4];
        #pragma unroll
        for (int r = 0; r < 2; ++r)
            #pragma unroll
            for (int t = 0; t < 6; ++t)
                #pragma unroll
                for (int c = 0; c < 4; ++c) acc[r][t][c] = 0.f;

        #pragma unroll 1
        for (int k0 = 0; k0 < H2; k0 += 16) {
            int kp = k0 >> 1;
            u32 bh[6][2];
            #pragma unroll
            for (int t = 0; t < 6; ++t) {
                int col = nbase + t * 8 + gid;
                bh[t][0] = __ldg(&g_m1h[(kp + tig) * H3 + col]);
                bh[t][1] = __ldg(&g_m1h[(kp + 4 + tig) * H3 + col]);
            }
            #pragma unroll
            for (int r = 0; r < 2; ++r) {
                int rb = r * 16;
                float2 f0 = *(const float2*)&sA[(rb + gid)     * MXP + k0 + 2 * tig];
                float2 f1 = *(const float2*)&sA[(rb + gid + 8) * MXP + k0 + 2 * tig];
                float2 f2 = *(const float2*)&sA[(rb + gid)     * MXP + k0 + 8 + 2 * tig];
                float2 f3 = *(const float2*)&sA[(rb + gid + 8) * MXP + k0 + 8 + 2 * tig];
                u32 ah0, al0, ah1, al1, ah2, al2, ah3, al3;
                split_a16(f0, ah0, al0); split_a16(f1, ah1, al1);
                split_a16(f2, ah2, al2); split_a16(f3, ah3, al3);
                #pragma unroll
                for (int t = 0; t < 6; ++t) {
                    mma_f16(acc[r][t][0], acc[r][t][1], acc[r][t][2], acc[r][t][3],
                            ah0, ah1, ah2, ah3, bh[t][0], bh[t][1]);
                    mma_f16(acc[r][t][0], acc[r][t][1], acc[r][t][2], acc[r][t][3],
                            al0, al1, al2, al3, bh[t][0], bh[t][1]);
                }
            }
        }
        #pragma unroll
        for (int r = 0; r < 2; ++r) {
            int row0 = r * 16 + gid;
            int row1 = row0 + 8;
            #pragma unroll
            for (int t = 0; t < 6; ++t) {
                int col = nbase + t * 8 + 2 * tig;
                float b0v = __ldg(&bm1[col]);
                float b1v = __ldg(&bm1[col + 1]);
                sB[row0 * MXP + col]     = silu_f(acc[r][t][0] + b0v);
                sB[row0 * MXP + col + 1] = silu_f(acc[r][t][1] + b1v);
                sB[row1 * MXP + col]     = silu_f(acc[r][t][2] + b0v);
                sB[row1 * MXP + col + 1] = silu_f(acc[r][t][3] + b1v);
            }
        }
    }
    __syncthreads();

    {
        float acc[2][6][4];
        #pragma unroll
        for (int r = 0; r < 2; ++r)
            #pragma unroll
            for (int t = 0; t < 6; ++t)
                #pragma unroll
                for (int c = 0; c < 4; ++c) acc[r][t][c] = 0.f;

        #pragma unroll 1
        for (int k0 = 0; k0 < H3; k0 += 16) {
            int kp = k0 >> 1;
            u32 bh[6][2];
            #pragma unroll
            for (int t = 0; t < 6; ++t) {
                int col = nbase + t * 8 + gid;
                bh[t][0] = __ldg(&g_m2h[(kp + tig) * H3 + col]);
                bh[t][1] = __ldg(&g_m2h[(kp + 4 + tig) * H3 + col]);
            }
            #pragma unroll
            for (int r = 0; r < 2; ++r) {
                int rb = r * 16;
                float2 f0 = *(const float2*)&sB[(rb + gid)     * MXP + k0 + 2 * tig];
                float2 f1 = *(const float2*)&sB[(rb + gid + 8) * MXP + k0 + 2 * tig];
                float2 f2 = *(const float2*)&sB[(rb + gid)     * MXP + k0 + 8 + 2 * tig];
                float2 f3 = *(const float2*)&sB[(rb + gid + 8) * MXP + k0 + 8 + 2 * tig];
                u32 ah0, al0, ah1, al1, ah2, al2, ah3, al3;
                split_a16(f0, ah0, al0); split_a16(f1, ah1, al1);
                split_a16(f2, ah2, al2); split_a16(f3, ah3, al3);
                #pragma unroll
                for (int t = 0; t < 6; ++t) {
                    mma_f16(acc[r][t][0], acc[r][t][1], acc[r][t][2], acc[r][t][3],
                            ah0, ah1, ah2, ah3, bh[t][0], bh[t][1]);
                    mma_f16(acc[r][t][0], acc[r][t][1], acc[r][t][2], acc[r][t][3],
                            al0, al1, al2, al3, bh[t][0], bh[t][1]);
                }
            }
        }
        __syncthreads();
        #pragma unroll
        for (int r = 0; r < 2; ++r) {
            int row0 = r * 16 + gid;
            int row1 = row0 + 8;
            #pragma unroll
            for (int t = 0; t < 6; ++t) {
                int col = nbase + t * 8 + 2 * tig;
                float b0v = __ldg(&bm2[col]);
                float b1v = __ldg(&bm2[col + 1]);
                sA[row0 * MXP + col]     = acc[r][t][0] + b0v;
                sA[row0 * MXP + col + 1] = acc[r][t][1] + b1v;
                sA[row1 * MXP + col]     = acc[r][t][2] + b0v;
                sA[row1 * MXP + col + 1] = acc[r][t][3] + b1v;
            }
        }
    }
    __syncthreads();

    for (int slot = tid; slot < 32 * HH; slot += 256) {
        int r = slot >> 7;
        int o = slot & 127;
        int n = n0 + r;
        if (n >= NN) break;
        float dq  = sA[r * MXP + o];
        float dms = sA[r * MXP + HH + o];
        float dqm = sA[r * MXP + 2 * HH + o];
        qout[n * HH + o] = g_qmid[n * HH + o] + dq + dqm * g_inner[n * HH + o];
        #pragma unroll
        for (int d = 0; d < 3; ++d) {
            int idx = n * 3 * HH + d * HH + o;
            muout[idx] = g_mumid[idx] + g_muw[idx] * dms;
        }
    }
}

// ---------------- launch ----------------
extern "C" void kernel_launch(void* const* d_in, const int* in_sizes, int n_in,
                              void* d_out, int out_size)
{
    const float* q   = (const float*)d_in[0];
    const float* mu  = (const float*)d_in[1];
    const int*   ei  = (const int*)d_in[2];
    const float* rbf = (const float*)d_in[3];
    const float* uv  = (const float*)d_in[4];
    const float* cut = (const float*)d_in[5];
    const float* Wi1 = (const float*)d_in[6];
    const float* bi1 = (const float*)d_in[7];
    const float* Wi2 = (const float*)d_in[8];
    const float* bi2 = (const float*)d_in[9];
    const float* Wf1 = (const float*)d_in[10];
    const float* bf1 = (const float*)d_in[11];
    const float* Wf2 = (const float*)d_in[12];
    const float* bf2 = (const float*)d_in[13];
    const float* Wv  = (const float*)d_in[14];
    const float* Wm1 = (const float*)d_in[15];
    const float* bm1 = (const float*)d_in[16];
    const float* Wm2 = (const float*)d_in[17];
    const float* bm2 = (const float*)d_in[18];

    float* qout  = (float*)d_out;
    float* muout = qout + (size_t)NN * HH;

    cudaFuncSetAttribute(k_node_mlp, cudaFuncAttributeMaxDynamicSharedMemorySize, NODE_SMEM);
    cudaFuncSetAttribute(k_equiv,    cudaFuncAttributeMaxDynamicSharedMemorySize, EQ_SMEM);
    cudaFuncSetAttribute(k_mix,      cudaFuncAttributeMaxDynamicSharedMemorySize, MIX_SMEM);

    // merged prologue: fp16 weight packs + count zeroing (one launch)
    k_prep<<<(SEG7 + 255) / 256, 256>>>(Wf2, Wi1, Wi2, Wv, Wm1, Wm2, Wf1);
    // CSR build
    k_count<<<512, 256>>>(ei);
    k_scan<<<1, 1024>>>();
    k_fill<<<512, 256>>>(ei, uv);

    // dense stages
    k_node_mlp<<<(NN + 31) / 32, 256, NODE_SMEM>>>(q, bi1, bi2);
    k_edge_filter<<<NE / 64, 256>>>(rbf, cut, bf1, bf2);

    // message aggregation (2 nodes/block)
    k_aggregate<<<(NN + 1) / 2, 128>>>(q, mu);

    // mixing
    k_equiv<<<(NN + 15) / 16, 256, EQ_SMEM>>>();
    k_mix<<<(NN + 31) / 32, 256, MIX_SMEM>>>(bm1, bm2, qout, muout);
}

// round 16
// speedup vs baseline: 1.7910x; 1.0799x over previous
#include <cuda_runtime.h>
#include <cuda_bf16.h>
#include <cuda_fp16.h>
#include <math.h>

#define NN 10000
#define NE 256000
#define HH 128
#define H2 256
#define H3 384
#define NR 20

typedef unsigned int u32;

// ---------------- scratch (static device globals; no allocation) ----------------
__device__ float  g_x[NN * H3];
__device__ __half g_filters[(size_t)NE * H3];
__device__ float4 g_uv4[NE];
__device__ int    g_src[NE];
__device__ int    g_epos[NE];
__device__ u32   g_bhp[(HH / 2) * H3];
__device__ u32   g_f1h[16 * HH];
__device__ u32   g_i1h[(HH / 2) * H3];
__device__ u32   g_i2h[(H3 / 2) * H3];
__device__ u32   g_vch[(HH / 2) * H2];
__device__ u32   g_m1h[(H2 / 2) * H3];
__device__ u32   g_m2h[(H3 / 2) * H3];
__device__ float g_qmid[NN * HH];
__device__ float g_mumid[NN * 3 * HH];
__device__ float g_vnorm[NN * HH];
__device__ float g_inner[NN * HH];
__device__ float g_muw[NN * 3 * HH];
__device__ int   g_count[NN];
__device__ int   g_off[NN + 1];
__device__ int   g_cursor[NN];

__device__ __forceinline__ float silu_f(float x) {
    return x / (1.0f + __expf(-x));
}

__device__ __forceinline__ u32 pack_f16x2(float lo, float hi) {
    __half2 h = __floats2half2_rn(lo, hi);
    return *(u32*)&h;
}

__device__ __forceinline__ void mma_f16(float& c0, float& c1, float& c2, float& c3,
                                        u32 a0, u32 a1, u32 a2, u32 a3,
                                        u32 b0, u32 b1) {
    asm("mma.sync.aligned.m16n8k16.row.col.f32.f16.f16.f32 "
        "{%0,%1,%2,%3}, {%4,%5,%6,%7}, {%8,%9}, {%0,%1,%2,%3};"
        : "+f"(c0), "+f"(c1), "+f"(c2), "+f"(c3)
        : "r"(a0), "r"(a1), "r"(a2), "r"(a3), "r"(b0), "r"(b1));
}

__device__ __forceinline__ void ldsm_x4(u32& r0, u32& r1, u32& r2, u32& r3,
                                        const u32* p) {
    u32 addr = (u32)__cvta_generic_to_shared(p);
    asm volatile("ldmatrix.sync.aligned.m8n8.x4.shared.b16 {%0,%1,%2,%3}, [%4];"
                 : "=r"(r0), "=r"(r1), "=r"(r2), "=r"(r3) : "r"(addr));
}

__device__ __forceinline__ void split_pair_f16(float v0, float v1, u32& hi, u32& lo) {
    __half2 h = __floats2half2_rn(v0, v1);
    hi = *(u32*)&h;
    lo = pack_f16x2(v0 - __half2float(__low2half(h)),
                    v1 - __half2float(__high2half(h)));
}

// ---------------- merged prologue ----------------
__device__ __forceinline__ void do_pack16(const float* __restrict__ W,
                                          u32* __restrict__ dst, int idx, int width) {
    int p = idx / width, col = idx % width;
    dst[idx] = pack_f16x2(W[(2 * p) * width + col], W[(2 * p + 1) * width + col]);
}

#define SEG0 24576
#define SEG1 49152
#define SEG2 122880
#define SEG3 139264
#define SEG4 188416
#define SEG5 262144
#define SEGW 264192
#define SEG7 274192
__global__ void k_prep(const float* __restrict__ Wf2, const float* __restrict__ Wi1,
                       const float* __restrict__ Wi2, const float* __restrict__ Wv,
                       const float* __restrict__ Wm1, const float* __restrict__ Wm2,
                       const float* __restrict__ Wf1) {
    int i = blockIdx.x * blockDim.x + threadIdx.x;
    if (i < SEG0)       do_pack16(Wf2, g_bhp, i, H3);
    else if (i < SEG1)  do_pack16(Wi1, g_i1h, i - SEG0, H3);
    else if (i < SEG2)  do_pack16(Wi2, g_i2h, i - SEG1, H3);
    else if (i < SEG3)  do_pack16(Wv,  g_vch, i - SEG2, H2);
    else if (i < SEG4)  do_pack16(Wm1, g_m1h, i - SEG3, H3);
    else if (i < SEG5)  do_pack16(Wm2, g_m2h, i - SEG4, H3);
    else if (i < SEGW) {
        int j = i - SEG5;
        int p = j >> 7, col = j & 127;
        float w0 = (2 * p < NR)     ? Wf1[(2 * p) * HH + col]     : 0.f;
        float w1 = (2 * p + 1 < NR) ? Wf1[(2 * p + 1) * HH + col] : 0.f;
        g_f1h[j] = pack_f16x2(w0, w1);
    }
    else if (i < SEG7)  g_count[i - SEGW] = 0;
}

// ---------------- CSR build ----------------
__global__ void k_count(const int* __restrict__ ei) {
    for (int e = blockIdx.x * blockDim.x + threadIdx.x; e < NE;
         e += gridDim.x * blockDim.x)
        atomicAdd(&g_count[ei[e]], 1);
}

__global__ __launch_bounds__(1024) void k_scan() {
    __shared__ int wsum[32];
    int tid = threadIdx.x;
    const int CH = 10;
    int base = tid * CH;
    int vals[CH];
    int s = 0;
    #pragma unroll
    for (int j = 0; j < CH; ++j) {
        int idx = base + j;
        vals[j] = (idx < NN) ? g_count[idx] : 0;
        s += vals[j];
    }
    int lane = tid & 31, w = tid >> 5;
    int x = s;
    #pragma unroll
    for (int o = 1; o < 32; o <<= 1) {
        int v = __shfl_up_sync(0xFFFFFFFFu, x, o);
        if (lane >= o) x += v;
    }
    if (lane == 31) wsum[w] = x;
    __syncthreads();
    if (w == 0) {
        int y = wsum[lane];
        #pragma unroll
        for (int o = 1; o < 32; o <<= 1) {
            int v = __shfl_up_sync(0xFFFFFFFFu, y, o);
            if (lane >= o) y += v;
        }
        wsum[lane] = y;
    }
    __syncthreads();
    int run = x - s + (w > 0 ? wsum[w - 1] : 0);
    #pragma unroll
    for (int j = 0; j < CH; ++j) {
        int idx = base + j;
        if (idx < NN) {
            g_off[idx] = run;
            g_cursor[idx] = run;
            run += vals[j];
        }
    }
    if (tid == 1023) g_off[NN] = run;
}

__global__ void k_fill(const int* __restrict__ ei, const float* __restrict__ uv) {
    for (int e = blockIdx.x * blockDim.x + threadIdx.x; e < NE;
         e += gridDim.x * blockDim.x) {
        int t = ei[e];
        int pos = atomicAdd(&g_cursor[t], 1);
        g_epos[e] = pos;
        g_src[pos] = ei[NE + e];
        g_uv4[pos] = make_float4(uv[3 * e], uv[3 * e + 1], uv[3 * e + 2], 0.f);
    }
}

// ---------------- node inter MLP: pre-split A + ldmatrix, fp16 2-term mma ----------------
#define NQP 68
#define NHP 196
#define NODE_SMEM ((2 * 32 * NQP + 2 * 32 * NHP) * 4)
__global__ __launch_bounds__(256) void k_node_mlp(
    const float* __restrict__ q,
    const float* __restrict__ b1, const float* __restrict__ b2)
{
    extern __shared__ u32 smn[];
    u32* sqh = smn;                        // [32][NQP]
    u32* sql = sqh + 32 * NQP;
    u32* shh = sql + 32 * NQP;             // [32][NHP]
    u32* shl = shh + 32 * NHP;
    int tid = threadIdx.x;
    int n0 = blockIdx.x * 32;

    for (int i = tid; i < 32 * 64; i += 256) {
        int r = i >> 6, kp = i & 63;
        int n = n0 + r;
        float2 v = (n < NN) ? *(const float2*)&q[n * HH + 2 * kp]
                            : make_float2(0.f, 0.f);
        u32 h, l;
        split_pair_f16(v.x, v.y, h, l);
        sqh[r * NQP + kp] = h;
        sql[r * NQP + kp] = l;
    }
    __syncthreads();

    int wid  = tid >> 5;
    int lane = tid & 31;
    int gid  = lane >> 2;
    int tig  = lane & 3;
    int nbase = wid * 48;

    // phase 1: hidden = silu(q @ Wi1 + b1), K=128
    {
        float acc[2][6][4];
        #pragma unroll
        for (int r = 0; r < 2; ++r)
            #pragma unroll
            for (int t = 0; t < 6; ++t)
                #pragma unroll
                for (int c = 0; c < 4; ++c) acc[r][t][c] = 0.f;

        #pragma unroll 1
        for (int k0 = 0; k0 < HH; k0 += 16) {
            int kp = k0 >> 1;
            u32 bh[6][2];
            #pragma unroll
            for (int t = 0; t < 6; ++t) {
                int col = nbase + t * 8 + gid;
                bh[t][0] = __ldg(&g_i1h[(kp + tig) * H3 + col]);
                bh[t][1] = __ldg(&g_i1h[(kp + 4 + tig) * H3 + col]);
            }
            #pragma unroll
            for (int r = 0; r < 2; ++r) {
                int loff = (r * 16 + (lane & 15)) * NQP + kp + ((lane >> 4) << 2);
                u32 ah0, ah1, ah2, ah3, al0, al1, al2, al3;
                ldsm_x4(ah0, ah1, ah2, ah3, &sqh[loff]);
                ldsm_x4(al0, al1, al2, al3, &sql[loff]);
                #pragma unroll
                for (int t = 0; t < 6; ++t) {
                    mma_f16(acc[r][t][0], acc[r][t][1], acc[r][t][2], acc[r][t][3],
                            ah0, ah1, ah2, ah3, bh[t][0], bh[t][1]);
                    mma_f16(acc[r][t][0], acc[r][t][1], acc[r][t][2], acc[r][t][3],
                            al0, al1, al2, al3, bh[t][0], bh[t][1]);
                }
            }
        }
        #pragma unroll
        for (int r = 0; r < 2; ++r) {
            int row0 = r * 16 + gid;
            int row1 = row0 + 8;
            #pragma unroll
            for (int t = 0; t < 6; ++t) {
                int col = nbase + t * 8 + 2 * tig;
                int kpo = col >> 1;
                float b0v = __ldg(&b1[col]);
                float b1v = __ldg(&b1[col + 1]);
                u32 h, l;
                split_pair_f16(silu_f(acc[r][t][0] + b0v), silu_f(acc[r][t][1] + b1v), h, l);
                shh[row0 * NHP + kpo] = h;
                shl[row0 * NHP + kpo] = l;
                split_pair_f16(silu_f(acc[r][t][2] + b0v), silu_f(acc[r][t][3] + b1v), h, l);
                shh[row1 * NHP + kpo] = h;
                shl[row1 * NHP + kpo] = l;
            }
        }
    }
    __syncthreads();

    // phase 2: x = hidden @ Wi2 + b2, K=384
    {
        float acc[2][6][4];
        #pragma unroll
        for (int r = 0; r < 2; ++r)
            #pragma unroll
            for (int t = 0; t < 6; ++t)
                #pragma unroll
                for (int c = 0; c < 4; ++c) acc[r][t][c] = 0.f;

        #pragma unroll 1
        for (int k0 = 0; k0 < H3; k0 += 16) {
            int kp = k0 >> 1;
            u32 bh[6][2];
            #pragma unroll
            for (int t = 0; t < 6; ++t) {
                int col = nbase + t * 8 + gid;
                bh[t][0] = __ldg(&g_i2h[(kp + tig) * H3 + col]);
                bh[t][1] = __ldg(&g_i2h[(kp + 4 + tig) * H3 + col]);
            }
            #pragma unroll
            for (int r = 0; r < 2; ++r) {
                int loff = (r * 16 + (lane & 15)) * NHP + kp + ((lane >> 4) << 2);
                u32 ah0, ah1, ah2, ah3, al0, al1, al2, al3;
                ldsm_x4(ah0, ah1, ah2, ah3, &shh[loff]);
                ldsm_x4(al0, al1, al2, al3, &shl[loff]);
                #pragma unroll
                for (int t = 0; t < 6; ++t) {
                    mma_f16(acc[r][t][0], acc[r][t][1], acc[r][t][2], acc[r][t][3],
                            ah0, ah1, ah2, ah3, bh[t][0], bh[t][1]);
                    mma_f16(acc[r][t][0], acc[r][t][1], acc[r][t][2], acc[r][t][3],
                            al0, al1, al2, al3, bh[t][0], bh[t][1]);
                }
            }
        }
        #pragma unroll
        for (int r = 0; r < 2; ++r) {
            int row0 = r * 16 + gid;
            int row1 = row0 + 8;
            #pragma unroll
            for (int t = 0; t < 6; ++t) {
                int col = nbase + t * 8 + 2 * tig;
                float b0v = __ldg(&b2[col]);
                float b1v = __ldg(&b2[col + 1]);
                if (n0 + row0 < NN)
                    *(float2*)&g_x[(size_t)(n0 + row0) * H3 + col] =
                        make_float2(acc[r][t][0] + b0v, acc[r][t][1] + b1v);
                if (n0 + row1 < NN)
                    *(float2*)&g_x[(size_t)(n0 + row1) * H3 + col] =
                        make_float2(acc[r][t][2] + b0v, acc[r][t][3] + b1v);
            }
        }
    }
}

// ---------------- edge filter MLP (R15 proven) ----------------
#define KPS 68
#define RKP 20
__global__ __launch_bounds__(256) void k_edge_filter(
    const float* __restrict__ rbf, const float* __restrict__ cut,
    const float* __restrict__ bf1, const float* __restrict__ bf2)
{
    __shared__ float scut[64];
    __shared__ int   spos[64];
    __shared__ u32 srbh[64 * RKP];
    __shared__ u32 srbl[64 * RKP];
    __shared__ u32 shiT[64 * KPS];
    __shared__ u32 sloT[64 * KPS];
    int tid = threadIdx.x;
    int e0 = blockIdx.x * 64;

    for (int i = tid; i < 64 * 16; i += 256) {
        int r = i >> 4, kp = i & 15;
        float v0 = 0.f, v1 = 0.f;
        if (kp < 10) {
            v0 = rbf[(e0 + r) * NR + 2 * kp];
            v1 = rbf[(e0 + r) * NR + 2 * kp + 1];
        }
        u32 h, l;
        split_pair_f16(v0, v1, h, l);
        srbh[r * RKP + kp] = h;
        srbl[r * RKP + kp] = l;
    }
    if (tid < 64) {
        scut[tid] = cut[e0 + tid];
        spos[tid] = g_epos[e0 + tid];
    }
    __syncthreads();

    int wid  = tid >> 5;
    int lane = tid & 31;
    int gid  = lane >> 2;
    int tig  = lane & 3;

    {
        int rb1 = (wid >> 1) * 16;
        int cb  = (wid & 1) * 64;
        float a1[8][4];
        #pragma unroll
        for (int t = 0; t < 8; ++t)
            #pragma unroll
            for (int c = 0; c < 4; ++c) a1[t][c] = 0.f;

        #pragma unroll
        for (int ks = 0; ks < 2; ++ks) {
            int kp = ks * 8;
            u32 bh1[8][2];
            #pragma unroll
            for (int t = 0; t < 8; ++t) {
                int col = cb + t * 8 + gid;
                bh1[t][0] = __ldg(&g_f1h[(kp + tig) * HH + col]);
                bh1[t][1] = __ldg(&g_f1h[(kp + 4 + tig) * HH + col]);
            }
            int loff = (rb1 + (lane & 15)) * RKP + kp + ((lane >> 4) << 2);
            u32 ah0, ah1, ah2, ah3, al0, al1, al2, al3;
            ldsm_x4(ah0, ah1, ah2, ah3, &srbh[loff]);
            ldsm_x4(al0, al1, al2, al3, &srbl[loff]);
            #pragma unroll
            for (int t = 0; t < 8; ++t) {
                mma_f16(a1[t][0], a1[t][1], a1[t][2], a1[t][3],
                        ah0, ah1, ah2, ah3, bh1[t][0], bh1[t][1]);
                mma_f16(a1[t][0], a1[t][1], a1[t][2], a1[t][3],
                        al0, al1, al2, al3, bh1[t][0], bh1[t][1]);
            }
        }
        #pragma unroll
        for (int t = 0; t < 8; ++t) {
            int col = cb + t * 8 + 2 * tig;
            int kpo = col >> 1;
            float b0v = __ldg(&bf1[col]);
            float b1v = __ldg(&bf1[col + 1]);
            int row0 = rb1 + gid;
            int row1 = row0 + 8;
            u32 h, l;
            split_pair_f16(silu_f(a1[t][0] + b0v), silu_f(a1[t][1] + b1v), h, l);
            shiT[row0 * KPS + kpo] = h;
            sloT[row0 * KPS + kpo] = l;
            split_pair_f16(silu_f(a1[t][2] + b0v), silu_f(a1[t][3] + b1v), h, l);
            shiT[row1 * KPS + kpo] = h;
            sloT[row1 * KPS + kpo] = l;
        }
    }
    __syncthreads();

    int nbase = wid * 48;

    float acc[4][6][4];
    #pragma unroll
    for (int r = 0; r < 4; ++r)
        #pragma unroll
        for (int t = 0; t < 6; ++t)
            #pragma unroll
            for (int c = 0; c < 4; ++c) acc[r][t][c] = 0.f;

    #pragma unroll 1
    for (int k0 = 0; k0 < HH; k0 += 16) {
        int kp = k0 >> 1;
        u32 bh[6][2];
        #pragma unroll
        for (int t = 0; t < 6; ++t) {
            int col = nbase + t * 8 + gid;
            bh[t][0] = __ldg(&g_bhp[(kp + tig) * H3 + col]);
            bh[t][1] = __ldg(&g_bhp[(kp + 4 + tig) * H3 + col]);
        }
        #pragma unroll
        for (int r = 0; r < 4; ++r) {
            int loff = (r * 16 + (lane & 15)) * KPS + kp + ((lane >> 4) << 2);
            u32 ah0, ah1, ah2, ah3, al0, al1, al2, al3;
            ldsm_x4(ah0, ah1, ah2, ah3, &shiT[loff]);
            ldsm_x4(al0, al1, al2, al3, &sloT[loff]);
            #pragma unroll
            for (int t = 0; t < 6; ++t) {
                mma_f16(acc[r][t][0], acc[r][t][1], acc[r][t][2], acc[r][t][3],
                        ah0, ah1, ah2, ah3, bh[t][0], bh[t][1]);
                mma_f16(acc[r][t][0], acc[r][t][1], acc[r][t][2], acc[r][t][3],
                        al0, al1, al2, al3, bh[t][0], bh[t][1]);
            }
        }
    }

    #pragma unroll
    for (int r = 0; r < 4; ++r) {
        int row0 = r * 16 + gid;
        int row1 = row0 + 8;
        float c0v = scut[row0];
        float c1v = scut[row1];
        size_t p0 = (size_t)spos[row0] * H3;
        size_t p1 = (size_t)spos[row1] * H3;
        #pragma unroll
        for (int t = 0; t < 6; ++t) {
            int col = nbase + t * 8 + 2 * tig;
            float b0v = bf2[col];
            float b1v = bf2[col + 1];
            __half2 v0 = __floats2half2_rn((acc[r][t][0] + b0v) * c0v,
                                           (acc[r][t][1] + b1v) * c0v);
            __half2 v1 = __floats2half2_rn((acc[r][t][2] + b0v) * c1v,
                                           (acc[r][t][3] + b1v) * c1v);
            *(__half2*)&g_filters[p0 + col] = v0;
            *(__half2*)&g_filters[p1 + col] = v1;
        }
    }
}

// ---------------- pull aggregation (R14 proven) ----------------
__global__ __launch_bounds__(128) void k_aggregate(
    const float* __restrict__ q, const float* __restrict__ mu)
{
    int node = blockIdx.x * 2 + (threadIdx.x >> 6);
    int hp = threadIdx.x & 63;
    if (node >= NN) return;
    int beg = g_off[node], end = g_off[node + 1];
    float2 qa = {0.f, 0.f};
    float2 m0 = {0.f, 0.f}, m1 = {0.f, 0.f}, m2 = {0.f, 0.f};
    for (int i = beg; i < end; ++i) {
        int s = g_src[i];
        const __half2* f = (const __half2*)&g_filters[(size_t)i * H3];
        float2 fq = __half22float2(f[hp]);
        float2 fr = __half22float2(f[64 + hp]);
        float2 fm = __half22float2(f[128 + hp]);
        const float2* xs = (const float2*)&g_x[s * H3];
        float2 x0 = xs[hp], x1 = xs[64 + hp], x2 = xs[128 + hp];
        float4 u = g_uv4[i];
        const float2* ms = (const float2*)&mu[s * 3 * HH];
        float2 u0 = ms[hp], u1v = ms[64 + hp], u2v = ms[128 + hp];
        float xrx = x1.x * fr.x, xry = x1.y * fr.y;
        float xmx = x2.x * fm.x, xmy = x2.y * fm.y;
        qa.x += x0.x * fq.x;
        qa.y += x0.y * fq.y;
        m0.x = fmaf(u.x, xrx, fmaf(u0.x,  xmx, m0.x));
        m0.y = fmaf(u.x, xry, fmaf(u0.y,  xmy, m0.y));
        m1.x = fmaf(u.y, xrx, fmaf(u1v.x, xmx, m1.x));
        m1.y = fmaf(u.y, xry, fmaf(u1v.y, xmy, m1.y));
        m2.x = fmaf(u.z, xrx, fmaf(u2v.x, xmx, m2.x));
        m2.y = fmaf(u.z, xry, fmaf(u2v.y, xmy, m2.y));
    }
    {
        float2 qv = *(const float2*)&q[node * HH + 2 * hp];
        *(float2*)&g_qmid[node * HH + 2 * hp] = make_float2(qv.x + qa.x, qv.y + qa.y);
        const float2* mb = (const float2*)&mu[node * 3 * HH];
        float2 b0 = mb[hp], b1 = mb[64 + hp], b2 = mb[128 + hp];
        float2* out = (float2*)&g_mumid[node * 3 * HH];
        out[hp]       = make_float2(b0.x + m0.x, b0.y + m0.y);
        out[64 + hp]  = make_float2(b1.x + m1.x, b1.y + m1.y);
        out[128 + hp] = make_float2(b2.x + m2.x, b2.y + m2.y);
    }
}

// ---------------- equivariant linear: pre-split A + ldmatrix ----------------
#define EKP 68
#define EOP 260
#define EQ_SMEM ((2 * 48 * EKP) * 4 + 48 * EOP * 4)
__global__ __launch_bounds__(256) void k_equiv()
{
    extern __shared__ u32 sme[];
    u32* smh = sme;                       // [48][EKP]
    u32* sml = smh + 48 * EKP;
    float* sout = (float*)(sml + 48 * EKP);   // [48][EOP]
    int tid = threadIdx.x;
    int n0 = blockIdx.x * 16;
    int row_base = n0 * 3;

    for (int i = tid; i < 48 * 64; i += 256) {
        int r = i >> 6, kp = i & 63;
        int grow = row_base + r;
        float2 v = (grow < NN * 3) ? *(const float2*)&g_mumid[grow * HH + 2 * kp]
                                   : make_float2(0.f, 0.f);
        u32 h, l;
        split_pair_f16(v.x, v.y, h, l);
        smh[r * EKP + kp] = h;
        sml[r * EKP + kp] = l;
    }
    __syncthreads();

    int wid  = tid >> 5;
    int lane = tid & 31;
    int gid  = lane >> 2;
    int tig  = lane & 3;
    int nbase = wid * 32;

    float acc[3][4][4];
    #pragma unroll
    for (int r = 0; r < 3; ++r)
        #pragma unroll
        for (int t = 0; t < 4; ++t)
            #pragma unroll
            for (int c = 0; c < 4; ++c) acc[r][t][c] = 0.f;

    #pragma unroll 1
    for (int k0 = 0; k0 < HH; k0 += 16) {
        int kp = k0 >> 1;
        u32 bh[4][2];
        #pragma unroll
        for (int t = 0; t < 4; ++t) {
            int col = nbase + t * 8 + gid;
            bh[t][0] = __ldg(&g_vch[(kp + tig) * H2 + col]);
            bh[t][1] = __ldg(&g_vch[(kp + 4 + tig) * H2 + col]);
        }
        #pragma unroll
        for (int r = 0; r < 3; ++r) {
            int loff = (r * 16 + (lane & 15)) * EKP + kp + ((lane >> 4) << 2);
            u32 ah0, ah1, ah2, ah3, al0, al1, al2, al3;
            ldsm_x4(ah0, ah1, ah2, ah3, &smh[loff]);
            ldsm_x4(al0, al1, al2, al3, &sml[loff]);
            #pragma unroll
            for (int t = 0; t < 4; ++t) {
                mma_f16(acc[r][t][0], acc[r][t][1], acc[r][t][2], acc[r][t][3],
                        ah0, ah1, ah2, ah3, bh[t][0], bh[t][1]);
                mma_f16(acc[r][t][0], acc[r][t][1], acc[r][t][2], acc[r][t][3],
                        al0, al1, al2, al3, bh[t][0], bh[t][1]);
            }
        }
    }

    #pragma unroll
    for (int r = 0; r < 3; ++r) {
        int row0 = r * 16 + gid;
        int row1 = row0 + 8;
        #pragma unroll
        for (int t = 0; t < 4; ++t) {
            int col = nbase + t * 8 + 2 * tig;
            sout[row0 * EOP + col]     = acc[r][t][0];
            sout[row0 * EOP + col + 1] = acc[r][t][1];
            sout[row1 * EOP + col]     = acc[r][t][2];
            sout[row1 * EOP + col + 1] = acc[r][t][3];
        }
    }
    __syncthreads();

    for (int slot = tid; slot < 16 * HH; slot += 256) {
        int r = slot >> 7;
        int o = slot & 127;
        int n = n0 + r;
        if (n >= NN) break;
        float v0 = sout[(r * 3 + 0) * EOP + o];
        float v1 = sout[(r * 3 + 1) * EOP + o];
        float v2 = sout[(r * 3 + 2) * EOP + o];
        float w0 = sout[(r * 3 + 0) * EOP + HH + o];
        float w1 = sout[(r * 3 + 1) * EOP + HH + o];
        float w2 = sout[(r * 3 + 2) * EOP + HH + o];
        g_vnorm[n * HH + o] = sqrtf(v0 * v0 + v1 * v1 + v2 * v2 + 1e-8f);
        g_inner[n * HH + o] = v0 * w0 + v1 * w1 + v2 * w2;
        g_muw[n * 3 * HH + o]          = w0;
        g_muw[n * 3 * HH + HH + o]     = w1;
        g_muw[n * 3 * HH + 2 * HH + o] = w2;
    }
}

// ---------------- scalar mix MLP: pre-split A + ldmatrix ----------------
#define MAP 132
#define MHP 196
#define MDP 388
#define MIX_SMEM ((2 * 32 * MAP + 2 * 32 * MHP) * 4)
__global__ __launch_bounds__(256) void k_mix(
    const float* __restrict__ bm1, const float* __restrict__ bm2,
    float* __restrict__ qout, float* __restrict__ muout)
{
    extern __shared__ u32 smx[];
    u32* sAh = smx;                        // [32][MAP]  input pre-split
    u32* sAl = sAh + 32 * MAP;
    u32* sBh = sAl + 32 * MAP;             // [32][MHP]  hidden pre-split
    u32* sBl = sBh + 32 * MHP;
    float* sD = (float*)sBh;               // delta staging (overlays sBh+sBl)
    int tid = threadIdx.x;
    int n0 = blockIdx.x * 32;

    for (int i = tid; i < 32 * 128; i += 256) {
        int r = i >> 7, kp = i & 127;
        int n = n0 + r;
        float2 v = make_float2(0.f, 0.f);
        if (n < NN)
            v = (kp < 64) ? *(const float2*)&g_qmid[n * HH + 2 * kp]
                          : *(const float2*)&g_vnorm[n * HH + 2 * (kp - 64)];
        u32 h, l;
        split_pair_f16(v.x, v.y, h, l);
        sAh[r * MAP + kp] = h;
        sAl[r * MAP + kp] = l;
    }
    __syncthreads();

    int wid  = tid >> 5;
    int lane = tid & 31;
    int gid  = lane >> 2;
    int tig  = lane & 3;
    int nbase = wid * 48;

    // phase 1: hidden = silu(input @ Wm1 + bm1), K=256
    {
        float acc[2][6][4];
        #pragma unroll
        for (int r = 0; r < 2; ++r)
            #pragma unroll
            for (int t = 0; t < 6; ++t)
                #pragma unroll
                for (int c = 0; c < 4; ++c) acc[r][t][c] = 0.f;

        #pragma unroll 1
        for (int k0 = 0; k0 < H2; k0 += 16) {
            int kp = k0 >> 1;
            u32 bh[6][2];
            #pragma unroll
            for (int t = 0; t < 6; ++t) {
                int col = nbase + t * 8 + gid;
                bh[t][0] = __ldg(&g_m1h[(kp + tig) * H3 + col]);
                bh[t][1] = __ldg(&g_m1h[(kp + 4 + tig) * H3 + col]);
            }
            #pragma unroll
            for (int r = 0; r < 2; ++r) {
                int loff = (r * 16 + (lane & 15)) * MAP + kp + ((lane >> 4) << 2);
                u32 ah0, ah1, ah2, ah3, al0, al1, al2, al3;
                ldsm_x4(ah0, ah1, ah2, ah3, &sAh[loff]);
                ldsm_x4(al0, al1, al2, al3, &sAl[loff]);
                #pragma unroll
                for (int t = 0; t < 6; ++t) {
                    mma_f16(acc[r][t][0], acc[r][t][1], acc[r][t][2], acc[r][t][3],
                            ah0, ah1, ah2, ah3, bh[t][0], bh[t][1]);
                    mma_f16(acc[r][t][0], acc[r][t][1], acc[r][t][2], acc[r][t][3],
                            al0, al1, al2, al3, bh[t][0], bh[t][1]);
                }
            }
        }
        #pragma unroll
        for (int r = 0; r < 2; ++r) {
            int row0 = r * 16 + gid;
            int row1 = row0 + 8;
            #pragma unroll
            for (int t = 0; t < 6; ++t) {
                int col = nbase + t * 8 + 2 * tig;
                int kpo = col >> 1;
                float b0v = __ldg(&bm1[col]);
                float b1v = __ldg(&bm1[col + 1]);
                u32 h, l;
                split_pair_f16(silu_f(acc[r][t][0] + b0v), silu_f(acc[r][t][1] + b1v), h, l);
                sBh[row0 * MHP + kpo] = h;
                sBl[row0 * MHP + kpo] = l;
                split_pair_f16(silu_f(acc[r][t][2] + b0v), silu_f(acc[r][t][3] + b1v), h, l);
                sBh[row1 * MHP + kpo] = h;
                sBl[row1 * MHP + kpo] = l;
            }
        }
    }
    __syncthreads();

    // phase 2: delta = hidden @ Wm2 + bm2, K=384
    {
        float acc[2][6][4];
        #pragma unroll
        for (int r = 0; r < 2; ++r)
            #pragma unroll
            for (int t = 0; t < 6; ++t)
                #pragma unroll
                for (int c = 0; c < 4; ++c) acc[r][t][c] = 0.f;

        #pragma unroll 1
        for (int k0 = 0; k0 < H3; k0 += 16) {
            int kp = k0 >> 1;
            u32 bh[6][2];
            #pragma unroll
            for (int t = 0; t < 6; ++t) {
                int col = nbase + t * 8 + gid;
                bh[t][0] = __ldg(&g_m2h[(kp + tig) * H3 + col]);
                bh[t][1] = __ldg(&g_m2h[(kp + 4 + tig) * H3 + col]);
            }
            #pragma unroll
            for (int r = 0; r < 2; ++r) {
                int loff = (r * 16 + (lane & 15)) * MHP + kp + ((lane >> 4) << 2);
                u32 ah0, ah1, ah2, ah3, al0, al1, al2, al3;
                ldsm_x4(ah0, ah1, ah2, ah3, &sBh[loff]);
                ldsm_x4(al0, al1, al2, al3, &sBl[loff]);
                #pragma unroll
                for (int t = 0; t < 6; ++t) {
                    mma_f16(acc[r][t][0], acc[r][t][1], acc[r][t][2], acc[r][t][3],
                            ah0, ah1, ah2, ah3, bh[t][0], bh[t][1]);
                    mma_f16(acc[r][t][0], acc[r][t][1], acc[r][t][2], acc[r][t][3],
                            al0, al1, al2, al3, bh[t][0], bh[t][1]);
                }
            }
        }
        __syncthreads();   // all reads of hidden done; sD overlays sBh/sBl
        #pragma unroll
        for (int r = 0; r < 2; ++r) {
            int row0 = r * 16 + gid;
            int row1 = row0 + 8;
            #pragma unroll
            for (int t = 0; t < 6; ++t) {
                int col = nbase + t * 8 + 2 * tig;
                float b0v = __ldg(&bm2[col]);
                float b1v = __ldg(&bm2[col + 1]);
                sD[row0 * MDP + col]     = acc[r][t][0] + b0v;
                sD[row0 * MDP + col + 1] = acc[r][t][1] + b1v;
                sD[row1 * MDP + col]     = acc[r][t][2] + b0v;
                sD[row1 * MDP + col + 1] = acc[r][t][3] + b1v;
            }
        }
    }
    __syncthreads();

    for (int slot = tid; slot < 32 * HH; slot += 256) {
        int r = slot >> 7;
        int o = slot & 127;
        int n = n0 + r;
        if (n >= NN) break;
        float dq  = sD[r * MDP + o];
        float dms = sD[r * MDP + HH + o];
        float dqm = sD[r * MDP + 2 * HH + o];
        qout[n * HH + o] = g_qmid[n * HH + o] + dq + dqm * g_inner[n * HH + o];
        #pragma unroll
        for (int d = 0; d < 3; ++d) {
            int idx = n * 3 * HH + d * HH + o;
            muout[idx] = g_mumid[idx] + g_muw[idx] * dms;
        }
    }
}

// ---------------- launch ----------------
extern "C" void kernel_launch(void* const* d_in, const int* in_sizes, int n_in,
                              void* d_out, int out_size)
{
    const float* q   = (const float*)d_in[0];
    const float* mu  = (const float*)d_in[1];
    const int*   ei  = (const int*)d_in[2];
    const float* rbf = (const float*)d_in[3];
    const float* uv  = (const float*)d_in[4];
    const float* cut = (const float*)d_in[5];
    const float* Wi1 = (const float*)d_in[6];
    const float* bi1 = (const float*)d_in[7];
    const float* Wi2 = (const float*)d_in[8];
    const float* bi2 = (const float*)d_in[9];
    const float* Wf1 = (const float*)d_in[10];
    const float* bf1 = (const float*)d_in[11];
    const float* Wf2 = (const float*)d_in[12];
    const float* bf2 = (const float*)d_in[13];
    const float* Wv  = (const float*)d_in[14];
    const float* Wm1 = (const float*)d_in[15];
    const float* bm1 = (const float*)d_in[16];
    const float* Wm2 = (const float*)d_in[17];
    const float* bm2 = (const float*)d_in[18];

    float* qout  = (float*)d_out;
    float* muout = qout + (size_t)NN * HH;

    cudaFuncSetAttribute(k_node_mlp, cudaFuncAttributeMaxDynamicSharedMemorySize, NODE_SMEM);
    cudaFuncSetAttribute(k_equiv,    cudaFuncAttributeMaxDynamicSharedMemorySize, EQ_SMEM);
    cudaFuncSetAttribute(k_mix,      cudaFuncAttributeMaxDynamicSharedMemorySize, MIX_SMEM);

    k_prep<<<(SEG7 + 255) / 256, 256>>>(Wf2, Wi1, Wi2, Wv, Wm1, Wm2, Wf1);
    k_count<<<512, 256>>>(ei);
    k_scan<<<1, 1024>>>();
    k_fill<<<512, 256>>>(ei, uv);

    k_node_mlp<<<(NN + 31) / 32, 256, NODE_SMEM>>>(q, bi1, bi2);
    k_edge_filter<<<NE / 64, 256>>>(rbf, cut, bf1, bf2);

    k_aggregate<<<(NN + 1) / 2, 128>>>(q, mu);

    k_equiv<<<(NN + 15) / 16, 256, EQ_SMEM>>>();
    k_mix<<<(NN + 31) / 32, 256, MIX_SMEM>>>(bm1, bm2, qout, muout);
}